// round 4
// baseline (speedup 1.0000x reference)
#include <cuda_runtime.h>
#include <math.h>
#include <stdint.h>

#define Lc 6
#define Bc 16
#define Tc 512
#define Dc 512
#define Hc 8
#define Ac 64
#define Fc 2048
#define Ec 200000
#define BIASDIM 4

// ---------------- packed f32x2 FMA helpers (Blackwell FFMA2) ----------------
typedef unsigned long long u64t;

__device__ __forceinline__ u64t dup2(float a) {
    u64t d;
    asm("mov.b64 %0, {%1, %1};" : "=l"(d) : "f"(a));
    return d;
}
__device__ __forceinline__ void fma2(u64t& acc, u64t a, u64t b) {
    asm("fma.rn.f32x2 %0, %1, %2, %0;" : "+l"(acc) : "l"(a), "l"(b));
}
__device__ __forceinline__ void unpack2(u64t p, float& lo, float& hi) {
    asm("mov.b64 {%0, %1}, %2;" : "=f"(lo), "=f"(hi) : "l"(p));
}

// ---------------- scratch (device globals; no allocations allowed) ----------
__device__ float g_x[Bc*Tc*Dc];
__device__ float g_h[Bc*Tc*Dc];
__device__ float g_q[Bc*Tc*Dc];
__device__ float g_k[Bc*Tc*Dc];
__device__ float g_v[Bc*Tc*Dc];
__device__ float g_ctx[Bc*Tc*Dc];
__device__ float g_ksum[Bc*Hc*Tc];                  // [b,h,t]
__device__ float g_dense[Bc*Tc*Tc];
__device__ float g_alpha[(size_t)Bc*Hc*Tc*Tc];
__device__ float g_ffh[Bc*Tc*Fc];

// ---------------- embedding + positional encoding ---------------------------
__global__ __launch_bounds__(512) void embed_pe_kernel(
    const int* __restrict__ tokens, const float* __restrict__ embed)
{
    int bt = blockIdx.x;
    int d  = threadIdx.x;
    int t  = bt % Tc;
    int tok = tokens[bt];
    float val = embed[(size_t)tok * Dc + d] * 22.62741699796952f; // sqrt(512)
    float expo  = (2.0f * (float)(d >> 1)) / (float)Dc;
    float denom = powf(10000.0f, expo);
    float angle = (float)t / denom;
    val += ((d & 1) == 0) ? sinf(angle) : cosf(angle);
    g_x[(size_t)bt * Dc + d] = val;
}

// ---------------- layernorm (block per token, D=512) -------------------------
__global__ __launch_bounds__(256) void layernorm_kernel(
    const float* __restrict__ in, const float* __restrict__ gamma,
    const float* __restrict__ beta, float* __restrict__ out)
{
    __shared__ float red[256];
    size_t base = (size_t)blockIdx.x * Dc;
    int tid = threadIdx.x;
    float v0 = in[base + tid];
    float v1 = in[base + tid + 256];
    red[tid] = v0 + v1;
    __syncthreads();
    #pragma unroll
    for (int s = 128; s > 0; s >>= 1) {
        if (tid < s) red[tid] += red[tid + s];
        __syncthreads();
    }
    float mu = red[0] * (1.0f / Dc);
    __syncthreads();
    float d0 = v0 - mu, d1 = v1 - mu;
    red[tid] = d0 * d0 + d1 * d1;
    __syncthreads();
    #pragma unroll
    for (int s = 128; s > 0; s >>= 1) {
        if (tid < s) red[tid] += red[tid + s];
        __syncthreads();
    }
    float rstd = rsqrtf(red[0] * (1.0f / Dc) + 1e-3f);
    out[base + tid]       = d0 * rstd * gamma[tid]       + beta[tid];
    out[base + tid + 256] = d1 * rstd * gamma[tid + 256] + beta[tid + 256];
}

// ---------------- 128x128 SGEMM, 8x8 microtile, FFMA2 inner loop ------------
// C[M,N] = A[M,K] @ B[K,N] (+bias, relu, residual). grid (N/128, M/128), 256 thr.
__global__ __launch_bounds__(256) void gemm_nn_128(
    const float* __restrict__ A, const float* __restrict__ B,
    const float* __restrict__ bias, const float* __restrict__ resid,
    float* __restrict__ C, int M, int N, int K, int do_relu)
{
    __shared__ __align__(16) float As[8][128];
    __shared__ __align__(16) float Bs[8][128];
    int t = threadIdx.x;
    int row0 = blockIdx.y * 128, col0 = blockIdx.x * 128;

    int ar = t >> 1, ac = (t & 1) * 4;     // A loader
    int br = t >> 5, bc = (t & 31) * 4;    // B loader
    const float* Aptr = A + (size_t)(row0 + ar) * K + ac;
    const float* Bptr = B + (size_t)br * N + col0 + bc;

    int tx = t & 15, ty = t >> 4;
    u64t acc2[8][4] = {};

    float4 pa = *(const float4*)Aptr;
    float4 pb = *(const float4*)Bptr;

    for (int k0 = 0; k0 < K; k0 += 8) {
        As[ac + 0][ar] = pa.x; As[ac + 1][ar] = pa.y;
        As[ac + 2][ar] = pa.z; As[ac + 3][ar] = pa.w;
        *(float4*)&Bs[br][bc] = pb;
        __syncthreads();
        if (k0 + 8 < K) {
            pa = *(const float4*)(Aptr + k0 + 8);
            pb = *(const float4*)(Bptr + (size_t)(k0 + 8) * N);
        }
        #pragma unroll
        for (int kk = 0; kk < 8; kk++) {
            float4 a0 = *(const float4*)&As[kk][ty * 4];
            float4 a1 = *(const float4*)&As[kk][ty * 4 + 64];
            ulonglong2 b0 = *(const ulonglong2*)&Bs[kk][tx * 4];
            ulonglong2 b1 = *(const ulonglong2*)&Bs[kk][tx * 4 + 64];
            u64t bp[4] = {b0.x, b0.y, b1.x, b1.y};
            float av[8] = {a0.x,a0.y,a0.z,a0.w,a1.x,a1.y,a1.z,a1.w};
            #pragma unroll
            for (int i = 0; i < 8; i++) {
                u64t ad = dup2(av[i]);
                #pragma unroll
                for (int jp = 0; jp < 4; jp++)
                    fma2(acc2[i][jp], ad, bp[jp]);
            }
        }
        __syncthreads();
    }
    #pragma unroll
    for (int i = 0; i < 8; i++) {
        int m = row0 + ty * 4 + (i & 3) + (i >> 2) * 64;
        #pragma unroll
        for (int jh = 0; jh < 2; jh++) {
            int n = col0 + tx * 4 + jh * 64;
            float4 v;
            unpack2(acc2[i][jh*2+0], v.x, v.y);
            unpack2(acc2[i][jh*2+1], v.z, v.w);
            if (bias) {
                v.x += bias[n+0]; v.y += bias[n+1];
                v.z += bias[n+2]; v.w += bias[n+3];
            }
            if (do_relu) {
                v.x = fmaxf(v.x, 0.f); v.y = fmaxf(v.y, 0.f);
                v.z = fmaxf(v.z, 0.f); v.w = fmaxf(v.w, 0.f);
            }
            if (resid) {
                float4 r = *(const float4*)(resid + (size_t)m * N + n);
                v.x += r.x; v.y += r.y; v.z += r.z; v.w += r.w;
            }
            *(float4*)(C + (size_t)m * N + n) = v;
        }
    }
}

// ---------------- ksum[b,h,t] = sum_a k[b,t,h,a] ----------------------------
__global__ __launch_bounds__(256) void ksum_kernel(void)
{
    int i = blockIdx.x * blockDim.x + threadIdx.x;
    if (i >= Bc * Tc * Hc) return;
    int bt = i >> 3, h = i & 7;
    int b = bt / Tc, tt = bt % Tc;
    const float* p = g_k + (size_t)bt * Dc + h * Ac;
    float s = 0.0f;
    #pragma unroll
    for (int a = 0; a < Ac; a += 4) {
        float4 w = *(const float4*)(p + a);
        s += w.x + w.y + w.z + w.w;
    }
    g_ksum[((size_t)b * Hc + h) * Tc + tt] = s;
}

// ---------------- zero dense bias map ---------------------------------------
__global__ __launch_bounds__(256) void zero_kernel(float* __restrict__ p, int n4)
{
    int i = blockIdx.x * blockDim.x + threadIdx.x;
    if (i < n4) ((float4*)p)[i] = make_float4(0.f, 0.f, 0.f, 0.f);
}

// ---------------- sparse edge bias scatter ----------------------------------
__global__ __launch_bounds__(256) void bias_scatter_kernel(
    const int* __restrict__ ab, const float* __restrict__ be_l,
    const float* __restrict__ bs_l)
{
    __shared__ float evtab[BIASDIM];
    if (threadIdx.x < BIASDIM) {
        float s = 0.0f;
        #pragma unroll
        for (int a = 0; a < Ac; a++)
            s += be_l[threadIdx.x * Ac + a] * bs_l[a];
        evtab[threadIdx.x] = s;
    }
    __syncthreads();
    int e = blockIdx.x * blockDim.x + threadIdx.x;
    if (e >= Ec) return;
    int ty = ab[e * 4 + 0];
    int b  = ab[e * 4 + 1];
    int q  = ab[e * 4 + 2];
    int k  = ab[e * 4 + 3];
    atomicAdd(&g_dense[((size_t)b * Tc + q) * Tc + k], evtab[ty]);
}

// ---------------- attention scores: 128x128 tiles, FFMA2 --------------------
// grid (T/128, T/128, B*H). alpha[z,q,k] = (q.kT + dense*ksum)*scale, masked.
__global__ __launch_bounds__(256) void attn_score_kernel(
    const float* __restrict__ masks)
{
    __shared__ __align__(16) float Qs[8][128];
    __shared__ __align__(16) float Ks[8][128];
    int z = blockIdx.z;
    int b = z >> 3, h = z & 7;
    int t = threadIdx.x;
    int q0 = blockIdx.y * 128, c0 = blockIdx.x * 128;

    const float* qb = g_q + (size_t)b * Tc * Dc + h * Ac;
    const float* kb = g_k + (size_t)b * Tc * Dc + h * Ac;

    int ar = t >> 1, ac = (t & 1) * 4;
    const float* Qptr = qb + (size_t)(q0 + ar) * Dc + ac;
    const float* Kptr = kb + (size_t)(c0 + ar) * Dc + ac;

    int tx = t & 15, ty = t >> 4;
    u64t acc2[8][4] = {};

    float4 pq = *(const float4*)Qptr;
    float4 pk = *(const float4*)Kptr;

    for (int a0 = 0; a0 < Ac; a0 += 8) {
        Qs[ac + 0][ar] = pq.x; Qs[ac + 1][ar] = pq.y;
        Qs[ac + 2][ar] = pq.z; Qs[ac + 3][ar] = pq.w;
        Ks[ac + 0][ar] = pk.x; Ks[ac + 1][ar] = pk.y;
        Ks[ac + 2][ar] = pk.z; Ks[ac + 3][ar] = pk.w;
        __syncthreads();
        if (a0 + 8 < Ac) {
            pq = *(const float4*)(Qptr + a0 + 8);
            pk = *(const float4*)(Kptr + a0 + 8);
        }
        #pragma unroll
        for (int kk = 0; kk < 8; kk++) {
            float4 a0v = *(const float4*)&Qs[kk][ty * 4];
            float4 a1v = *(const float4*)&Qs[kk][ty * 4 + 64];
            ulonglong2 b0v = *(const ulonglong2*)&Ks[kk][tx * 4];
            ulonglong2 b1v = *(const ulonglong2*)&Ks[kk][tx * 4 + 64];
            u64t bp[4] = {b0v.x, b0v.y, b1v.x, b1v.y};
            float av[8] = {a0v.x,a0v.y,a0v.z,a0v.w,a1v.x,a1v.y,a1v.z,a1v.w};
            #pragma unroll
            for (int i = 0; i < 8; i++) {
                u64t ad = dup2(av[i]);
                #pragma unroll
                for (int jp = 0; jp < 4; jp++)
                    fma2(acc2[i][jp], ad, bp[jp]);
            }
        }
        __syncthreads();
    }

    const float* ksrow = g_ksum + ((size_t)b * Hc + h) * Tc;
    #pragma unroll
    for (int i = 0; i < 8; i++) {
        int qg = q0 + ty * 4 + (i & 3) + (i >> 2) * 64;
        size_t drow = ((size_t)b * Tc + qg) * Tc;
        size_t orow = ((size_t)z * Tc + qg) * Tc;
        #pragma unroll
        for (int jh = 0; jh < 2; jh++) {
            int n = c0 + tx * 4 + jh * 64;
            float4 dv = *(const float4*)(g_dense + drow + n);
            float4 ks = *(const float4*)(ksrow + n);
            float4 mk = *(const float4*)(masks + drow + n);
            float aa[4];
            unpack2(acc2[i][jh*2+0], aa[0], aa[1]);
            unpack2(acc2[i][jh*2+1], aa[2], aa[3]);
            float dd[4] = {dv.x, dv.y, dv.z, dv.w};
            float kk2[4] = {ks.x, ks.y, ks.z, ks.w};
            float mm[4] = {mk.x, mk.y, mk.z, mk.w};
            float r[4];
            #pragma unroll
            for (int j = 0; j < 4; j++) {
                float val = (aa[j] + dd[j] * kk2[j]) * 0.125f;
                r[j] = val * mm[j] + (1.0f - ceilf(mm[j])) * (-3.402823466e38f);
            }
            *(float4*)(g_alpha + orow + n) = make_float4(r[0], r[1], r[2], r[3]);
        }
    }
}

// ---------------- softmax over last axis (rows of 512) ----------------------
__global__ __launch_bounds__(128) void softmax_kernel(void)
{
    __shared__ float red[128];
    size_t base = (size_t)blockIdx.x * Tc;
    int tid = threadIdx.x;
    float4 v = *(float4*)(g_alpha + base + tid * 4);
    float m = fmaxf(fmaxf(v.x, v.y), fmaxf(v.z, v.w));
    red[tid] = m;
    __syncthreads();
    #pragma unroll
    for (int s = 64; s > 0; s >>= 1) {
        if (tid < s) red[tid] = fmaxf(red[tid], red[tid + s]);
        __syncthreads();
    }
    m = red[0];
    __syncthreads();
    float e0 = expf(v.x - m), e1 = expf(v.y - m);
    float e2 = expf(v.z - m), e3 = expf(v.w - m);
    red[tid] = e0 + e1 + e2 + e3;
    __syncthreads();
    #pragma unroll
    for (int s = 64; s > 0; s >>= 1) {
        if (tid < s) red[tid] += red[tid + s];
        __syncthreads();
    }
    float inv = 1.0f / red[0];
    *(float4*)(g_alpha + base + tid * 4) =
        make_float4(e0 * inv, e1 * inv, e2 * inv, e3 * inv);
}

// ---------------- context: ctx = alpha @ V, tile 128x64, FFMA2 --------------
// grid (T/128, B*H), 128 threads
__global__ __launch_bounds__(128) void attn_ctx_kernel(void)
{
    __shared__ __align__(16) float As[8][128];
    __shared__ __align__(16) float Bs[8][64];
    int z = blockIdx.y;
    int b = z >> 3, h = z & 7;
    int t = threadIdx.x;
    int q0 = blockIdx.x * 128;

    const float* ap = g_alpha + (size_t)z * Tc * Tc;
    const float* vb = g_v + (size_t)b * Tc * Dc + h * Ac;

    int ar = t >> 1, ac = (t & 1) * 4;
    int br = t >> 4, bc = (t & 15) * 4;
    const float* Aptr0 = ap + (size_t)(q0 + ar) * Tc + ac;
    const float* Aptr1 = ap + (size_t)(q0 + ar + 64) * Tc + ac;
    const float* Bptr  = vb + (size_t)br * Dc + bc;

    int tx = t & 7, ty = t >> 3;
    u64t acc2[8][4] = {};

    float4 pa0 = *(const float4*)Aptr0;
    float4 pa1 = *(const float4*)Aptr1;
    float4 pb  = *(const float4*)Bptr;

    for (int k0 = 0; k0 < Tc; k0 += 8) {
        As[ac + 0][ar] = pa0.x; As[ac + 1][ar] = pa0.y;
        As[ac + 2][ar] = pa0.z; As[ac + 3][ar] = pa0.w;
        As[ac + 0][ar + 64] = pa1.x; As[ac + 1][ar + 64] = pa1.y;
        As[ac + 2][ar + 64] = pa1.z; As[ac + 3][ar + 64] = pa1.w;
        *(float4*)&Bs[br][bc] = pb;
        __syncthreads();
        if (k0 + 8 < Tc) {
            pa0 = *(const float4*)(Aptr0 + k0 + 8);
            pa1 = *(const float4*)(Aptr1 + k0 + 8);
            pb  = *(const float4*)(Bptr + (size_t)(k0 + 8) * Dc);
        }
        #pragma unroll
        for (int kk = 0; kk < 8; kk++) {
            float4 a0v = *(const float4*)&As[kk][ty * 4];
            float4 a1v = *(const float4*)&As[kk][ty * 4 + 64];
            ulonglong2 b0v = *(const ulonglong2*)&Bs[kk][tx * 4];
            ulonglong2 b1v = *(const ulonglong2*)&Bs[kk][tx * 4 + 32];
            u64t bp[4] = {b0v.x, b0v.y, b1v.x, b1v.y};
            float av[8] = {a0v.x,a0v.y,a0v.z,a0v.w,a1v.x,a1v.y,a1v.z,a1v.w};
            #pragma unroll
            for (int i = 0; i < 8; i++) {
                u64t ad = dup2(av[i]);
                #pragma unroll
                for (int jp = 0; jp < 4; jp++)
                    fma2(acc2[i][jp], ad, bp[jp]);
            }
        }
        __syncthreads();
    }
    #pragma unroll
    for (int i = 0; i < 8; i++) {
        int qg = q0 + ty * 4 + (i & 3) + (i >> 2) * 64;
        float* crow = g_ctx + ((size_t)b * Tc + qg) * Dc + h * Ac;
        #pragma unroll
        for (int jh = 0; jh < 2; jh++) {
            int n = tx * 4 + jh * 32;
            float4 v;
            unpack2(acc2[i][jh*2+0], v.x, v.y);
            unpack2(acc2[i][jh*2+1], v.z, v.w);
            *(float4*)(crow + n) = v;
        }
    }
}

// ---------------- host driver -----------------------------------------------
extern "C" void kernel_launch(void* const* d_in, const int* in_sizes, int n_in,
                              void* d_out, int out_size)
{
    const int*   tokens = (const int*)  d_in[0];
    const float* masks  = (const float*)d_in[1];
    const int*   ab     = (const int*)  d_in[2];
    const float* embed  = (const float*)d_in[3];
    const float* Wq     = (const float*)d_in[4];
    const float* Wk     = (const float*)d_in[5];
    const float* Wv     = (const float*)d_in[6];
    const float* Wo     = (const float*)d_in[7];
    const float* be     = (const float*)d_in[8];
    const float* bs     = (const float*)d_in[9];
    const float* ln_g   = (const float*)d_in[10];
    const float* ln_b   = (const float*)d_in[11];
    const float* ff1w   = (const float*)d_in[12];
    const float* ff1b   = (const float*)d_in[13];
    const float* ff2w   = (const float*)d_in[14];
    const float* ff2b   = (const float*)d_in[15];
    const float* lng    = (const float*)d_in[16];
    const float* lnb    = (const float*)d_in[17];
    float* out = (float*)d_out;

    float *x, *h, *q, *k, *v, *ctx, *dense, *ffh;
    cudaGetSymbolAddress((void**)&x,     g_x);
    cudaGetSymbolAddress((void**)&h,     g_h);
    cudaGetSymbolAddress((void**)&q,     g_q);
    cudaGetSymbolAddress((void**)&k,     g_k);
    cudaGetSymbolAddress((void**)&v,     g_v);
    cudaGetSymbolAddress((void**)&ctx,   g_ctx);
    cudaGetSymbolAddress((void**)&dense, g_dense);
    cudaGetSymbolAddress((void**)&ffh,   g_ffh);

    const int MT = Bc * Tc;                 // 8192 tokens

    embed_pe_kernel<<<MT, 512>>>(tokens, embed);

    for (int l = 0; l < Lc; l++) {
        const float* Wq_l  = Wq + (size_t)l * Dc * Dc;
        const float* Wk_l  = Wk + (size_t)l * Dc * Dc;
        const float* Wv_l  = Wv + (size_t)l * Dc * Dc;
        const float* Wo_l  = Wo + (size_t)l * Dc * Dc;
        const float* be_l  = be + (size_t)l * BIASDIM * Ac;
        const float* bs_l  = bs + (size_t)l * Ac;
        const float* ln1g  = ln_g + (size_t)l * 2 * Dc;
        const float* ln1b  = ln_b + (size_t)l * 2 * Dc;
        const float* ln2g  = ln1g + Dc;
        const float* ln2b  = ln1b + Dc;
        const float* f1w   = ff1w + (size_t)l * Dc * Fc;
        const float* f1b   = ff1b + (size_t)l * Fc;
        const float* f2w   = ff2w + (size_t)l * Fc * Dc;
        const float* f2b   = ff2b + (size_t)l * Dc;

        layernorm_kernel<<<MT, 256>>>(x, ln1g, ln1b, h);

        gemm_nn_128<<<dim3(Dc/128, MT/128), 256>>>(h, Wq_l, nullptr, nullptr, q, MT, Dc, Dc, 0);
        gemm_nn_128<<<dim3(Dc/128, MT/128), 256>>>(h, Wk_l, nullptr, nullptr, k, MT, Dc, Dc, 0);
        gemm_nn_128<<<dim3(Dc/128, MT/128), 256>>>(h, Wv_l, nullptr, nullptr, v, MT, Dc, Dc, 0);

        ksum_kernel<<<(Bc*Tc*Hc + 255)/256, 256>>>();

        zero_kernel<<<(Bc*Tc*Tc/4 + 255)/256, 256>>>(dense, Bc*Tc*Tc/4);
        bias_scatter_kernel<<<(Ec + 255)/256, 256>>>(ab, be_l, bs_l);

        attn_score_kernel<<<dim3(Tc/128, Tc/128, Bc*Hc), 256>>>(masks);
        softmax_kernel<<<Bc*Hc*Tc, 128>>>();

        attn_ctx_kernel<<<dim3(Tc/128, Bc*Hc), 128>>>();
        gemm_nn_128<<<dim3(Dc/128, MT/128), 256>>>(ctx, Wo_l, nullptr, x, x, MT, Dc, Dc, 0);

        layernorm_kernel<<<MT, 256>>>(x, ln2g, ln2b, h);
        gemm_nn_128<<<dim3(Fc/128, MT/128), 256>>>(h, f1w, f1b, nullptr, ffh, MT, Fc, Dc, 1);
        gemm_nn_128<<<dim3(Dc/128, MT/128), 256>>>(ffh, f2w, f2b, x, x, MT, Dc, Fc, 0);
    }

    layernorm_kernel<<<MT, 256>>>(x, lng, lnb, out);
}

// round 5
// speedup vs baseline: 1.5625x; 1.5625x over previous
#include <cuda_runtime.h>
#include <cuda_bf16.h>
#include <math.h>
#include <stdint.h>

#define Lc 6
#define Bc 16
#define Tc 512
#define Dc 512
#define Hc 8
#define Ac 64
#define Fc 2048
#define Ec 200000
#define BIASDIM 4

typedef __nv_bfloat16 bf16;

// ======================= helpers =============================================
__device__ __forceinline__ uint32_t smem_u32(const void* p) {
    uint32_t a;
    asm("{ .reg .u64 t; cvta.to.shared.u64 t, %1; cvt.u32.u64 %0, t; }"
        : "=r"(a) : "l"(p));
    return a;
}
__device__ __forceinline__ void cp16(uint32_t s, const void* g) {
    asm volatile("cp.async.cg.shared.global [%0], [%1], 16;" :: "r"(s), "l"(g));
}
__device__ __forceinline__ uint32_t lds32(uint32_t a) {
    uint32_t v;
    asm volatile("ld.shared.b32 %0, [%1];" : "=r"(v) : "r"(a));
    return v;
}
__device__ __forceinline__ void mma16816(float* c, const uint32_t* a,
                                         const uint32_t* b) {
    asm volatile("mma.sync.aligned.m16n8k16.row.col.f32.bf16.bf16.f32 "
        "{%0,%1,%2,%3}, {%4,%5,%6,%7}, {%8,%9}, {%0,%1,%2,%3};"
        : "+f"(c[0]), "+f"(c[1]), "+f"(c[2]), "+f"(c[3])
        : "r"(a[0]), "r"(a[1]), "r"(a[2]), "r"(a[3]), "r"(b[0]), "r"(b[1]));
}
__device__ __forceinline__ uint32_t pack_hi(float v0, float v1, float& r0, float& r1) {
    bf16 h0 = __float2bfloat16_rn(v0), h1 = __float2bfloat16_rn(v1);
    r0 = v0 - __bfloat162float(h0);
    r1 = v1 - __bfloat162float(h1);
    unsigned short u0 = *reinterpret_cast<unsigned short*>(&h0);
    unsigned short u1 = *reinterpret_cast<unsigned short*>(&h1);
    return (uint32_t)u0 | ((uint32_t)u1 << 16);
}
__device__ __forceinline__ uint32_t pack_bf(float v0, float v1) {
    bf16 h0 = __float2bfloat16_rn(v0), h1 = __float2bfloat16_rn(v1);
    unsigned short u0 = *reinterpret_cast<unsigned short*>(&h0);
    unsigned short u1 = *reinterpret_cast<unsigned short*>(&h1);
    return (uint32_t)u0 | ((uint32_t)u1 << 16);
}

// ---------------- scratch (device globals; no allocations) ------------------
__device__ float g_x[Bc*Tc*Dc];
__device__ float g_q[Bc*Tc*Dc];
__device__ float g_k[Bc*Tc*Dc];
__device__ float g_v[Bc*Tc*Dc];
__device__ float g_ksum[Bc*Hc*Tc];
__device__ float g_dense[Bc*Tc*Tc];
__device__ float g_alpha[(size_t)Bc*Hc*Tc*Tc];
// bf16 hi/lo activations
__device__ bf16 g_hh[Bc*Tc*Dc],  g_hl[Bc*Tc*Dc];
__device__ bf16 g_ch[Bc*Tc*Dc],  g_cl[Bc*Tc*Dc];
__device__ bf16 g_fh[Bc*Tc*Fc],  g_fl[Bc*Tc*Fc];
// transposed bf16 hi/lo weights  [N][K] per layer
__device__ bf16 g_wqTh[Lc*Dc*Dc], g_wqTl[Lc*Dc*Dc];
__device__ bf16 g_wkTh[Lc*Dc*Dc], g_wkTl[Lc*Dc*Dc];
__device__ bf16 g_wvTh[Lc*Dc*Dc], g_wvTl[Lc*Dc*Dc];
__device__ bf16 g_woTh[Lc*Dc*Dc], g_woTl[Lc*Dc*Dc];
__device__ bf16 g_f1Th[Lc*Dc*Fc], g_f1Tl[Lc*Dc*Fc];
__device__ bf16 g_f2Th[Lc*Fc*Dc], g_f2Tl[Lc*Fc*Dc];

// ======================= weight transpose+convert ============================
// W [K][N] f32 -> WT hi/lo [N][K] bf16.  grid (N/32, K/32, nmat), block (32,8)
__global__ void wconv_kernel(const float* __restrict__ W,
                             bf16* __restrict__ Th, bf16* __restrict__ Tl,
                             int K, int N)
{
    __shared__ float tile[32][33];
    size_t zoff = (size_t)blockIdx.z * K * N;
    const float* Wz = W + zoff;
    bf16* Thz = Th + zoff;
    bf16* Tlz = Tl + zoff;
    int n0 = blockIdx.x * 32, k0 = blockIdx.y * 32;
    int tx = threadIdx.x, ty = threadIdx.y;
    #pragma unroll
    for (int i = 0; i < 4; i++)
        tile[ty + 8*i][tx] = Wz[(size_t)(k0 + ty + 8*i) * N + n0 + tx];
    __syncthreads();
    #pragma unroll
    for (int i = 0; i < 4; i++) {
        int n = n0 + ty + 8*i, k = k0 + tx;
        float v = tile[tx][ty + 8*i];
        bf16 h = __float2bfloat16_rn(v);
        Thz[(size_t)n * K + k] = h;
        Tlz[(size_t)n * K + k] = __float2bfloat16_rn(v - __bfloat162float(h));
    }
}

// ======================= bf16-split MMA GEMM =================================
// C[M,N] = A[M,K] @ B^T[N,K]  (split hi/lo, 3 products), +bias/relu/resid.
// grid (N/128, M/128), 256 threads. Dynamic smem 2*40960.
#define STG 40960u
__global__ __launch_bounds__(256) void gemm_mma(
    const bf16* __restrict__ Ahi, const bf16* __restrict__ Alo,
    const bf16* __restrict__ Bhi, const bf16* __restrict__ Blo,
    const float* __restrict__ bias, const float* __restrict__ resid,
    float* __restrict__ Cf, bf16* __restrict__ Ch, bf16* __restrict__ Cl,
    int M, int N, int K, int do_relu)
{
    extern __shared__ char smem[];
    uint32_t sb = smem_u32(smem);
    int t = threadIdx.x;
    int lane = t & 31, w = t >> 5;
    int row0 = blockIdx.y * 128, col0 = blockIdx.x * 128;
    int warpM = (w & 3) * 32, warpN = (w >> 2) * 64;
    int g = lane >> 2, tg = lane & 3;

    // stage loaders: thread -> row (t>>1), k-offset (t&1)*16
    int arow = t >> 1, koff = (t & 1) * 16;
    const bf16* pAh = Ahi + (size_t)(row0 + arow) * K + koff;
    const bf16* pAl = Alo + (size_t)(row0 + arow) * K + koff;
    const bf16* pBh = Bhi + (size_t)(col0 + arow) * K + koff;
    const bf16* pBl = Blo + (size_t)(col0 + arow) * K + koff;
    uint32_t soff = (uint32_t)(arow * 80 + koff * 2);

    float c[2][8][4];
    #pragma unroll
    for (int i = 0; i < 2; i++)
        #pragma unroll
        for (int j = 0; j < 8; j++)
            #pragma unroll
            for (int r = 0; r < 4; r++) c[i][j][r] = 0.0f;

    int ns = K / 32;

    auto issue = [&](int kt) {
        uint32_t base = sb + (uint32_t)(kt & 1) * STG;
        const bf16* a;
        a = pAh + kt * 32;
        cp16(base + soff, a);                 cp16(base + soff + 16, a + 8);
        a = pAl + kt * 32;
        cp16(base + 10240 + soff, a);         cp16(base + 10240 + soff + 16, a + 8);
        a = pBh + kt * 32;
        cp16(base + 20480 + soff, a);         cp16(base + 20480 + soff + 16, a + 8);
        a = pBl + kt * 32;
        cp16(base + 30720 + soff, a);         cp16(base + 30720 + soff + 16, a + 8);
        asm volatile("cp.async.commit_group;" ::: "memory");
    };

    issue(0);
    for (int kt = 0; kt < ns; kt++) {
        if (kt + 1 < ns) {
            issue(kt + 1);
            asm volatile("cp.async.wait_group 1;" ::: "memory");
        } else {
            asm volatile("cp.async.wait_group 0;" ::: "memory");
        }
        __syncthreads();
        uint32_t base = sb + (uint32_t)(kt & 1) * STG;
        #pragma unroll
        for (int ks = 0; ks < 2; ks++) {
            int k0 = ks * 16;
            uint32_t bh[8][2], bl[8][2];
            #pragma unroll
            for (int bn = 0; bn < 8; bn++) {
                uint32_t r_ = (uint32_t)((warpN + bn*8 + g) * 80 + (tg*2 + k0) * 2);
                bh[bn][0] = lds32(base + 20480 + r_);
                bh[bn][1] = lds32(base + 20480 + r_ + 16);
                bl[bn][0] = lds32(base + 30720 + r_);
                bl[bn][1] = lds32(base + 30720 + r_ + 16);
            }
            #pragma unroll
            for (int am = 0; am < 2; am++) {
                uint32_t ah[4], al[4];
                #pragma unroll
                for (int r = 0; r < 4; r++) {
                    int rr = warpM + am*16 + g + (r & 1)*8;
                    int cc = tg*2 + (r >> 1)*8 + k0;
                    uint32_t ad = (uint32_t)(rr * 80 + cc * 2);
                    ah[r] = lds32(base + ad);
                    al[r] = lds32(base + 10240 + ad);
                }
                #pragma unroll
                for (int bn = 0; bn < 8; bn++) {
                    mma16816(c[am][bn], ah, bh[bn]);
                    mma16816(c[am][bn], ah, bl[bn]);
                    mma16816(c[am][bn], al, bh[bn]);
                }
            }
        }
        __syncthreads();
    }

    // epilogue
    #pragma unroll
    for (int am = 0; am < 2; am++) {
        #pragma unroll
        for (int bn = 0; bn < 8; bn++) {
            int n = col0 + warpN + bn*8 + tg*2;
            #pragma unroll
            for (int hf = 0; hf < 2; hf++) {
                int m = row0 + warpM + am*16 + g + hf*8;
                float v0 = c[am][bn][hf*2+0], v1 = c[am][bn][hf*2+1];
                if (bias) { v0 += bias[n]; v1 += bias[n+1]; }
                if (do_relu) { v0 = fmaxf(v0, 0.f); v1 = fmaxf(v1, 0.f); }
                if (resid) {
                    float2 r = *(const float2*)(resid + (size_t)m * N + n);
                    v0 += r.x; v1 += r.y;
                }
                if (Cf) *(float2*)(Cf + (size_t)m * N + n) = make_float2(v0, v1);
                if (Ch) {
                    float l0, l1;
                    uint32_t hp = pack_hi(v0, v1, l0, l1);
                    *(uint32_t*)(Ch + (size_t)m * N + n) = hp;
                    *(uint32_t*)(Cl + (size_t)m * N + n) = pack_bf(l0, l1);
                }
            }
        }
    }
}

// ---------------- embedding + positional encoding ---------------------------
__global__ __launch_bounds__(512) void embed_pe_kernel(
    const int* __restrict__ tokens, const float* __restrict__ embed)
{
    int bt = blockIdx.x;
    int d  = threadIdx.x;
    int t  = bt % Tc;
    int tok = tokens[bt];
    float val = embed[(size_t)tok * Dc + d] * 22.62741699796952f;
    float expo  = (2.0f * (float)(d >> 1)) / (float)Dc;
    float denom = powf(10000.0f, expo);
    float angle = (float)t / denom;
    val += ((d & 1) == 0) ? sinf(angle) : cosf(angle);
    g_x[(size_t)bt * Dc + d] = val;
}

// ---------------- layernorm: f32 out and/or bf16 hi/lo out -------------------
__global__ __launch_bounds__(256) void layernorm_kernel(
    const float* __restrict__ in, const float* __restrict__ gamma,
    const float* __restrict__ beta, float* __restrict__ outf,
    bf16* __restrict__ oh, bf16* __restrict__ ol)
{
    __shared__ float red[256];
    size_t base = (size_t)blockIdx.x * Dc;
    int tid = threadIdx.x;
    float v0 = in[base + tid];
    float v1 = in[base + tid + 256];
    red[tid] = v0 + v1;
    __syncthreads();
    #pragma unroll
    for (int s = 128; s > 0; s >>= 1) {
        if (tid < s) red[tid] += red[tid + s];
        __syncthreads();
    }
    float mu = red[0] * (1.0f / Dc);
    __syncthreads();
    float d0 = v0 - mu, d1 = v1 - mu;
    red[tid] = d0 * d0 + d1 * d1;
    __syncthreads();
    #pragma unroll
    for (int s = 128; s > 0; s >>= 1) {
        if (tid < s) red[tid] += red[tid + s];
        __syncthreads();
    }
    float rstd = rsqrtf(red[0] * (1.0f / Dc) + 1e-3f);
    float o0 = d0 * rstd * gamma[tid]       + beta[tid];
    float o1 = d1 * rstd * gamma[tid + 256] + beta[tid + 256];
    if (outf) {
        outf[base + tid]       = o0;
        outf[base + tid + 256] = o1;
    }
    if (oh) {
        bf16 h0 = __float2bfloat16_rn(o0);
        bf16 h1 = __float2bfloat16_rn(o1);
        oh[base + tid]       = h0;
        oh[base + tid + 256] = h1;
        ol[base + tid]       = __float2bfloat16_rn(o0 - __bfloat162float(h0));
        ol[base + tid + 256] = __float2bfloat16_rn(o1 - __bfloat162float(h1));
    }
}

// ---------------- ksum[b,h,t] ------------------------------------------------
__global__ __launch_bounds__(256) void ksum_kernel(void)
{
    int i = blockIdx.x * blockDim.x + threadIdx.x;
    if (i >= Bc * Tc * Hc) return;
    int bt = i >> 3, h = i & 7;
    int b = bt / Tc, tt = bt % Tc;
    const float* p = g_k + (size_t)bt * Dc + h * Ac;
    float s = 0.0f;
    #pragma unroll
    for (int a = 0; a < Ac; a += 4) {
        float4 w = *(const float4*)(p + a);
        s += w.x + w.y + w.z + w.w;
    }
    g_ksum[((size_t)b * Hc + h) * Tc + tt] = s;
}

// ---------------- zero -------------------------------------------------------
__global__ __launch_bounds__(256) void zero_kernel(float* __restrict__ p, int n4)
{
    int i = blockIdx.x * blockDim.x + threadIdx.x;
    if (i < n4) ((float4*)p)[i] = make_float4(0.f, 0.f, 0.f, 0.f);
}

// ---------------- sparse edge bias scatter ----------------------------------
__global__ __launch_bounds__(256) void bias_scatter_kernel(
    const int* __restrict__ ab, const float* __restrict__ be_l,
    const float* __restrict__ bs_l)
{
    __shared__ float evtab[BIASDIM];
    if (threadIdx.x < BIASDIM) {
        float s = 0.0f;
        #pragma unroll
        for (int a = 0; a < Ac; a++)
            s += be_l[threadIdx.x * Ac + a] * bs_l[a];
        evtab[threadIdx.x] = s;
    }
    __syncthreads();
    int e = blockIdx.x * blockDim.x + threadIdx.x;
    if (e >= Ec) return;
    int ty = ab[e * 4 + 0];
    int b  = ab[e * 4 + 1];
    int q  = ab[e * 4 + 2];
    int k  = ab[e * 4 + 3];
    atomicAdd(&g_dense[((size_t)b * Tc + q) * Tc + k], evtab[ty]);
}

// ---------------- attention scores (fp32 SIMT, 128x128) ----------------------
__global__ __launch_bounds__(256) void attn_score_kernel(
    const float* __restrict__ masks)
{
    __shared__ __align__(16) float Qs[8][128];
    __shared__ __align__(16) float Ks[8][128];
    int z = blockIdx.z;
    int b = z >> 3, h = z & 7;
    int t = threadIdx.x;
    int q0 = blockIdx.y * 128, c0 = blockIdx.x * 128;

    const float* qb = g_q + (size_t)b * Tc * Dc + h * Ac;
    const float* kb = g_k + (size_t)b * Tc * Dc + h * Ac;

    int ar = t >> 1, ac = (t & 1) * 4;
    const float* Qptr = qb + (size_t)(q0 + ar) * Dc + ac;
    const float* Kptr = kb + (size_t)(c0 + ar) * Dc + ac;

    int tx = t & 15, ty = t >> 4;
    float acc[8][8] = {};

    float4 pq = *(const float4*)Qptr;
    float4 pk = *(const float4*)Kptr;

    for (int a0 = 0; a0 < Ac; a0 += 8) {
        Qs[ac + 0][ar] = pq.x; Qs[ac + 1][ar] = pq.y;
        Qs[ac + 2][ar] = pq.z; Qs[ac + 3][ar] = pq.w;
        Ks[ac + 0][ar] = pk.x; Ks[ac + 1][ar] = pk.y;
        Ks[ac + 2][ar] = pk.z; Ks[ac + 3][ar] = pk.w;
        __syncthreads();
        if (a0 + 8 < Ac) {
            pq = *(const float4*)(Qptr + a0 + 8);
            pk = *(const float4*)(Kptr + a0 + 8);
        }
        #pragma unroll
        for (int kk = 0; kk < 8; kk++) {
            float4 a0v = *(const float4*)&Qs[kk][ty * 4];
            float4 a1v = *(const float4*)&Qs[kk][ty * 4 + 64];
            float4 b0v = *(const float4*)&Ks[kk][tx * 4];
            float4 b1v = *(const float4*)&Ks[kk][tx * 4 + 64];
            float av[8] = {a0v.x,a0v.y,a0v.z,a0v.w,a1v.x,a1v.y,a1v.z,a1v.w};
            float bv[8] = {b0v.x,b0v.y,b0v.z,b0v.w,b1v.x,b1v.y,b1v.z,b1v.w};
            #pragma unroll
            for (int i = 0; i < 8; i++)
                #pragma unroll
                for (int j = 0; j < 8; j++)
                    acc[i][j] += av[i] * bv[j];
        }
        __syncthreads();
    }

    const float* ksrow = g_ksum + ((size_t)b * Hc + h) * Tc;
    #pragma unroll
    for (int i = 0; i < 8; i++) {
        int qg = q0 + ty * 4 + (i & 3) + (i >> 2) * 64;
        size_t drow = ((size_t)b * Tc + qg) * Tc;
        size_t orow = ((size_t)z * Tc + qg) * Tc;
        #pragma unroll
        for (int jh = 0; jh < 2; jh++) {
            int n = c0 + tx * 4 + jh * 64;
            float4 dv = *(const float4*)(g_dense + drow + n);
            float4 ks = *(const float4*)(ksrow + n);
            float4 mk = *(const float4*)(masks + drow + n);
            float aa[4] = {acc[i][jh*4+0], acc[i][jh*4+1],
                           acc[i][jh*4+2], acc[i][jh*4+3]};
            float dd[4] = {dv.x, dv.y, dv.z, dv.w};
            float kk2[4] = {ks.x, ks.y, ks.z, ks.w};
            float mm[4] = {mk.x, mk.y, mk.z, mk.w};
            float r[4];
            #pragma unroll
            for (int j = 0; j < 4; j++) {
                float val = (aa[j] + dd[j] * kk2[j]) * 0.125f;
                r[j] = val * mm[j] + (1.0f - ceilf(mm[j])) * (-3.402823466e38f);
            }
            *(float4*)(g_alpha + orow + n) = make_float4(r[0], r[1], r[2], r[3]);
        }
    }
}

// ---------------- softmax ----------------------------------------------------
__global__ __launch_bounds__(128) void softmax_kernel(void)
{
    __shared__ float red[128];
    size_t base = (size_t)blockIdx.x * Tc;
    int tid = threadIdx.x;
    float4 v = *(float4*)(g_alpha + base + tid * 4);
    float m = fmaxf(fmaxf(v.x, v.y), fmaxf(v.z, v.w));
    red[tid] = m;
    __syncthreads();
    #pragma unroll
    for (int s = 64; s > 0; s >>= 1) {
        if (tid < s) red[tid] = fmaxf(red[tid], red[tid + s]);
        __syncthreads();
    }
    m = red[0];
    __syncthreads();
    float e0 = expf(v.x - m), e1 = expf(v.y - m);
    float e2 = expf(v.z - m), e3 = expf(v.w - m);
    red[tid] = e0 + e1 + e2 + e3;
    __syncthreads();
    #pragma unroll
    for (int s = 64; s > 0; s >>= 1) {
        if (tid < s) red[tid] += red[tid + s];
        __syncthreads();
    }
    float inv = 1.0f / red[0];
    *(float4*)(g_alpha + base + tid * 4) =
        make_float4(e0 * inv, e1 * inv, e2 * inv, e3 * inv);
}

// ---------------- context: ctx = alpha @ V, writes bf16 hi/lo ----------------
// grid (T/128, B*H), 128 threads
__global__ __launch_bounds__(128) void attn_ctx_kernel(void)
{
    __shared__ __align__(16) float As[8][128];
    __shared__ __align__(16) float Bs[8][64];
    int z = blockIdx.y;
    int b = z >> 3, h = z & 7;
    int t = threadIdx.x;
    int q0 = blockIdx.x * 128;

    const float* ap = g_alpha + (size_t)z * Tc * Tc;
    const float* vb = g_v + (size_t)b * Tc * Dc + h * Ac;

    int ar = t >> 1, ac = (t & 1) * 4;
    int br = t >> 4, bc = (t & 15) * 4;
    const float* Aptr0 = ap + (size_t)(q0 + ar) * Tc + ac;
    const float* Aptr1 = ap + (size_t)(q0 + ar + 64) * Tc + ac;
    const float* Bptr  = vb + (size_t)br * Dc + bc;

    int tx = t & 7, ty = t >> 3;
    float acc[8][8] = {};

    float4 pa0 = *(const float4*)Aptr0;
    float4 pa1 = *(const float4*)Aptr1;
    float4 pb  = *(const float4*)Bptr;

    for (int k0 = 0; k0 < Tc; k0 += 8) {
        As[ac + 0][ar] = pa0.x; As[ac + 1][ar] = pa0.y;
        As[ac + 2][ar] = pa0.z; As[ac + 3][ar] = pa0.w;
        As[ac + 0][ar + 64] = pa1.x; As[ac + 1][ar + 64] = pa1.y;
        As[ac + 2][ar + 64] = pa1.z; As[ac + 3][ar + 64] = pa1.w;
        *(float4*)&Bs[br][bc] = pb;
        __syncthreads();
        if (k0 + 8 < Tc) {
            pa0 = *(const float4*)(Aptr0 + k0 + 8);
            pa1 = *(const float4*)(Aptr1 + k0 + 8);
            pb  = *(const float4*)(Bptr + (size_t)(k0 + 8) * Dc);
        }
        #pragma unroll
        for (int kk = 0; kk < 8; kk++) {
            float4 a0v = *(const float4*)&As[kk][ty * 4];
            float4 a1v = *(const float4*)&As[kk][ty * 4 + 64];
            float4 b0v = *(const float4*)&Bs[kk][tx * 4];
            float4 b1v = *(const float4*)&Bs[kk][tx * 4 + 32];
            float av[8] = {a0v.x,a0v.y,a0v.z,a0v.w,a1v.x,a1v.y,a1v.z,a1v.w};
            float bv[8] = {b0v.x,b0v.y,b0v.z,b0v.w,b1v.x,b1v.y,b1v.z,b1v.w};
            #pragma unroll
            for (int i = 0; i < 8; i++)
                #pragma unroll
                for (int j = 0; j < 8; j++)
                    acc[i][j] += av[i] * bv[j];
        }
        __syncthreads();
    }
    #pragma unroll
    for (int i = 0; i < 8; i++) {
        int qg = q0 + ty * 4 + (i & 3) + (i >> 2) * 64;
        size_t crow = ((size_t)b * Tc + qg) * Dc + h * Ac;
        #pragma unroll
        for (int jh = 0; jh < 2; jh++) {
            int n = tx * 4 + jh * 32;
            float l0, l1, l2, l3;
            uint32_t h0 = pack_hi(acc[i][jh*4+0], acc[i][jh*4+1], l0, l1);
            uint32_t h1 = pack_hi(acc[i][jh*4+2], acc[i][jh*4+3], l2, l3);
            *(uint32_t*)(g_ch + crow + n)     = h0;
            *(uint32_t*)(g_ch + crow + n + 2) = h1;
            *(uint32_t*)(g_cl + crow + n)     = pack_bf(l0, l1);
            *(uint32_t*)(g_cl + crow + n + 2) = pack_bf(l2, l3);
        }
    }
}

// ---------------- host driver -----------------------------------------------
extern "C" void kernel_launch(void* const* d_in, const int* in_sizes, int n_in,
                              void* d_out, int out_size)
{
    const int*   tokens = (const int*)  d_in[0];
    const float* masks  = (const float*)d_in[1];
    const int*   ab     = (const int*)  d_in[2];
    const float* embed  = (const float*)d_in[3];
    const float* Wq     = (const float*)d_in[4];
    const float* Wk     = (const float*)d_in[5];
    const float* Wv     = (const float*)d_in[6];
    const float* Wo     = (const float*)d_in[7];
    const float* be     = (const float*)d_in[8];
    const float* bs     = (const float*)d_in[9];
    const float* ln_g   = (const float*)d_in[10];
    const float* ln_b   = (const float*)d_in[11];
    const float* ff1w   = (const float*)d_in[12];
    const float* ff1b   = (const float*)d_in[13];
    const float* ff2w   = (const float*)d_in[14];
    const float* ff2b   = (const float*)d_in[15];
    const float* lng    = (const float*)d_in[16];
    const float* lnb    = (const float*)d_in[17];
    float* out = (float*)d_out;

    float *x, *q, *k, *v, *dense;
    bf16 *hh, *hl, *ch, *cl, *fh, *fl;
    bf16 *wqTh,*wqTl,*wkTh,*wkTl,*wvTh,*wvTl,*woTh,*woTl,*f1Th,*f1Tl,*f2Th,*f2Tl;
    cudaGetSymbolAddress((void**)&x,     g_x);
    cudaGetSymbolAddress((void**)&q,     g_q);
    cudaGetSymbolAddress((void**)&k,     g_k);
    cudaGetSymbolAddress((void**)&v,     g_v);
    cudaGetSymbolAddress((void**)&dense, g_dense);
    cudaGetSymbolAddress((void**)&hh,    g_hh);
    cudaGetSymbolAddress((void**)&hl,    g_hl);
    cudaGetSymbolAddress((void**)&ch,    g_ch);
    cudaGetSymbolAddress((void**)&cl,    g_cl);
    cudaGetSymbolAddress((void**)&fh,    g_fh);
    cudaGetSymbolAddress((void**)&fl,    g_fl);
    cudaGetSymbolAddress((void**)&wqTh,  g_wqTh);
    cudaGetSymbolAddress((void**)&wqTl,  g_wqTl);
    cudaGetSymbolAddress((void**)&wkTh,  g_wkTh);
    cudaGetSymbolAddress((void**)&wkTl,  g_wkTl);
    cudaGetSymbolAddress((void**)&wvTh,  g_wvTh);
    cudaGetSymbolAddress((void**)&wvTl,  g_wvTl);
    cudaGetSymbolAddress((void**)&woTh,  g_woTh);
    cudaGetSymbolAddress((void**)&woTl,  g_woTl);
    cudaGetSymbolAddress((void**)&f1Th,  g_f1Th);
    cudaGetSymbolAddress((void**)&f1Tl,  g_f1Tl);
    cudaGetSymbolAddress((void**)&f2Th,  g_f2Th);
    cudaGetSymbolAddress((void**)&f2Tl,  g_f2Tl);

    cudaFuncSetAttribute(gemm_mma, cudaFuncAttributeMaxDynamicSharedMemorySize,
                         2 * STG);

    const int MT = Bc * Tc;                 // 8192 tokens
    dim3 wb(32, 8);

    // one-time (per launch) weight transpose + hi/lo convert
    wconv_kernel<<<dim3(16, 16, Lc), wb>>>(Wq,   wqTh, wqTl, Dc, Dc);
    wconv_kernel<<<dim3(16, 16, Lc), wb>>>(Wk,   wkTh, wkTl, Dc, Dc);
    wconv_kernel<<<dim3(16, 16, Lc), wb>>>(Wv,   wvTh, wvTl, Dc, Dc);
    wconv_kernel<<<dim3(16, 16, Lc), wb>>>(Wo,   woTh, woTl, Dc, Dc);
    wconv_kernel<<<dim3(64, 16, Lc), wb>>>(ff1w, f1Th, f1Tl, Dc, Fc);
    wconv_kernel<<<dim3(16, 64, Lc), wb>>>(ff2w, f2Th, f2Tl, Fc, Dc);

    embed_pe_kernel<<<MT, 512>>>(tokens, embed);

    for (int l = 0; l < Lc; l++) {
        size_t wo1 = (size_t)l * Dc * Dc;
        size_t wf1 = (size_t)l * Dc * Fc;
        size_t wf2 = (size_t)l * Fc * Dc;
        const float* be_l  = be + (size_t)l * BIASDIM * Ac;
        const float* bs_l  = bs + (size_t)l * Ac;
        const float* ln1g  = ln_g + (size_t)l * 2 * Dc;
        const float* ln1b  = ln_b + (size_t)l * 2 * Dc;
        const float* ln2g  = ln1g + Dc;
        const float* ln2b  = ln1b + Dc;
        const float* f1b   = ff1b + (size_t)l * Fc;
        const float* f2b   = ff2b + (size_t)l * Dc;

        // LN1 -> bf16 hi/lo
        layernorm_kernel<<<MT, 256>>>(x, ln1g, ln1b, nullptr, hh, hl);

        // QKV projections (tensor-core)
        gemm_mma<<<dim3(Dc/128, MT/128), 256, 2*STG>>>(hh, hl, wqTh+wo1, wqTl+wo1,
            nullptr, nullptr, q, nullptr, nullptr, MT, Dc, Dc, 0);
        gemm_mma<<<dim3(Dc/128, MT/128), 256, 2*STG>>>(hh, hl, wkTh+wo1, wkTl+wo1,
            nullptr, nullptr, k, nullptr, nullptr, MT, Dc, Dc, 0);
        gemm_mma<<<dim3(Dc/128, MT/128), 256, 2*STG>>>(hh, hl, wvTh+wo1, wvTl+wo1,
            nullptr, nullptr, v, nullptr, nullptr, MT, Dc, Dc, 0);

        ksum_kernel<<<(Bc*Tc*Hc + 255)/256, 256>>>();

        zero_kernel<<<(Bc*Tc*Tc/4 + 255)/256, 256>>>(dense, Bc*Tc*Tc/4);
        bias_scatter_kernel<<<(Ec + 255)/256, 256>>>(ab, be_l, bs_l);

        attn_score_kernel<<<dim3(Tc/128, Tc/128, Bc*Hc), 256>>>(masks);
        softmax_kernel<<<Bc*Hc*Tc, 128>>>();

        // context -> bf16 hi/lo, then Wo projection + residual
        attn_ctx_kernel<<<dim3(Tc/128, Bc*Hc), 128>>>();
        gemm_mma<<<dim3(Dc/128, MT/128), 256, 2*STG>>>(ch, cl, woTh+wo1, woTl+wo1,
            nullptr, x, x, nullptr, nullptr, MT, Dc, Dc, 0);

        // LN2 -> bf16 hi/lo, FFN
        layernorm_kernel<<<MT, 256>>>(x, ln2g, ln2b, nullptr, hh, hl);
        gemm_mma<<<dim3(Fc/128, MT/128), 256, 2*STG>>>(hh, hl, f1Th+wf1, f1Tl+wf1,
            f1b, nullptr, nullptr, fh, fl, MT, Fc, Dc, 1);
        gemm_mma<<<dim3(Dc/128, MT/128), 256, 2*STG>>>(fh, fl, f2Th+wf2, f2Tl+wf2,
            f2b, x, x, nullptr, nullptr, MT, Dc, Fc, 0);
    }

    layernorm_kernel<<<MT, 256>>>(x, lng, lnb, out, nullptr, nullptr);
}

// round 6
// speedup vs baseline: 1.7671x; 1.1309x over previous
#include <cuda_runtime.h>
#include <cuda_bf16.h>
#include <math.h>
#include <stdint.h>

#define Lc 6
#define Bc 16
#define Tc 512
#define Dc 512
#define Hc 8
#define Ac 64
#define Fc 2048
#define Ec 200000
#define BIASDIM 4

typedef __nv_bfloat16 bf16;

// ======================= helpers =============================================
__device__ __forceinline__ uint32_t smem_u32(const void* p) {
    uint32_t a;
    asm("{ .reg .u64 t; cvta.to.shared.u64 t, %1; cvt.u32.u64 %0, t; }"
        : "=r"(a) : "l"(p));
    return a;
}
__device__ __forceinline__ void cp16(uint32_t s, const void* g) {
    asm volatile("cp.async.cg.shared.global [%0], [%1], 16;" :: "r"(s), "l"(g));
}
__device__ __forceinline__ uint32_t lds32(uint32_t a) {
    uint32_t v;
    asm volatile("ld.shared.b32 %0, [%1];" : "=r"(v) : "r"(a));
    return v;
}
__device__ __forceinline__ void mma16816(float* c, const uint32_t* a,
                                         const uint32_t* b) {
    asm volatile("mma.sync.aligned.m16n8k16.row.col.f32.bf16.bf16.f32 "
        "{%0,%1,%2,%3}, {%4,%5,%6,%7}, {%8,%9}, {%0,%1,%2,%3};"
        : "+f"(c[0]), "+f"(c[1]), "+f"(c[2]), "+f"(c[3])
        : "r"(a[0]), "r"(a[1]), "r"(a[2]), "r"(a[3]), "r"(b[0]), "r"(b[1]));
}
__device__ __forceinline__ void ldmx4(uint32_t* r, uint32_t a) {
    asm volatile("ldmatrix.sync.aligned.m8n8.x4.shared.b16 {%0,%1,%2,%3}, [%4];"
        : "=r"(r[0]), "=r"(r[1]), "=r"(r[2]), "=r"(r[3]) : "r"(a));
}
__device__ __forceinline__ void ldmx4t(uint32_t* r, uint32_t a) {
    asm volatile("ldmatrix.sync.aligned.m8n8.x4.trans.shared.b16 {%0,%1,%2,%3}, [%4];"
        : "=r"(r[0]), "=r"(r[1]), "=r"(r[2]), "=r"(r[3]) : "r"(a));
}
__device__ __forceinline__ uint32_t pack_hi(float v0, float v1, float& r0, float& r1) {
    bf16 h0 = __float2bfloat16_rn(v0), h1 = __float2bfloat16_rn(v1);
    r0 = v0 - __bfloat162float(h0);
    r1 = v1 - __bfloat162float(h1);
    unsigned short u0 = *reinterpret_cast<unsigned short*>(&h0);
    unsigned short u1 = *reinterpret_cast<unsigned short*>(&h1);
    return (uint32_t)u0 | ((uint32_t)u1 << 16);
}
__device__ __forceinline__ uint32_t pack_bf(float v0, float v1) {
    bf16 h0 = __float2bfloat16_rn(v0), h1 = __float2bfloat16_rn(v1);
    unsigned short u0 = *reinterpret_cast<unsigned short*>(&h0);
    unsigned short u1 = *reinterpret_cast<unsigned short*>(&h1);
    return (uint32_t)u0 | ((uint32_t)u1 << 16);
}

// ---------------- scratch (device globals; no allocations) ------------------
__device__ float g_x[Bc*Tc*Dc];
__device__ float g_ksum[Bc*Hc*Tc];
__device__ float g_dense[Bc*Tc*Tc];
// bf16 hi/lo activations
__device__ bf16 g_hh[Bc*Tc*Dc],  g_hl[Bc*Tc*Dc];
__device__ bf16 g_qh[Bc*Tc*Dc],  g_ql[Bc*Tc*Dc];
__device__ bf16 g_kh[Bc*Tc*Dc],  g_kl[Bc*Tc*Dc];
__device__ bf16 g_vh[Bc*Tc*Dc],  g_vl[Bc*Tc*Dc];
__device__ bf16 g_ch[Bc*Tc*Dc],  g_cl[Bc*Tc*Dc];
__device__ bf16 g_fh[Bc*Tc*Fc],  g_fl[Bc*Tc*Fc];
// transposed bf16 hi/lo weights  [N][K] per layer
__device__ bf16 g_wqTh[Lc*Dc*Dc], g_wqTl[Lc*Dc*Dc];
__device__ bf16 g_wkTh[Lc*Dc*Dc], g_wkTl[Lc*Dc*Dc];
__device__ bf16 g_wvTh[Lc*Dc*Dc], g_wvTl[Lc*Dc*Dc];
__device__ bf16 g_woTh[Lc*Dc*Dc], g_woTl[Lc*Dc*Dc];
__device__ bf16 g_f1Th[Lc*Dc*Fc], g_f1Tl[Lc*Dc*Fc];
__device__ bf16 g_f2Th[Lc*Fc*Dc], g_f2Tl[Lc*Fc*Dc];

// ======================= weight transpose+convert ============================
__global__ void wconv_kernel(const float* __restrict__ W,
                             bf16* __restrict__ Th, bf16* __restrict__ Tl,
                             int K, int N)
{
    __shared__ float tile[32][33];
    size_t zoff = (size_t)blockIdx.z * K * N;
    const float* Wz = W + zoff;
    bf16* Thz = Th + zoff;
    bf16* Tlz = Tl + zoff;
    int n0 = blockIdx.x * 32, k0 = blockIdx.y * 32;
    int tx = threadIdx.x, ty = threadIdx.y;
    #pragma unroll
    for (int i = 0; i < 4; i++)
        tile[ty + 8*i][tx] = Wz[(size_t)(k0 + ty + 8*i) * N + n0 + tx];
    __syncthreads();
    #pragma unroll
    for (int i = 0; i < 4; i++) {
        int n = n0 + ty + 8*i, k = k0 + tx;
        float v = tile[tx][ty + 8*i];
        bf16 h = __float2bfloat16_rn(v);
        Thz[(size_t)n * K + k] = h;
        Tlz[(size_t)n * K + k] = __float2bfloat16_rn(v - __bfloat162float(h));
    }
}

// ======================= bf16-split MMA GEMM (dense projections) =============
#define STG 40960u
__global__ __launch_bounds__(256) void gemm_mma(
    const bf16* __restrict__ Ahi, const bf16* __restrict__ Alo,
    const bf16* __restrict__ Bhi, const bf16* __restrict__ Blo,
    const float* __restrict__ bias, const float* __restrict__ resid,
    float* __restrict__ Cf, bf16* __restrict__ Ch, bf16* __restrict__ Cl,
    int M, int N, int K, int do_relu)
{
    extern __shared__ char smem[];
    uint32_t sb = smem_u32(smem);
    int t = threadIdx.x;
    int lane = t & 31, w = t >> 5;
    int row0 = blockIdx.y * 128, col0 = blockIdx.x * 128;
    int warpM = (w & 3) * 32, warpN = (w >> 2) * 64;
    int g = lane >> 2, tg = lane & 3;

    int arow = t >> 1, koff = (t & 1) * 16;
    const bf16* pAh = Ahi + (size_t)(row0 + arow) * K + koff;
    const bf16* pAl = Alo + (size_t)(row0 + arow) * K + koff;
    const bf16* pBh = Bhi + (size_t)(col0 + arow) * K + koff;
    const bf16* pBl = Blo + (size_t)(col0 + arow) * K + koff;
    uint32_t soff = (uint32_t)(arow * 80 + koff * 2);

    float c[2][8][4];
    #pragma unroll
    for (int i = 0; i < 2; i++)
        #pragma unroll
        for (int j = 0; j < 8; j++)
            #pragma unroll
            for (int r = 0; r < 4; r++) c[i][j][r] = 0.0f;

    int ns = K / 32;

    auto issue = [&](int kt) {
        uint32_t base = sb + (uint32_t)(kt & 1) * STG;
        const bf16* a;
        a = pAh + kt * 32;
        cp16(base + soff, a);                 cp16(base + soff + 16, a + 8);
        a = pAl + kt * 32;
        cp16(base + 10240 + soff, a);         cp16(base + 10240 + soff + 16, a + 8);
        a = pBh + kt * 32;
        cp16(base + 20480 + soff, a);         cp16(base + 20480 + soff + 16, a + 8);
        a = pBl + kt * 32;
        cp16(base + 30720 + soff, a);         cp16(base + 30720 + soff + 16, a + 8);
        asm volatile("cp.async.commit_group;" ::: "memory");
    };

    issue(0);
    for (int kt = 0; kt < ns; kt++) {
        if (kt + 1 < ns) {
            issue(kt + 1);
            asm volatile("cp.async.wait_group 1;" ::: "memory");
        } else {
            asm volatile("cp.async.wait_group 0;" ::: "memory");
        }
        __syncthreads();
        uint32_t base = sb + (uint32_t)(kt & 1) * STG;
        #pragma unroll
        for (int ks = 0; ks < 2; ks++) {
            int k0 = ks * 16;
            uint32_t bh[8][2], bl[8][2];
            #pragma unroll
            for (int bn = 0; bn < 8; bn++) {
                uint32_t r_ = (uint32_t)((warpN + bn*8 + g) * 80 + (tg*2 + k0) * 2);
                bh[bn][0] = lds32(base + 20480 + r_);
                bh[bn][1] = lds32(base + 20480 + r_ + 16);
                bl[bn][0] = lds32(base + 30720 + r_);
                bl[bn][1] = lds32(base + 30720 + r_ + 16);
            }
            #pragma unroll
            for (int am = 0; am < 2; am++) {
                uint32_t ah[4], al[4];
                #pragma unroll
                for (int r = 0; r < 4; r++) {
                    int rr = warpM + am*16 + g + (r & 1)*8;
                    int cc = tg*2 + (r >> 1)*8 + k0;
                    uint32_t ad = (uint32_t)(rr * 80 + cc * 2);
                    ah[r] = lds32(base + ad);
                    al[r] = lds32(base + 10240 + ad);
                }
                #pragma unroll
                for (int bn = 0; bn < 8; bn++) {
                    mma16816(c[am][bn], ah, bh[bn]);
                    mma16816(c[am][bn], ah, bl[bn]);
                    mma16816(c[am][bn], al, bh[bn]);
                }
            }
        }
        __syncthreads();
    }

    #pragma unroll
    for (int am = 0; am < 2; am++) {
        #pragma unroll
        for (int bn = 0; bn < 8; bn++) {
            int n = col0 + warpN + bn*8 + tg*2;
            #pragma unroll
            for (int hf = 0; hf < 2; hf++) {
                int m = row0 + warpM + am*16 + g + hf*8;
                float v0 = c[am][bn][hf*2+0], v1 = c[am][bn][hf*2+1];
                if (bias) { v0 += bias[n]; v1 += bias[n+1]; }
                if (do_relu) { v0 = fmaxf(v0, 0.f); v1 = fmaxf(v1, 0.f); }
                if (resid) {
                    float2 r = *(const float2*)(resid + (size_t)m * N + n);
                    v0 += r.x; v1 += r.y;
                }
                if (Cf) *(float2*)(Cf + (size_t)m * N + n) = make_float2(v0, v1);
                if (Ch) {
                    float l0, l1;
                    uint32_t hp = pack_hi(v0, v1, l0, l1);
                    *(uint32_t*)(Ch + (size_t)m * N + n) = hp;
                    *(uint32_t*)(Cl + (size_t)m * N + n) = pack_bf(l0, l1);
                }
            }
        }
    }
}

// ======================= fused flash attention ===============================
// grid (T/128, B*H), 256 threads (8 warps, 16 q-rows each).
// S = QK^T (bf16 split 3-mma) + dense*ksum, scaled+masked; online softmax;
// O += P@V (bf16 split 3-mma). ch/cl written as bf16 hi/lo.
#define FS_QH    0u
#define FS_QL    18432u
#define FS_KS    36864u
#define FS_ST    38912u
#define FS_STAGE 73728u
#define FS_K     0u
#define FS_KLO   18432u
#define FS_V     36864u
#define FS_VLO   55296u
#define FS_TOTAL (38912u + 2u * 73728u)

__global__ __launch_bounds__(256) void flash_kernel(
    const float* __restrict__ masks,
    bf16* __restrict__ ch, bf16* __restrict__ cl)
{
    extern __shared__ char smem[];
    uint32_t sb = smem_u32(smem);
    int t = threadIdx.x, lane = t & 31, w = t >> 5;
    int z = blockIdx.y, b = z >> 3, h = z & 7;
    int q0 = blockIdx.x * 128;
    size_t bT = (size_t)b * Tc;

    // load Q hi/lo + ksum row (group 0, together with stage 0)
    {
        int row = t >> 1, half = t & 1;
        size_t gq = (bT + q0 + row) * Dc + h * Ac + half * 32;
        uint32_t so = (uint32_t)(row * 144 + half * 64);
        #pragma unroll
        for (int c4 = 0; c4 < 4; c4++) {
            cp16(sb + FS_QH + so + c4 * 16, g_qh + gq + c4 * 8);
            cp16(sb + FS_QL + so + c4 * 16, g_ql + gq + c4 * 8);
        }
        if (t < 128)
            cp16(sb + FS_KS + t * 16, g_ksum + ((size_t)b * Hc + h) * Tc + t * 4);
    }
    auto issue = [&](int it) {
        uint32_t base = sb + FS_ST + (uint32_t)(it & 1) * FS_STAGE;
        int row = t >> 1, half = t & 1;
        size_t gp = (bT + it * 128 + row) * Dc + h * Ac + half * 32;
        uint32_t so = (uint32_t)(row * 144 + half * 64);
        #pragma unroll
        for (int c4 = 0; c4 < 4; c4++) {
            cp16(base + FS_K   + so + c4 * 16, g_kh + gp + c4 * 8);
            cp16(base + FS_KLO + so + c4 * 16, g_kl + gp + c4 * 8);
            cp16(base + FS_V   + so + c4 * 16, g_vh + gp + c4 * 8);
            cp16(base + FS_VLO + so + c4 * 16, g_vl + gp + c4 * 8);
        }
        asm volatile("cp.async.commit_group;" ::: "memory");
    };
    issue(0);

    int wm = w * 16;
    int g = lane >> 2, tg = lane & 3;
    float m_[2] = {-1e30f, -1e30f};
    float l_[2] = {0.f, 0.f};
    float o[8][4] = {};

    for (int it = 0; it < 4; it++) {
        asm volatile("cp.async.wait_group 0;" ::: "memory");
        __syncthreads();
        if (it + 1 < 4) issue(it + 1);
        uint32_t stb = sb + FS_ST + (uint32_t)(it & 1) * FS_STAGE;

        // ---- S = Q @ K^T (3-product split) ----
        float c[16][4] = {};
        #pragma unroll
        for (int s = 0; s < 4; s++) {
            uint32_t qoff = (uint32_t)((wm + (lane & 15)) * 144
                           + (s * 16 + ((lane >> 4) << 3)) * 2);
            uint32_t aqh[4], aql[4];
            ldmx4(aqh, sb + FS_QH + qoff);
            ldmx4(aql, sb + FS_QL + qoff);
            #pragma unroll
            for (int n2 = 0; n2 < 8; n2++) {
                uint32_t koff = (uint32_t)(
                    (n2 * 16 + (lane & 7) + ((lane >> 4) << 3)) * 144
                    + (s * 16 + (((lane >> 3) & 1) << 3)) * 2);
                uint32_t kb[4], klb[4];
                ldmx4(kb, stb + FS_K + koff);
                ldmx4(klb, stb + FS_KLO + koff);
                uint32_t bh0[2] = {kb[0], kb[1]},  bh1[2] = {kb[2], kb[3]};
                uint32_t bl0[2] = {klb[0], klb[1]}, bl1[2] = {klb[2], klb[3]};
                mma16816(c[2*n2],   aqh, bh0);
                mma16816(c[2*n2],   aqh, bl0);
                mma16816(c[2*n2],   aql, bh0);
                mma16816(c[2*n2+1], aqh, bh1);
                mma16816(c[2*n2+1], aqh, bl1);
                mma16816(c[2*n2+1], aql, bh1);
            }
        }
        // ---- bias + scale + mask ----
        #pragma unroll
        for (int nt = 0; nt < 16; nt++) {
            int kc = it * 128 + nt * 8 + tg * 2;
            float2 ks = *(float2*)(smem + FS_KS + kc * 4);
            #pragma unroll
            for (int hf = 0; hf < 2; hf++) {
                int row = q0 + wm + g + hf * 8;
                size_t off = (bT + row) * Tc + kc;
                float2 dv = *(const float2*)(g_dense + off);
                float2 mk = *(const float2*)(masks + off);
                float v0 = (c[nt][hf*2+0] + dv.x * ks.x) * 0.125f;
                float v1 = (c[nt][hf*2+1] + dv.y * ks.y) * 0.125f;
                c[nt][hf*2+0] = v0 * mk.x + (1.f - ceilf(mk.x)) * (-3.402823466e38f);
                c[nt][hf*2+1] = v1 * mk.y + (1.f - ceilf(mk.y)) * (-3.402823466e38f);
            }
        }
        // ---- online softmax ----
        float scale[2];
        #pragma unroll
        for (int hf = 0; hf < 2; hf++) {
            float mx = -3.402823466e38f;
            #pragma unroll
            for (int nt = 0; nt < 16; nt++)
                mx = fmaxf(mx, fmaxf(c[nt][hf*2], c[nt][hf*2+1]));
            mx = fmaxf(mx, __shfl_xor_sync(0xffffffffu, mx, 1));
            mx = fmaxf(mx, __shfl_xor_sync(0xffffffffu, mx, 2));
            float mn = fmaxf(m_[hf], mx);
            scale[hf] = __expf(m_[hf] - mn);
            m_[hf] = mn;
            float sum = 0.f;
            #pragma unroll
            for (int nt = 0; nt < 16; nt++) {
                float p0 = __expf(c[nt][hf*2]   - mn);
                float p1 = __expf(c[nt][hf*2+1] - mn);
                c[nt][hf*2] = p0; c[nt][hf*2+1] = p1;
                sum += p0 + p1;
            }
            sum += __shfl_xor_sync(0xffffffffu, sum, 1);
            sum += __shfl_xor_sync(0xffffffffu, sum, 2);
            l_[hf] = l_[hf] * scale[hf] + sum;
        }
        #pragma unroll
        for (int ant = 0; ant < 8; ant++) {
            o[ant][0] *= scale[0]; o[ant][1] *= scale[0];
            o[ant][2] *= scale[1]; o[ant][3] *= scale[1];
        }
        // ---- O += P @ V (3-product split) ----
        #pragma unroll
        for (int j = 0; j < 8; j++) {
            uint32_t ah[4], al[4];
            float r0, r1;
            ah[0] = pack_hi(c[2*j][0],   c[2*j][1],   r0, r1); al[0] = pack_bf(r0, r1);
            ah[1] = pack_hi(c[2*j][2],   c[2*j][3],   r0, r1); al[1] = pack_bf(r0, r1);
            ah[2] = pack_hi(c[2*j+1][0], c[2*j+1][1], r0, r1); al[2] = pack_bf(r0, r1);
            ah[3] = pack_hi(c[2*j+1][2], c[2*j+1][3], r0, r1); al[3] = pack_bf(r0, r1);
            #pragma unroll
            for (int ap = 0; ap < 4; ap++) {
                uint32_t voff = (uint32_t)(
                    (j * 16 + (lane & 7) + (((lane >> 3) & 1) << 3)) * 144
                    + (ap * 16 + ((lane >> 4) << 3)) * 2);
                uint32_t vb[4], vlb[4];
                ldmx4t(vb, stb + FS_V + voff);
                ldmx4t(vlb, stb + FS_VLO + voff);
                uint32_t vh0[2] = {vb[0], vb[1]},  vh1[2] = {vb[2], vb[3]};
                uint32_t vl0[2] = {vlb[0], vlb[1]}, vl1[2] = {vlb[2], vlb[3]};
                mma16816(o[2*ap],   ah, vh0);
                mma16816(o[2*ap],   ah, vl0);
                mma16816(o[2*ap],   al, vh0);
                mma16816(o[2*ap+1], ah, vh1);
                mma16816(o[2*ap+1], ah, vl1);
                mma16816(o[2*ap+1], al, vh1);
            }
        }
    }
    // ---- epilogue: normalize and store bf16 hi/lo ----
    #pragma unroll
    for (int hf = 0; hf < 2; hf++) {
        float inv = (l_[hf] > 0.f) ? 1.f / l_[hf] : 0.f;
        int row = q0 + wm + g + hf * 8;
        size_t base = (bT + row) * Dc + h * Ac + tg * 2;
        #pragma unroll
        for (int ant = 0; ant < 8; ant++) {
            float o0 = o[ant][hf*2+0] * inv, o1 = o[ant][hf*2+1] * inv;
            float r0, r1;
            uint32_t hp = pack_hi(o0, o1, r0, r1);
            *(uint32_t*)(ch + base + ant * 8) = hp;
            *(uint32_t*)(cl + base + ant * 8) = pack_bf(r0, r1);
        }
    }
}

// ---------------- embedding + positional encoding ---------------------------
__global__ __launch_bounds__(512) void embed_pe_kernel(
    const int* __restrict__ tokens, const float* __restrict__ embed)
{
    int bt = blockIdx.x;
    int d  = threadIdx.x;
    int t  = bt % Tc;
    int tok = tokens[bt];
    float val = embed[(size_t)tok * Dc + d] * 22.62741699796952f;
    float expo  = (2.0f * (float)(d >> 1)) / (float)Dc;
    float denom = powf(10000.0f, expo);
    float angle = (float)t / denom;
    val += ((d & 1) == 0) ? sinf(angle) : cosf(angle);
    g_x[(size_t)bt * Dc + d] = val;
}

// ---------------- layernorm --------------------------------------------------
__global__ __launch_bounds__(256) void layernorm_kernel(
    const float* __restrict__ in, const float* __restrict__ gamma,
    const float* __restrict__ beta, float* __restrict__ outf,
    bf16* __restrict__ oh, bf16* __restrict__ ol)
{
    __shared__ float red[256];
    size_t base = (size_t)blockIdx.x * Dc;
    int tid = threadIdx.x;
    float v0 = in[base + tid];
    float v1 = in[base + tid + 256];
    red[tid] = v0 + v1;
    __syncthreads();
    #pragma unroll
    for (int s = 128; s > 0; s >>= 1) {
        if (tid < s) red[tid] += red[tid + s];
        __syncthreads();
    }
    float mu = red[0] * (1.0f / Dc);
    __syncthreads();
    float d0 = v0 - mu, d1 = v1 - mu;
    red[tid] = d0 * d0 + d1 * d1;
    __syncthreads();
    #pragma unroll
    for (int s = 128; s > 0; s >>= 1) {
        if (tid < s) red[tid] += red[tid + s];
        __syncthreads();
    }
    float rstd = rsqrtf(red[0] * (1.0f / Dc) + 1e-3f);
    float o0 = d0 * rstd * gamma[tid]       + beta[tid];
    float o1 = d1 * rstd * gamma[tid + 256] + beta[tid + 256];
    if (outf) {
        outf[base + tid]       = o0;
        outf[base + tid + 256] = o1;
    }
    if (oh) {
        bf16 h0 = __float2bfloat16_rn(o0);
        bf16 h1 = __float2bfloat16_rn(o1);
        oh[base + tid]       = h0;
        oh[base + tid + 256] = h1;
        ol[base + tid]       = __float2bfloat16_rn(o0 - __bfloat162float(h0));
        ol[base + tid + 256] = __float2bfloat16_rn(o1 - __bfloat162float(h1));
    }
}

// ---------------- ksum[b,h,t] from bf16 hi/lo k ------------------------------
__global__ __launch_bounds__(256) void ksum_kernel(void)
{
    int i = blockIdx.x * blockDim.x + threadIdx.x;
    if (i >= Bc * Tc * Hc) return;
    int bt = i >> 3, h = i & 7;
    int b = bt / Tc, tt = bt % Tc;
    const bf16* ph = g_kh + (size_t)bt * Dc + h * Ac;
    const bf16* pl = g_kl + (size_t)bt * Dc + h * Ac;
    float s = 0.0f;
    #pragma unroll
    for (int a = 0; a < Ac; a++)
        s += __bfloat162float(ph[a]) + __bfloat162float(pl[a]);
    g_ksum[((size_t)b * Hc + h) * Tc + tt] = s;
}

// ---------------- zero -------------------------------------------------------
__global__ __launch_bounds__(256) void zero_kernel(float* __restrict__ p, int n4)
{
    int i = blockIdx.x * blockDim.x + threadIdx.x;
    if (i < n4) ((float4*)p)[i] = make_float4(0.f, 0.f, 0.f, 0.f);
}

// ---------------- sparse edge bias scatter ----------------------------------
__global__ __launch_bounds__(256) void bias_scatter_kernel(
    const int* __restrict__ ab, const float* __restrict__ be_l,
    const float* __restrict__ bs_l)
{
    __shared__ float evtab[BIASDIM];
    if (threadIdx.x < BIASDIM) {
        float s = 0.0f;
        #pragma unroll
        for (int a = 0; a < Ac; a++)
            s += be_l[threadIdx.x * Ac + a] * bs_l[a];
        evtab[threadIdx.x] = s;
    }
    __syncthreads();
    int e = blockIdx.x * blockDim.x + threadIdx.x;
    if (e >= Ec) return;
    int ty = ab[e * 4 + 0];
    int b  = ab[e * 4 + 1];
    int q  = ab[e * 4 + 2];
    int k  = ab[e * 4 + 3];
    atomicAdd(&g_dense[((size_t)b * Tc + q) * Tc + k], evtab[ty]);
}

// ---------------- host driver -----------------------------------------------
extern "C" void kernel_launch(void* const* d_in, const int* in_sizes, int n_in,
                              void* d_out, int out_size)
{
    const int*   tokens = (const int*)  d_in[0];
    const float* masks  = (const float*)d_in[1];
    const int*   ab     = (const int*)  d_in[2];
    const float* embed  = (const float*)d_in[3];
    const float* Wq     = (const float*)d_in[4];
    const float* Wk     = (const float*)d_in[5];
    const float* Wv     = (const float*)d_in[6];
    const float* Wo     = (const float*)d_in[7];
    const float* be     = (const float*)d_in[8];
    const float* bs     = (const float*)d_in[9];
    const float* ln_g   = (const float*)d_in[10];
    const float* ln_b   = (const float*)d_in[11];
    const float* ff1w   = (const float*)d_in[12];
    const float* ff1b   = (const float*)d_in[13];
    const float* ff2w   = (const float*)d_in[14];
    const float* ff2b   = (const float*)d_in[15];
    const float* lng    = (const float*)d_in[16];
    const float* lnb    = (const float*)d_in[17];
    float* out = (float*)d_out;

    float *x, *dense;
    bf16 *hh, *hl, *qh, *ql, *kh, *kl, *vh, *vl, *ch, *cl, *fh, *fl;
    bf16 *wqTh,*wqTl,*wkTh,*wkTl,*wvTh,*wvTl,*woTh,*woTl,*f1Th,*f1Tl,*f2Th,*f2Tl;
    cudaGetSymbolAddress((void**)&x,     g_x);
    cudaGetSymbolAddress((void**)&dense, g_dense);
    cudaGetSymbolAddress((void**)&hh,    g_hh);
    cudaGetSymbolAddress((void**)&hl,    g_hl);
    cudaGetSymbolAddress((void**)&qh,    g_qh);
    cudaGetSymbolAddress((void**)&ql,    g_ql);
    cudaGetSymbolAddress((void**)&kh,    g_kh);
    cudaGetSymbolAddress((void**)&kl,    g_kl);
    cudaGetSymbolAddress((void**)&vh,    g_vh);
    cudaGetSymbolAddress((void**)&vl,    g_vl);
    cudaGetSymbolAddress((void**)&ch,    g_ch);
    cudaGetSymbolAddress((void**)&cl,    g_cl);
    cudaGetSymbolAddress((void**)&fh,    g_fh);
    cudaGetSymbolAddress((void**)&fl,    g_fl);
    cudaGetSymbolAddress((void**)&wqTh,  g_wqTh);
    cudaGetSymbolAddress((void**)&wqTl,  g_wqTl);
    cudaGetSymbolAddress((void**)&wkTh,  g_wkTh);
    cudaGetSymbolAddress((void**)&wkTl,  g_wkTl);
    cudaGetSymbolAddress((void**)&wvTh,  g_wvTh);
    cudaGetSymbolAddress((void**)&wvTl,  g_wvTl);
    cudaGetSymbolAddress((void**)&woTh,  g_woTh);
    cudaGetSymbolAddress((void**)&woTl,  g_woTl);
    cudaGetSymbolAddress((void**)&f1Th,  g_f1Th);
    cudaGetSymbolAddress((void**)&f1Tl,  g_f1Tl);
    cudaGetSymbolAddress((void**)&f2Th,  g_f2Th);
    cudaGetSymbolAddress((void**)&f2Tl,  g_f2Tl);

    cudaFuncSetAttribute(gemm_mma, cudaFuncAttributeMaxDynamicSharedMemorySize,
                         2 * STG);
    cudaFuncSetAttribute(flash_kernel, cudaFuncAttributeMaxDynamicSharedMemorySize,
                         FS_TOTAL);

    const int MT = Bc * Tc;                 // 8192 tokens
    dim3 wb(32, 8);

    wconv_kernel<<<dim3(16, 16, Lc), wb>>>(Wq,   wqTh, wqTl, Dc, Dc);
    wconv_kernel<<<dim3(16, 16, Lc), wb>>>(Wk,   wkTh, wkTl, Dc, Dc);
    wconv_kernel<<<dim3(16, 16, Lc), wb>>>(Wv,   wvTh, wvTl, Dc, Dc);
    wconv_kernel<<<dim3(16, 16, Lc), wb>>>(Wo,   woTh, woTl, Dc, Dc);
    wconv_kernel<<<dim3(64, 16, Lc), wb>>>(ff1w, f1Th, f1Tl, Dc, Fc);
    wconv_kernel<<<dim3(16, 64, Lc), wb>>>(ff2w, f2Th, f2Tl, Fc, Dc);

    embed_pe_kernel<<<MT, 512>>>(tokens, embed);

    for (int l = 0; l < Lc; l++) {
        size_t wo1 = (size_t)l * Dc * Dc;
        size_t wf1 = (size_t)l * Dc * Fc;
        size_t wf2 = (size_t)l * Fc * Dc;
        const float* be_l  = be + (size_t)l * BIASDIM * Ac;
        const float* bs_l  = bs + (size_t)l * Ac;
        const float* ln1g  = ln_g + (size_t)l * 2 * Dc;
        const float* ln1b  = ln_b + (size_t)l * 2 * Dc;
        const float* ln2g  = ln1g + Dc;
        const float* ln2b  = ln1b + Dc;
        const float* f1b   = ff1b + (size_t)l * Fc;
        const float* f2b   = ff2b + (size_t)l * Dc;

        layernorm_kernel<<<MT, 256>>>(x, ln1g, ln1b, nullptr, hh, hl);

        // QKV -> bf16 hi/lo directly
        gemm_mma<<<dim3(Dc/128, MT/128), 256, 2*STG>>>(hh, hl, wqTh+wo1, wqTl+wo1,
            nullptr, nullptr, nullptr, qh, ql, MT, Dc, Dc, 0);
        gemm_mma<<<dim3(Dc/128, MT/128), 256, 2*STG>>>(hh, hl, wkTh+wo1, wkTl+wo1,
            nullptr, nullptr, nullptr, kh, kl, MT, Dc, Dc, 0);
        gemm_mma<<<dim3(Dc/128, MT/128), 256, 2*STG>>>(hh, hl, wvTh+wo1, wvTl+wo1,
            nullptr, nullptr, nullptr, vh, vl, MT, Dc, Dc, 0);

        ksum_kernel<<<(Bc*Tc*Hc + 255)/256, 256>>>();

        zero_kernel<<<(Bc*Tc*Tc/4 + 255)/256, 256>>>(dense, Bc*Tc*Tc/4);
        bias_scatter_kernel<<<(Ec + 255)/256, 256>>>(ab, be_l, bs_l);

        // fused attention (score + bias + mask + softmax + ctx)
        flash_kernel<<<dim3(Tc/128, Bc*Hc), 256, FS_TOTAL>>>(masks, ch, cl);

        gemm_mma<<<dim3(Dc/128, MT/128), 256, 2*STG>>>(ch, cl, woTh+wo1, woTl+wo1,
            nullptr, x, x, nullptr, nullptr, MT, Dc, Dc, 0);

        layernorm_kernel<<<MT, 256>>>(x, ln2g, ln2b, nullptr, hh, hl);
        gemm_mma<<<dim3(Fc/128, MT/128), 256, 2*STG>>>(hh, hl, f1Th+wf1, f1Tl+wf1,
            f1b, nullptr, nullptr, fh, fl, MT, Fc, Dc, 1);
        gemm_mma<<<dim3(Dc/128, MT/128), 256, 2*STG>>>(fh, fl, f2Th+wf2, f2Tl+wf2,
            f2b, x, x, nullptr, nullptr, MT, Dc, Fc, 0);
    }

    layernorm_kernel<<<MT, 256>>>(x, lng, lnb, out, nullptr, nullptr);
}

// round 7
// speedup vs baseline: 1.8479x; 1.0457x over previous
#include <cuda_runtime.h>
#include <cuda_bf16.h>
#include <math.h>
#include <stdint.h>

#define Lc 6
#define Bc 16
#define Tc 512
#define Dc 512
#define Hc 8
#define Ac 64
#define Fc 2048
#define Ec 200000
#define BIASDIM 4

typedef __nv_bfloat16 bf16;

// ======================= helpers =============================================
__device__ __forceinline__ uint32_t smem_u32(const void* p) {
    uint32_t a;
    asm("{ .reg .u64 t; cvta.to.shared.u64 t, %1; cvt.u32.u64 %0, t; }"
        : "=r"(a) : "l"(p));
    return a;
}
__device__ __forceinline__ void cp16(uint32_t s, const void* g) {
    asm volatile("cp.async.cg.shared.global [%0], [%1], 16;" :: "r"(s), "l"(g));
}
__device__ __forceinline__ void mma16816(float* c, const uint32_t* a,
                                         const uint32_t* b) {
    asm volatile("mma.sync.aligned.m16n8k16.row.col.f32.bf16.bf16.f32 "
        "{%0,%1,%2,%3}, {%4,%5,%6,%7}, {%8,%9}, {%0,%1,%2,%3};"
        : "+f"(c[0]), "+f"(c[1]), "+f"(c[2]), "+f"(c[3])
        : "r"(a[0]), "r"(a[1]), "r"(a[2]), "r"(a[3]), "r"(b[0]), "r"(b[1]));
}
__device__ __forceinline__ void ldmx4(uint32_t* r, uint32_t a) {
    asm volatile("ldmatrix.sync.aligned.m8n8.x4.shared.b16 {%0,%1,%2,%3}, [%4];"
        : "=r"(r[0]), "=r"(r[1]), "=r"(r[2]), "=r"(r[3]) : "r"(a));
}
__device__ __forceinline__ void ldmx4t(uint32_t* r, uint32_t a) {
    asm volatile("ldmatrix.sync.aligned.m8n8.x4.trans.shared.b16 {%0,%1,%2,%3}, [%4];"
        : "=r"(r[0]), "=r"(r[1]), "=r"(r[2]), "=r"(r[3]) : "r"(a));
}
__device__ __forceinline__ uint32_t pack_hi(float v0, float v1, float& r0, float& r1) {
    bf16 h0 = __float2bfloat16_rn(v0), h1 = __float2bfloat16_rn(v1);
    r0 = v0 - __bfloat162float(h0);
    r1 = v1 - __bfloat162float(h1);
    unsigned short u0 = *reinterpret_cast<unsigned short*>(&h0);
    unsigned short u1 = *reinterpret_cast<unsigned short*>(&h1);
    return (uint32_t)u0 | ((uint32_t)u1 << 16);
}
__device__ __forceinline__ uint32_t pack_bf(float v0, float v1) {
    bf16 h0 = __float2bfloat16_rn(v0), h1 = __float2bfloat16_rn(v1);
    unsigned short u0 = *reinterpret_cast<unsigned short*>(&h0);
    unsigned short u1 = *reinterpret_cast<unsigned short*>(&h1);
    return (uint32_t)u0 | ((uint32_t)u1 << 16);
}

// ---------------- scratch (device globals; no allocations) ------------------
#define QKVW (3*Dc)      // 1536
__device__ float g_x[Bc*Tc*Dc];
__device__ float g_ksum[Bc*Hc*Tc];
__device__ float g_dense[Bc*Tc*Tc];
// bf16 hi/lo activations
__device__ bf16 g_hh[Bc*Tc*Dc],   g_hl[Bc*Tc*Dc];
__device__ bf16 g_qkvh[Bc*Tc*QKVW], g_qkvl[Bc*Tc*QKVW];
__device__ bf16 g_ch[Bc*Tc*Dc],   g_cl[Bc*Tc*Dc];
__device__ bf16 g_fh[Bc*Tc*Fc],   g_fl[Bc*Tc*Fc];
// transposed bf16 hi/lo weights [N][K] per layer
__device__ bf16 g_wqkvTh[Lc*QKVW*Dc], g_wqkvTl[Lc*QKVW*Dc];
__device__ bf16 g_woTh[Lc*Dc*Dc],  g_woTl[Lc*Dc*Dc];
__device__ bf16 g_f1Th[Lc*Dc*Fc],  g_f1Tl[Lc*Dc*Fc];
__device__ bf16 g_f2Th[Lc*Fc*Dc],  g_f2Tl[Lc*Fc*Dc];

// ======================= weight transpose+convert ============================
// W [z][K][N] f32 -> out hi/lo [N][K] bf16 at Th + z*ozstride.
__global__ void wconv_kernel(const float* __restrict__ W,
                             bf16* __restrict__ Th, bf16* __restrict__ Tl,
                             int K, int N, size_t ozstride)
{
    __shared__ float tile[32][33];
    const float* Wz = W + (size_t)blockIdx.z * K * N;
    bf16* Thz = Th + (size_t)blockIdx.z * ozstride;
    bf16* Tlz = Tl + (size_t)blockIdx.z * ozstride;
    int n0 = blockIdx.x * 32, k0 = blockIdx.y * 32;
    int tx = threadIdx.x, ty = threadIdx.y;
    #pragma unroll
    for (int i = 0; i < 4; i++)
        tile[ty + 8*i][tx] = Wz[(size_t)(k0 + ty + 8*i) * N + n0 + tx];
    __syncthreads();
    #pragma unroll
    for (int i = 0; i < 4; i++) {
        int n = n0 + ty + 8*i, k = k0 + tx;
        float v = tile[tx][ty + 8*i];
        bf16 h = __float2bfloat16_rn(v);
        Thz[(size_t)n * K + k] = h;
        Tlz[(size_t)n * K + k] = __float2bfloat16_rn(v - __bfloat162float(h));
    }
}

// ======================= bf16-split MMA GEMM (dense projections) =============
// C[M,N] = A[M,K] @ B^T[N,K], ldmatrix fragments, 128x128 tile, 8 warps.
#define STG 40960u
__global__ __launch_bounds__(256) void gemm_mma(
    const bf16* __restrict__ Ahi, const bf16* __restrict__ Alo,
    const bf16* __restrict__ Bhi, const bf16* __restrict__ Blo,
    const float* __restrict__ bias, const float* __restrict__ resid,
    float* __restrict__ Cf, bf16* __restrict__ Ch, bf16* __restrict__ Cl,
    int M, int N, int K, int do_relu)
{
    extern __shared__ char smem[];
    uint32_t sb = smem_u32(smem);
    int t = threadIdx.x;
    int lane = t & 31, w = t >> 5;
    int row0 = blockIdx.y * 128, col0 = blockIdx.x * 128;
    int warpM = (w & 3) * 32, warpN = (w >> 2) * 64;
    int g = lane >> 2, tg = lane & 3;

    int arow = t >> 1, koff = (t & 1) * 16;
    const bf16* pAh = Ahi + (size_t)(row0 + arow) * K + koff;
    const bf16* pAl = Alo + (size_t)(row0 + arow) * K + koff;
    const bf16* pBh = Bhi + (size_t)(col0 + arow) * K + koff;
    const bf16* pBl = Blo + (size_t)(col0 + arow) * K + koff;
    uint32_t soff = (uint32_t)(arow * 80 + koff * 2);

    float c[2][8][4];
    #pragma unroll
    for (int i = 0; i < 2; i++)
        #pragma unroll
        for (int j = 0; j < 8; j++)
            #pragma unroll
            for (int r = 0; r < 4; r++) c[i][j][r] = 0.0f;

    int ns = K / 32;

    auto issue = [&](int kt) {
        uint32_t base = sb + (uint32_t)(kt & 1) * STG;
        const bf16* a;
        a = pAh + kt * 32;
        cp16(base + soff, a);                 cp16(base + soff + 16, a + 8);
        a = pAl + kt * 32;
        cp16(base + 10240 + soff, a);         cp16(base + 10240 + soff + 16, a + 8);
        a = pBh + kt * 32;
        cp16(base + 20480 + soff, a);         cp16(base + 20480 + soff + 16, a + 8);
        a = pBl + kt * 32;
        cp16(base + 30720 + soff, a);         cp16(base + 30720 + soff + 16, a + 8);
        asm volatile("cp.async.commit_group;" ::: "memory");
    };

    issue(0);
    for (int kt = 0; kt < ns; kt++) {
        if (kt + 1 < ns) {
            issue(kt + 1);
            asm volatile("cp.async.wait_group 1;" ::: "memory");
        } else {
            asm volatile("cp.async.wait_group 0;" ::: "memory");
        }
        __syncthreads();
        uint32_t base = sb + (uint32_t)(kt & 1) * STG;
        #pragma unroll
        for (int ks = 0; ks < 2; ks++) {
            int k0 = ks * 16;
            // B fragments: n64 as 4 tiles of n16 x k16 via ldmatrix.x4
            uint32_t kb[4][4], klb[4][4];
            #pragma unroll
            for (int n2 = 0; n2 < 4; n2++) {
                uint32_t roff = (uint32_t)(
                    (warpN + n2*16 + (lane & 7) + (((lane >> 4) & 1) << 3)) * 80
                    + (k0 + (((lane >> 3) & 1) << 3)) * 2);
                ldmx4(kb[n2],  base + 20480 + roff);
                ldmx4(klb[n2], base + 30720 + roff);
            }
            #pragma unroll
            for (int am = 0; am < 2; am++) {
                uint32_t aoff = (uint32_t)(
                    (warpM + am*16 + (lane & 15)) * 80
                    + (k0 + ((lane >> 4) << 3)) * 2);
                uint32_t ah[4], al[4];
                ldmx4(ah, base + aoff);
                ldmx4(al, base + 10240 + aoff);
                #pragma unroll
                for (int n2 = 0; n2 < 4; n2++) {
                    uint32_t bh0[2] = {kb[n2][0],  kb[n2][1]};
                    uint32_t bh1[2] = {kb[n2][2],  kb[n2][3]};
                    uint32_t bl0[2] = {klb[n2][0], klb[n2][1]};
                    uint32_t bl1[2] = {klb[n2][2], klb[n2][3]};
                    mma16816(c[am][2*n2],   ah, bh0);
                    mma16816(c[am][2*n2],   ah, bl0);
                    mma16816(c[am][2*n2],   al, bh0);
                    mma16816(c[am][2*n2+1], ah, bh1);
                    mma16816(c[am][2*n2+1], ah, bl1);
                    mma16816(c[am][2*n2+1], al, bh1);
                }
            }
        }
        __syncthreads();
    }

    #pragma unroll
    for (int am = 0; am < 2; am++) {
        #pragma unroll
        for (int bn = 0; bn < 8; bn++) {
            int n = col0 + warpN + (bn >> 1) * 16 + (bn & 1) * 8 + tg * 2;
            #pragma unroll
            for (int hf = 0; hf < 2; hf++) {
                int m = row0 + warpM + am*16 + g + hf*8;
                float v0 = c[am][bn][hf*2+0], v1 = c[am][bn][hf*2+1];
                if (bias) { v0 += bias[n]; v1 += bias[n+1]; }
                if (do_relu) { v0 = fmaxf(v0, 0.f); v1 = fmaxf(v1, 0.f); }
                if (resid) {
                    float2 r = *(const float2*)(resid + (size_t)m * N + n);
                    v0 += r.x; v1 += r.y;
                }
                if (Cf) *(float2*)(Cf + (size_t)m * N + n) = make_float2(v0, v1);
                if (Ch) {
                    float l0, l1;
                    uint32_t hp = pack_hi(v0, v1, l0, l1);
                    *(uint32_t*)(Ch + (size_t)m * N + n) = hp;
                    *(uint32_t*)(Cl + (size_t)m * N + n) = pack_bf(l0, l1);
                }
            }
        }
    }
}

// ======================= fused flash attention ===============================
// grid (T/128, B*H), 256 threads. q/k/v read from combined qkv buffer (stride 1536).
#define FS_QH    0u
#define FS_QL    18432u
#define FS_KS    36864u
#define FS_ST    38912u
#define FS_STAGE 73728u
#define FS_K     0u
#define FS_KLO   18432u
#define FS_V     36864u
#define FS_VLO   55296u
#define FS_TOTAL (38912u + 2u * 73728u)

__global__ __launch_bounds__(256) void flash_kernel(
    const float* __restrict__ masks,
    bf16* __restrict__ ch, bf16* __restrict__ cl)
{
    extern __shared__ char smem[];
    uint32_t sb = smem_u32(smem);
    int t = threadIdx.x, lane = t & 31, w = t >> 5;
    int z = blockIdx.y, b = z >> 3, h = z & 7;
    int q0 = blockIdx.x * 128;
    size_t bT = (size_t)b * Tc;

    {
        int row = t >> 1, half = t & 1;
        size_t gq = (bT + q0 + row) * QKVW + h * Ac + half * 32;
        uint32_t so = (uint32_t)(row * 144 + half * 64);
        #pragma unroll
        for (int c4 = 0; c4 < 4; c4++) {
            cp16(sb + FS_QH + so + c4 * 16, g_qkvh + gq + c4 * 8);
            cp16(sb + FS_QL + so + c4 * 16, g_qkvl + gq + c4 * 8);
        }
        if (t < 128)
            cp16(sb + FS_KS + t * 16, g_ksum + ((size_t)b * Hc + h) * Tc + t * 4);
    }
    auto issue = [&](int it) {
        uint32_t base = sb + FS_ST + (uint32_t)(it & 1) * FS_STAGE;
        int row = t >> 1, half = t & 1;
        size_t gk = (bT + it * 128 + row) * QKVW + Dc + h * Ac + half * 32;
        size_t gv = gk + Dc;
        uint32_t so = (uint32_t)(row * 144 + half * 64);
        #pragma unroll
        for (int c4 = 0; c4 < 4; c4++) {
            cp16(base + FS_K   + so + c4 * 16, g_qkvh + gk + c4 * 8);
            cp16(base + FS_KLO + so + c4 * 16, g_qkvl + gk + c4 * 8);
            cp16(base + FS_V   + so + c4 * 16, g_qkvh + gv + c4 * 8);
            cp16(base + FS_VLO + so + c4 * 16, g_qkvl + gv + c4 * 8);
        }
        asm volatile("cp.async.commit_group;" ::: "memory");
    };
    issue(0);

    int wm = w * 16;
    int g = lane >> 2, tg = lane & 3;
    float m_[2] = {-1e30f, -1e30f};
    float l_[2] = {0.f, 0.f};
    float o[8][4] = {};

    for (int it = 0; it < 4; it++) {
        asm volatile("cp.async.wait_group 0;" ::: "memory");
        __syncthreads();
        if (it + 1 < 4) issue(it + 1);
        uint32_t stb = sb + FS_ST + (uint32_t)(it & 1) * FS_STAGE;

        float c[16][4] = {};
        #pragma unroll
        for (int s = 0; s < 4; s++) {
            uint32_t qoff = (uint32_t)((wm + (lane & 15)) * 144
                           + (s * 16 + ((lane >> 4) << 3)) * 2);
            uint32_t aqh[4], aql[4];
            ldmx4(aqh, sb + FS_QH + qoff);
            ldmx4(aql, sb + FS_QL + qoff);
            #pragma unroll
            for (int n2 = 0; n2 < 8; n2++) {
                uint32_t koff = (uint32_t)(
                    (n2 * 16 + (lane & 7) + ((lane >> 4) << 3)) * 144
                    + (s * 16 + (((lane >> 3) & 1) << 3)) * 2);
                uint32_t kb[4], klb[4];
                ldmx4(kb, stb + FS_K + koff);
                ldmx4(klb, stb + FS_KLO + koff);
                uint32_t bh0[2] = {kb[0], kb[1]},  bh1[2] = {kb[2], kb[3]};
                uint32_t bl0[2] = {klb[0], klb[1]}, bl1[2] = {klb[2], klb[3]};
                mma16816(c[2*n2],   aqh, bh0);
                mma16816(c[2*n2],   aqh, bl0);
                mma16816(c[2*n2],   aql, bh0);
                mma16816(c[2*n2+1], aqh, bh1);
                mma16816(c[2*n2+1], aqh, bl1);
                mma16816(c[2*n2+1], aql, bh1);
            }
        }
        #pragma unroll
        for (int nt = 0; nt < 16; nt++) {
            int kc = it * 128 + nt * 8 + tg * 2;
            float2 ks = *(float2*)(smem + FS_KS + kc * 4);
            #pragma unroll
            for (int hf = 0; hf < 2; hf++) {
                int row = q0 + wm + g + hf * 8;
                size_t off = (bT + row) * Tc + kc;
                float2 dv = *(const float2*)(g_dense + off);
                float2 mk = *(const float2*)(masks + off);
                float v0 = (c[nt][hf*2+0] + dv.x * ks.x) * 0.125f;
                float v1 = (c[nt][hf*2+1] + dv.y * ks.y) * 0.125f;
                c[nt][hf*2+0] = v0 * mk.x + (1.f - ceilf(mk.x)) * (-3.402823466e38f);
                c[nt][hf*2+1] = v1 * mk.y + (1.f - ceilf(mk.y)) * (-3.402823466e38f);
            }
        }
        float scale[2];
        #pragma unroll
        for (int hf = 0; hf < 2; hf++) {
            float mx = -3.402823466e38f;
            #pragma unroll
            for (int nt = 0; nt < 16; nt++)
                mx = fmaxf(mx, fmaxf(c[nt][hf*2], c[nt][hf*2+1]));
            mx = fmaxf(mx, __shfl_xor_sync(0xffffffffu, mx, 1));
            mx = fmaxf(mx, __shfl_xor_sync(0xffffffffu, mx, 2));
            float mn = fmaxf(m_[hf], mx);
            scale[hf] = __expf(m_[hf] - mn);
            m_[hf] = mn;
            float sum = 0.f;
            #pragma unroll
            for (int nt = 0; nt < 16; nt++) {
                float p0 = __expf(c[nt][hf*2]   - mn);
                float p1 = __expf(c[nt][hf*2+1] - mn);
                c[nt][hf*2] = p0; c[nt][hf*2+1] = p1;
                sum += p0 + p1;
            }
            sum += __shfl_xor_sync(0xffffffffu, sum, 1);
            sum += __shfl_xor_sync(0xffffffffu, sum, 2);
            l_[hf] = l_[hf] * scale[hf] + sum;
        }
        #pragma unroll
        for (int ant = 0; ant < 8; ant++) {
            o[ant][0] *= scale[0]; o[ant][1] *= scale[0];
            o[ant][2] *= scale[1]; o[ant][3] *= scale[1];
        }
        #pragma unroll
        for (int j = 0; j < 8; j++) {
            uint32_t ah[4], al[4];
            float r0, r1;
            ah[0] = pack_hi(c[2*j][0],   c[2*j][1],   r0, r1); al[0] = pack_bf(r0, r1);
            ah[1] = pack_hi(c[2*j][2],   c[2*j][3],   r0, r1); al[1] = pack_bf(r0, r1);
            ah[2] = pack_hi(c[2*j+1][0], c[2*j+1][1], r0, r1); al[2] = pack_bf(r0, r1);
            ah[3] = pack_hi(c[2*j+1][2], c[2*j+1][3], r0, r1); al[3] = pack_bf(r0, r1);
            #pragma unroll
            for (int ap = 0; ap < 4; ap++) {
                uint32_t voff = (uint32_t)(
                    (j * 16 + (lane & 7) + (((lane >> 3) & 1) << 3)) * 144
                    + (ap * 16 + ((lane >> 4) << 3)) * 2);
                uint32_t vb[4], vlb[4];
                ldmx4t(vb, stb + FS_V + voff);
                ldmx4t(vlb, stb + FS_VLO + voff);
                uint32_t vh0[2] = {vb[0], vb[1]},  vh1[2] = {vb[2], vb[3]};
                uint32_t vl0[2] = {vlb[0], vlb[1]}, vl1[2] = {vlb[2], vlb[3]};
                mma16816(o[2*ap],   ah, vh0);
                mma16816(o[2*ap],   ah, vl0);
                mma16816(o[2*ap],   al, vh0);
                mma16816(o[2*ap+1], ah, vh1);
                mma16816(o[2*ap+1], ah, vl1);
                mma16816(o[2*ap+1], al, vh1);
            }
        }
    }
    #pragma unroll
    for (int hf = 0; hf < 2; hf++) {
        float inv = (l_[hf] > 0.f) ? 1.f / l_[hf] : 0.f;
        int row = q0 + wm + g + hf * 8;
        size_t base = (bT + row) * Dc + h * Ac + tg * 2;
        #pragma unroll
        for (int ant = 0; ant < 8; ant++) {
            float o0 = o[ant][hf*2+0] * inv, o1 = o[ant][hf*2+1] * inv;
            float r0, r1;
            uint32_t hp = pack_hi(o0, o1, r0, r1);
            *(uint32_t*)(ch + base + ant * 8) = hp;
            *(uint32_t*)(cl + base + ant * 8) = pack_bf(r0, r1);
        }
    }
}

// ---------------- embedding + positional encoding ---------------------------
__global__ __launch_bounds__(512) void embed_pe_kernel(
    const int* __restrict__ tokens, const float* __restrict__ embed)
{
    int bt = blockIdx.x;
    int d  = threadIdx.x;
    int t  = bt % Tc;
    int tok = tokens[bt];
    float val = embed[(size_t)tok * Dc + d] * 22.62741699796952f;
    float expo  = (2.0f * (float)(d >> 1)) / (float)Dc;
    float denom = powf(10000.0f, expo);
    float angle = (float)t / denom;
    val += ((d & 1) == 0) ? sinf(angle) : cosf(angle);
    g_x[(size_t)bt * Dc + d] = val;
}

// ---------------- layernorm --------------------------------------------------
__global__ __launch_bounds__(256) void layernorm_kernel(
    const float* __restrict__ in, const float* __restrict__ gamma,
    const float* __restrict__ beta, float* __restrict__ outf,
    bf16* __restrict__ oh, bf16* __restrict__ ol)
{
    __shared__ float red[256];
    size_t base = (size_t)blockIdx.x * Dc;
    int tid = threadIdx.x;
    float v0 = in[base + tid];
    float v1 = in[base + tid + 256];
    red[tid] = v0 + v1;
    __syncthreads();
    #pragma unroll
    for (int s = 128; s > 0; s >>= 1) {
        if (tid < s) red[tid] += red[tid + s];
        __syncthreads();
    }
    float mu = red[0] * (1.0f / Dc);
    __syncthreads();
    float d0 = v0 - mu, d1 = v1 - mu;
    red[tid] = d0 * d0 + d1 * d1;
    __syncthreads();
    #pragma unroll
    for (int s = 128; s > 0; s >>= 1) {
        if (tid < s) red[tid] += red[tid + s];
        __syncthreads();
    }
    float rstd = rsqrtf(red[0] * (1.0f / Dc) + 1e-3f);
    float o0 = d0 * rstd * gamma[tid]       + beta[tid];
    float o1 = d1 * rstd * gamma[tid + 256] + beta[tid + 256];
    if (outf) {
        outf[base + tid]       = o0;
        outf[base + tid + 256] = o1;
    }
    if (oh) {
        bf16 h0 = __float2bfloat16_rn(o0);
        bf16 h1 = __float2bfloat16_rn(o1);
        oh[base + tid]       = h0;
        oh[base + tid + 256] = h1;
        ol[base + tid]       = __float2bfloat16_rn(o0 - __bfloat162float(h0));
        ol[base + tid + 256] = __float2bfloat16_rn(o1 - __bfloat162float(h1));
    }
}

// ---------------- ksum[b,h,t] from combined qkv (k at +Dc) ------------------
__global__ __launch_bounds__(256) void ksum_kernel(void)
{
    int i = blockIdx.x * blockDim.x + threadIdx.x;
    if (i >= Bc * Tc * Hc) return;
    int bt = i >> 3, h = i & 7;
    int b = bt / Tc, tt = bt % Tc;
    const bf16* ph = g_qkvh + (size_t)bt * QKVW + Dc + h * Ac;
    const bf16* pl = g_qkvl + (size_t)bt * QKVW + Dc + h * Ac;
    float s = 0.0f;
    #pragma unroll
    for (int a = 0; a < Ac; a++)
        s += __bfloat162float(ph[a]) + __bfloat162float(pl[a]);
    g_ksum[((size_t)b * Hc + h) * Tc + tt] = s;
}

// ---------------- zero -------------------------------------------------------
__global__ __launch_bounds__(256) void zero_kernel(float* __restrict__ p, int n4)
{
    int i = blockIdx.x * blockDim.x + threadIdx.x;
    if (i < n4) ((float4*)p)[i] = make_float4(0.f, 0.f, 0.f, 0.f);
}

// ---------------- sparse edge bias scatter ----------------------------------
__global__ __launch_bounds__(256) void bias_scatter_kernel(
    const int* __restrict__ ab, const float* __restrict__ be_l,
    const float* __restrict__ bs_l)
{
    __shared__ float evtab[BIASDIM];
    if (threadIdx.x < BIASDIM) {
        float s = 0.0f;
        #pragma unroll
        for (int a = 0; a < Ac; a++)
            s += be_l[threadIdx.x * Ac + a] * bs_l[a];
        evtab[threadIdx.x] = s;
    }
    __syncthreads();
    int e = blockIdx.x * blockDim.x + threadIdx.x;
    if (e >= Ec) return;
    int ty = ab[e * 4 + 0];
    int b  = ab[e * 4 + 1];
    int q  = ab[e * 4 + 2];
    int k  = ab[e * 4 + 3];
    atomicAdd(&g_dense[((size_t)b * Tc + q) * Tc + k], evtab[ty]);
}

// ---------------- host driver -----------------------------------------------
extern "C" void kernel_launch(void* const* d_in, const int* in_sizes, int n_in,
                              void* d_out, int out_size)
{
    const int*   tokens = (const int*)  d_in[0];
    const float* masks  = (const float*)d_in[1];
    const int*   ab     = (const int*)  d_in[2];
    const float* embed  = (const float*)d_in[3];
    const float* Wq     = (const float*)d_in[4];
    const float* Wk     = (const float*)d_in[5];
    const float* Wv     = (const float*)d_in[6];
    const float* Wo     = (const float*)d_in[7];
    const float* be     = (const float*)d_in[8];
    const float* bs     = (const float*)d_in[9];
    const float* ln_g   = (const float*)d_in[10];
    const float* ln_b   = (const float*)d_in[11];
    const float* ff1w   = (const float*)d_in[12];
    const float* ff1b   = (const float*)d_in[13];
    const float* ff2w   = (const float*)d_in[14];
    const float* ff2b   = (const float*)d_in[15];
    const float* lng    = (const float*)d_in[16];
    const float* lnb    = (const float*)d_in[17];
    float* out = (float*)d_out;

    float *x, *dense;
    bf16 *hh, *hl, *qkvh, *qkvl, *ch, *cl, *fh, *fl;
    bf16 *wqkvTh,*wqkvTl,*woTh,*woTl,*f1Th,*f1Tl,*f2Th,*f2Tl;
    cudaGetSymbolAddress((void**)&x,      g_x);
    cudaGetSymbolAddress((void**)&dense,  g_dense);
    cudaGetSymbolAddress((void**)&hh,     g_hh);
    cudaGetSymbolAddress((void**)&hl,     g_hl);
    cudaGetSymbolAddress((void**)&qkvh,   g_qkvh);
    cudaGetSymbolAddress((void**)&qkvl,   g_qkvl);
    cudaGetSymbolAddress((void**)&ch,     g_ch);
    cudaGetSymbolAddress((void**)&cl,     g_cl);
    cudaGetSymbolAddress((void**)&fh,     g_fh);
    cudaGetSymbolAddress((void**)&fl,     g_fl);
    cudaGetSymbolAddress((void**)&wqkvTh, g_wqkvTh);
    cudaGetSymbolAddress((void**)&wqkvTl, g_wqkvTl);
    cudaGetSymbolAddress((void**)&woTh,   g_woTh);
    cudaGetSymbolAddress((void**)&woTl,   g_woTl);
    cudaGetSymbolAddress((void**)&f1Th,   g_f1Th);
    cudaGetSymbolAddress((void**)&f1Tl,   g_f1Tl);
    cudaGetSymbolAddress((void**)&f2Th,   g_f2Th);
    cudaGetSymbolAddress((void**)&f2Tl,   g_f2Tl);

    cudaFuncSetAttribute(gemm_mma, cudaFuncAttributeMaxDynamicSharedMemorySize,
                         2 * STG);
    cudaFuncSetAttribute(flash_kernel, cudaFuncAttributeMaxDynamicSharedMemorySize,
                         FS_TOTAL);

    const int MT = Bc * Tc;                 // 8192 tokens
    dim3 wb(32, 8);

    // combined QKV weight: rows [0:512)=Wq, [512:1024)=Wk, [1024:1536)=Wv
    wconv_kernel<<<dim3(16, 16, Lc), wb>>>(Wq, wqkvTh,           wqkvTl,           Dc, Dc, (size_t)QKVW*Dc);
    wconv_kernel<<<dim3(16, 16, Lc), wb>>>(Wk, wqkvTh + Dc*Dc,   wqkvTl + Dc*Dc,   Dc, Dc, (size_t)QKVW*Dc);
    wconv_kernel<<<dim3(16, 16, Lc), wb>>>(Wv, wqkvTh + 2*Dc*Dc, wqkvTl + 2*Dc*Dc, Dc, Dc, (size_t)QKVW*Dc);
    wconv_kernel<<<dim3(16, 16, Lc), wb>>>(Wo,   woTh, woTl, Dc, Dc, (size_t)Dc*Dc);
    wconv_kernel<<<dim3(64, 16, Lc), wb>>>(ff1w, f1Th, f1Tl, Dc, Fc, (size_t)Dc*Fc);
    wconv_kernel<<<dim3(16, 64, Lc), wb>>>(ff2w, f2Th, f2Tl, Fc, Dc, (size_t)Fc*Dc);

    embed_pe_kernel<<<MT, 512>>>(tokens, embed);

    for (int l = 0; l < Lc; l++) {
        size_t wqkv = (size_t)l * QKVW * Dc;
        size_t wo1  = (size_t)l * Dc * Dc;
        size_t wf1  = (size_t)l * Dc * Fc;
        size_t wf2  = (size_t)l * Fc * Dc;
        const float* be_l  = be + (size_t)l * BIASDIM * Ac;
        const float* bs_l  = bs + (size_t)l * Ac;
        const float* ln1g  = ln_g + (size_t)l * 2 * Dc;
        const float* ln1b  = ln_b + (size_t)l * 2 * Dc;
        const float* ln2g  = ln1g + Dc;
        const float* ln2b  = ln1b + Dc;
        const float* f1b   = ff1b + (size_t)l * Fc;
        const float* f2b   = ff2b + (size_t)l * Dc;

        layernorm_kernel<<<MT, 256>>>(x, ln1g, ln1b, nullptr, hh, hl);

        // fused QKV projection -> combined bf16 hi/lo buffer
        gemm_mma<<<dim3(QKVW/128, MT/128), 256, 2*STG>>>(hh, hl,
            wqkvTh + wqkv, wqkvTl + wqkv,
            nullptr, nullptr, nullptr, qkvh, qkvl, MT, QKVW, Dc, 0);

        ksum_kernel<<<(Bc*Tc*Hc + 255)/256, 256>>>();

        zero_kernel<<<(Bc*Tc*Tc/4 + 255)/256, 256>>>(dense, Bc*Tc*Tc/4);
        bias_scatter_kernel<<<(Ec + 255)/256, 256>>>(ab, be_l, bs_l);

        flash_kernel<<<dim3(Tc/128, Bc*Hc), 256, FS_TOTAL>>>(masks, ch, cl);

        gemm_mma<<<dim3(Dc/128, MT/128), 256, 2*STG>>>(ch, cl, woTh+wo1, woTl+wo1,
            nullptr, x, x, nullptr, nullptr, MT, Dc, Dc, 0);

        layernorm_kernel<<<MT, 256>>>(x, ln2g, ln2b, nullptr, hh, hl);
        gemm_mma<<<dim3(Fc/128, MT/128), 256, 2*STG>>>(hh, hl, f1Th+wf1, f1Tl+wf1,
            f1b, nullptr, nullptr, fh, fl, MT, Fc, Dc, 1);
        gemm_mma<<<dim3(Dc/128, MT/128), 256, 2*STG>>>(fh, fl, f2Th+wf2, f2Tl+wf2,
            f2b, x, x, nullptr, nullptr, MT, Dc, Fc, 0);
    }

    layernorm_kernel<<<MT, 256>>>(x, lng, lnb, out, nullptr, nullptr);
}

// round 8
// speedup vs baseline: 1.8851x; 1.0201x over previous
#include <cuda_runtime.h>
#include <cuda_bf16.h>
#include <math.h>
#include <stdint.h>

#define Lc 6
#define Bc 16
#define Tc 512
#define Dc 512
#define Hc 8
#define Ac 64
#define Fc 2048
#define Ec 200000
#define BIASDIM 4

typedef __nv_bfloat16 bf16;

// ======================= helpers =============================================
__device__ __forceinline__ uint32_t smem_u32(const void* p) {
    uint32_t a;
    asm("{ .reg .u64 t; cvta.to.shared.u64 t, %1; cvt.u32.u64 %0, t; }"
        : "=r"(a) : "l"(p));
    return a;
}
__device__ __forceinline__ void cp16(uint32_t s, const void* g) {
    asm volatile("cp.async.cg.shared.global [%0], [%1], 16;" :: "r"(s), "l"(g));
}
__device__ __forceinline__ void mma16816(float* c, const uint32_t* a,
                                         const uint32_t* b) {
    asm volatile("mma.sync.aligned.m16n8k16.row.col.f32.bf16.bf16.f32 "
        "{%0,%1,%2,%3}, {%4,%5,%6,%7}, {%8,%9}, {%0,%1,%2,%3};"
        : "+f"(c[0]), "+f"(c[1]), "+f"(c[2]), "+f"(c[3])
        : "r"(a[0]), "r"(a[1]), "r"(a[2]), "r"(a[3]), "r"(b[0]), "r"(b[1]));
}
__device__ __forceinline__ void ldmx4(uint32_t* r, uint32_t a) {
    asm volatile("ldmatrix.sync.aligned.m8n8.x4.shared.b16 {%0,%1,%2,%3}, [%4];"
        : "=r"(r[0]), "=r"(r[1]), "=r"(r[2]), "=r"(r[3]) : "r"(a));
}
__device__ __forceinline__ void ldmx4t(uint32_t* r, uint32_t a) {
    asm volatile("ldmatrix.sync.aligned.m8n8.x4.trans.shared.b16 {%0,%1,%2,%3}, [%4];"
        : "=r"(r[0]), "=r"(r[1]), "=r"(r[2]), "=r"(r[3]) : "r"(a));
}
__device__ __forceinline__ uint32_t pack_hi(float v0, float v1, float& r0, float& r1) {
    bf16 h0 = __float2bfloat16_rn(v0), h1 = __float2bfloat16_rn(v1);
    r0 = v0 - __bfloat162float(h0);
    r1 = v1 - __bfloat162float(h1);
    unsigned short u0 = *reinterpret_cast<unsigned short*>(&h0);
    unsigned short u1 = *reinterpret_cast<unsigned short*>(&h1);
    return (uint32_t)u0 | ((uint32_t)u1 << 16);
}
__device__ __forceinline__ uint32_t pack_bf(float v0, float v1) {
    bf16 h0 = __float2bfloat16_rn(v0), h1 = __float2bfloat16_rn(v1);
    unsigned short u0 = *reinterpret_cast<unsigned short*>(&h0);
    unsigned short u1 = *reinterpret_cast<unsigned short*>(&h1);
    return (uint32_t)u0 | ((uint32_t)u1 << 16);
}

// ---------------- scratch (device globals; no allocations) ------------------
#define QKVW (3*Dc)      // 1536
__device__ float g_x[Bc*Tc*Dc];
__device__ float g_ksum[Bc*Hc*Tc];
__device__ float g_dense[Bc*Tc*Tc];
__device__ bf16 g_hh[Bc*Tc*Dc],   g_hl[Bc*Tc*Dc];
__device__ bf16 g_qkvh[Bc*Tc*QKVW], g_qkvl[Bc*Tc*QKVW];
__device__ bf16 g_ch[Bc*Tc*Dc],   g_cl[Bc*Tc*Dc];
__device__ bf16 g_fh[Bc*Tc*Fc],   g_fl[Bc*Tc*Fc];
__device__ bf16 g_wqkvTh[Lc*QKVW*Dc], g_wqkvTl[Lc*QKVW*Dc];
__device__ bf16 g_woTh[Lc*Dc*Dc],  g_woTl[Lc*Dc*Dc];
__device__ bf16 g_f1Th[Lc*Dc*Fc],  g_f1Tl[Lc*Dc*Fc];
__device__ bf16 g_f2Th[Lc*Fc*Dc],  g_f2Tl[Lc*Fc*Dc];

// ======================= weight transpose+convert ============================
__global__ void wconv_kernel(const float* __restrict__ W,
                             bf16* __restrict__ Th, bf16* __restrict__ Tl,
                             int K, int N, size_t ozstride)
{
    __shared__ float tile[32][33];
    const float* Wz = W + (size_t)blockIdx.z * K * N;
    bf16* Thz = Th + (size_t)blockIdx.z * ozstride;
    bf16* Tlz = Tl + (size_t)blockIdx.z * ozstride;
    int n0 = blockIdx.x * 32, k0 = blockIdx.y * 32;
    int tx = threadIdx.x, ty = threadIdx.y;
    #pragma unroll
    for (int i = 0; i < 4; i++)
        tile[ty + 8*i][tx] = Wz[(size_t)(k0 + ty + 8*i) * N + n0 + tx];
    __syncthreads();
    #pragma unroll
    for (int i = 0; i < 4; i++) {
        int n = n0 + ty + 8*i, k = k0 + tx;
        float v = tile[tx][ty + 8*i];
        bf16 h = __float2bfloat16_rn(v);
        Thz[(size_t)n * K + k] = h;
        Tlz[(size_t)n * K + k] = __float2bfloat16_rn(v - __bfloat162float(h));
    }
}

// ======================= bf16-split MMA GEMM =================================
// C[M,N] = A[M,K] @ B^T[N,K], 128x128 tile, 8 warps, target 2 CTAs/SM.
#define STG 40960u
__global__ __launch_bounds__(256, 2) void gemm_mma(
    const bf16* __restrict__ Ahi, const bf16* __restrict__ Alo,
    const bf16* __restrict__ Bhi, const bf16* __restrict__ Blo,
    const float* __restrict__ bias, const float* __restrict__ resid,
    float* __restrict__ Cf, bf16* __restrict__ Ch, bf16* __restrict__ Cl,
    int M, int N, int K, int do_relu)
{
    extern __shared__ char smem[];
    uint32_t sb = smem_u32(smem);
    int t = threadIdx.x;
    int lane = t & 31, w = t >> 5;
    int row0 = blockIdx.y * 128, col0 = blockIdx.x * 128;
    int warpM = (w & 3) * 32, warpN = (w >> 2) * 64;
    int g = lane >> 2, tg = lane & 3;

    int arow = t >> 1, koff = (t & 1) * 16;
    const bf16* pAh = Ahi + (size_t)(row0 + arow) * K + koff;
    const bf16* pAl = Alo + (size_t)(row0 + arow) * K + koff;
    const bf16* pBh = Bhi + (size_t)(col0 + arow) * K + koff;
    const bf16* pBl = Blo + (size_t)(col0 + arow) * K + koff;
    uint32_t soff = (uint32_t)(arow * 80 + koff * 2);

    float c[2][8][4];
    #pragma unroll
    for (int i = 0; i < 2; i++)
        #pragma unroll
        for (int j = 0; j < 8; j++)
            #pragma unroll
            for (int r = 0; r < 4; r++) c[i][j][r] = 0.0f;

    int ns = K / 32;

    auto issue = [&](int kt) {
        uint32_t base = sb + (uint32_t)(kt & 1) * STG;
        const bf16* a;
        a = pAh + kt * 32;
        cp16(base + soff, a);                 cp16(base + soff + 16, a + 8);
        a = pAl + kt * 32;
        cp16(base + 10240 + soff, a);         cp16(base + 10240 + soff + 16, a + 8);
        a = pBh + kt * 32;
        cp16(base + 20480 + soff, a);         cp16(base + 20480 + soff + 16, a + 8);
        a = pBl + kt * 32;
        cp16(base + 30720 + soff, a);         cp16(base + 30720 + soff + 16, a + 8);
        asm volatile("cp.async.commit_group;" ::: "memory");
    };

    issue(0);
    for (int kt = 0; kt < ns; kt++) {
        if (kt + 1 < ns) {
            issue(kt + 1);
            asm volatile("cp.async.wait_group 1;" ::: "memory");
        } else {
            asm volatile("cp.async.wait_group 0;" ::: "memory");
        }
        __syncthreads();
        uint32_t base = sb + (uint32_t)(kt & 1) * STG;
        #pragma unroll
        for (int ks = 0; ks < 2; ks++) {
            int k0 = ks * 16;
            #pragma unroll
            for (int am = 0; am < 2; am++) {
                uint32_t aoff = (uint32_t)(
                    (warpM + am*16 + (lane & 15)) * 80
                    + (k0 + ((lane >> 4) << 3)) * 2);
                uint32_t ah[4], al[4];
                ldmx4(ah, base + aoff);
                ldmx4(al, base + 10240 + aoff);
                #pragma unroll
                for (int n2 = 0; n2 < 4; n2++) {
                    uint32_t roff = (uint32_t)(
                        (warpN + n2*16 + (lane & 7) + (((lane >> 4) & 1) << 3)) * 80
                        + (k0 + (((lane >> 3) & 1) << 3)) * 2);
                    uint32_t kb[4], klb[4];
                    ldmx4(kb,  base + 20480 + roff);
                    ldmx4(klb, base + 30720 + roff);
                    uint32_t bh0[2] = {kb[0],  kb[1]},  bh1[2] = {kb[2],  kb[3]};
                    uint32_t bl0[2] = {klb[0], klb[1]}, bl1[2] = {klb[2], klb[3]};
                    mma16816(c[am][2*n2],   ah, bh0);
                    mma16816(c[am][2*n2],   ah, bl0);
                    mma16816(c[am][2*n2],   al, bh0);
                    mma16816(c[am][2*n2+1], ah, bh1);
                    mma16816(c[am][2*n2+1], ah, bl1);
                    mma16816(c[am][2*n2+1], al, bh1);
                }
            }
        }
        __syncthreads();
    }

    #pragma unroll
    for (int am = 0; am < 2; am++) {
        #pragma unroll
        for (int bn = 0; bn < 8; bn++) {
            int n = col0 + warpN + (bn >> 1) * 16 + (bn & 1) * 8 + tg * 2;
            #pragma unroll
            for (int hf = 0; hf < 2; hf++) {
                int m = row0 + warpM + am*16 + g + hf*8;
                float v0 = c[am][bn][hf*2+0], v1 = c[am][bn][hf*2+1];
                if (bias) { v0 += bias[n]; v1 += bias[n+1]; }
                if (do_relu) { v0 = fmaxf(v0, 0.f); v1 = fmaxf(v1, 0.f); }
                if (resid) {
                    float2 r = *(const float2*)(resid + (size_t)m * N + n);
                    v0 += r.x; v1 += r.y;
                }
                if (Cf) *(float2*)(Cf + (size_t)m * N + n) = make_float2(v0, v1);
                if (Ch) {
                    float l0, l1;
                    uint32_t hp = pack_hi(v0, v1, l0, l1);
                    *(uint32_t*)(Ch + (size_t)m * N + n) = hp;
                    *(uint32_t*)(Cl + (size_t)m * N + n) = pack_bf(l0, l1);
                }
            }
        }
    }
}

// ======================= fused flash attention ===============================
#define FS_QH    0u
#define FS_QL    18432u
#define FS_KS    36864u
#define FS_ST    38912u
#define FS_STAGE 73728u
#define FS_K     0u
#define FS_KLO   18432u
#define FS_V     36864u
#define FS_VLO   55296u
#define FS_TOTAL (38912u + 2u * 73728u)

__global__ __launch_bounds__(256) void flash_kernel(
    const float* __restrict__ masks,
    bf16* __restrict__ ch, bf16* __restrict__ cl)
{
    extern __shared__ char smem[];
    uint32_t sb = smem_u32(smem);
    int t = threadIdx.x, lane = t & 31, w = t >> 5;
    int z = blockIdx.y, b = z >> 3, h = z & 7;
    int q0 = blockIdx.x * 128;
    size_t bT = (size_t)b * Tc;

    {
        int row = t >> 1, half = t & 1;
        size_t gq = (bT + q0 + row) * QKVW + h * Ac + half * 32;
        uint32_t so = (uint32_t)(row * 144 + half * 64);
        #pragma unroll
        for (int c4 = 0; c4 < 4; c4++) {
            cp16(sb + FS_QH + so + c4 * 16, g_qkvh + gq + c4 * 8);
            cp16(sb + FS_QL + so + c4 * 16, g_qkvl + gq + c4 * 8);
        }
        if (t < 128)
            cp16(sb + FS_KS + t * 16, g_ksum + ((size_t)b * Hc + h) * Tc + t * 4);
    }
    auto issue = [&](int it) {
        uint32_t base = sb + FS_ST + (uint32_t)(it & 1) * FS_STAGE;
        int row = t >> 1, half = t & 1;
        size_t gk = (bT + it * 128 + row) * QKVW + Dc + h * Ac + half * 32;
        size_t gv = gk + Dc;
        uint32_t so = (uint32_t)(row * 144 + half * 64);
        #pragma unroll
        for (int c4 = 0; c4 < 4; c4++) {
            cp16(base + FS_K   + so + c4 * 16, g_qkvh + gk + c4 * 8);
            cp16(base + FS_KLO + so + c4 * 16, g_qkvl + gk + c4 * 8);
            cp16(base + FS_V   + so + c4 * 16, g_qkvh + gv + c4 * 8);
            cp16(base + FS_VLO + so + c4 * 16, g_qkvl + gv + c4 * 8);
        }
        asm volatile("cp.async.commit_group;" ::: "memory");
    };
    issue(0);

    int wm = w * 16;
    int g = lane >> 2, tg = lane & 3;
    float m_[2] = {-1e30f, -1e30f};
    float l_[2] = {0.f, 0.f};
    float o[8][4] = {};

    for (int it = 0; it < 4; it++) {
        asm volatile("cp.async.wait_group 0;" ::: "memory");
        __syncthreads();
        if (it + 1 < 4) issue(it + 1);
        uint32_t stb = sb + FS_ST + (uint32_t)(it & 1) * FS_STAGE;

        float c[16][4] = {};
        #pragma unroll
        for (int s = 0; s < 4; s++) {
            uint32_t qoff = (uint32_t)((wm + (lane & 15)) * 144
                           + (s * 16 + ((lane >> 4) << 3)) * 2);
            uint32_t aqh[4], aql[4];
            ldmx4(aqh, sb + FS_QH + qoff);
            ldmx4(aql, sb + FS_QL + qoff);
            #pragma unroll
            for (int n2 = 0; n2 < 8; n2++) {
                uint32_t koff = (uint32_t)(
                    (n2 * 16 + (lane & 7) + ((lane >> 4) << 3)) * 144
                    + (s * 16 + (((lane >> 3) & 1) << 3)) * 2);
                uint32_t kb[4], klb[4];
                ldmx4(kb, stb + FS_K + koff);
                ldmx4(klb, stb + FS_KLO + koff);
                uint32_t bh0[2] = {kb[0], kb[1]},  bh1[2] = {kb[2], kb[3]};
                uint32_t bl0[2] = {klb[0], klb[1]}, bl1[2] = {klb[2], klb[3]};
                mma16816(c[2*n2],   aqh, bh0);
                mma16816(c[2*n2],   aqh, bl0);
                mma16816(c[2*n2],   aql, bh0);
                mma16816(c[2*n2+1], aqh, bh1);
                mma16816(c[2*n2+1], aqh, bl1);
                mma16816(c[2*n2+1], aql, bh1);
            }
        }
        #pragma unroll
        for (int nt = 0; nt < 16; nt++) {
            int kc = it * 128 + nt * 8 + tg * 2;
            float2 ks = *(float2*)(smem + FS_KS + kc * 4);
            #pragma unroll
            for (int hf = 0; hf < 2; hf++) {
                int row = q0 + wm + g + hf * 8;
                size_t off = (bT + row) * Tc + kc;
                float2 dv = *(const float2*)(g_dense + off);
                float2 mk = *(const float2*)(masks + off);
                float v0 = (c[nt][hf*2+0] + dv.x * ks.x) * 0.125f;
                float v1 = (c[nt][hf*2+1] + dv.y * ks.y) * 0.125f;
                c[nt][hf*2+0] = v0 * mk.x + (1.f - ceilf(mk.x)) * (-3.402823466e38f);
                c[nt][hf*2+1] = v1 * mk.y + (1.f - ceilf(mk.y)) * (-3.402823466e38f);
            }
        }
        float scale[2];
        #pragma unroll
        for (int hf = 0; hf < 2; hf++) {
            float mx = -3.402823466e38f;
            #pragma unroll
            for (int nt = 0; nt < 16; nt++)
                mx = fmaxf(mx, fmaxf(c[nt][hf*2], c[nt][hf*2+1]));
            mx = fmaxf(mx, __shfl_xor_sync(0xffffffffu, mx, 1));
            mx = fmaxf(mx, __shfl_xor_sync(0xffffffffu, mx, 2));
            float mn = fmaxf(m_[hf], mx);
            scale[hf] = __expf(m_[hf] - mn);
            m_[hf] = mn;
            float sum = 0.f;
            #pragma unroll
            for (int nt = 0; nt < 16; nt++) {
                float p0 = __expf(c[nt][hf*2]   - mn);
                float p1 = __expf(c[nt][hf*2+1] - mn);
                c[nt][hf*2] = p0; c[nt][hf*2+1] = p1;
                sum += p0 + p1;
            }
            sum += __shfl_xor_sync(0xffffffffu, sum, 1);
            sum += __shfl_xor_sync(0xffffffffu, sum, 2);
            l_[hf] = l_[hf] * scale[hf] + sum;
        }
        #pragma unroll
        for (int ant = 0; ant < 8; ant++) {
            o[ant][0] *= scale[0]; o[ant][1] *= scale[0];
            o[ant][2] *= scale[1]; o[ant][3] *= scale[1];
        }
        #pragma unroll
        for (int j = 0; j < 8; j++) {
            uint32_t ah[4], al[4];
            float r0, r1;
            ah[0] = pack_hi(c[2*j][0],   c[2*j][1],   r0, r1); al[0] = pack_bf(r0, r1);
            ah[1] = pack_hi(c[2*j][2],   c[2*j][3],   r0, r1); al[1] = pack_bf(r0, r1);
            ah[2] = pack_hi(c[2*j+1][0], c[2*j+1][1], r0, r1); al[2] = pack_bf(r0, r1);
            ah[3] = pack_hi(c[2*j+1][2], c[2*j+1][3], r0, r1); al[3] = pack_bf(r0, r1);
            #pragma unroll
            for (int ap = 0; ap < 4; ap++) {
                uint32_t voff = (uint32_t)(
                    (j * 16 + (lane & 7) + (((lane >> 3) & 1) << 3)) * 144
                    + (ap * 16 + ((lane >> 4) << 3)) * 2);
                uint32_t vb[4], vlb[4];
                ldmx4t(vb, stb + FS_V + voff);
                ldmx4t(vlb, stb + FS_VLO + voff);
                uint32_t vh0[2] = {vb[0], vb[1]},  vh1[2] = {vb[2], vb[3]};
                uint32_t vl0[2] = {vlb[0], vlb[1]}, vl1[2] = {vlb[2], vlb[3]};
                mma16816(o[2*ap],   ah, vh0);
                mma16816(o[2*ap],   ah, vl0);
                mma16816(o[2*ap],   al, vh0);
                mma16816(o[2*ap+1], ah, vh1);
                mma16816(o[2*ap+1], ah, vl1);
                mma16816(o[2*ap+1], al, vh1);
            }
        }
    }
    #pragma unroll
    for (int hf = 0; hf < 2; hf++) {
        float inv = (l_[hf] > 0.f) ? 1.f / l_[hf] : 0.f;
        int row = q0 + wm + g + hf * 8;
        size_t base = (bT + row) * Dc + h * Ac + tg * 2;
        #pragma unroll
        for (int ant = 0; ant < 8; ant++) {
            float o0 = o[ant][hf*2+0] * inv, o1 = o[ant][hf*2+1] * inv;
            float r0, r1;
            uint32_t hp = pack_hi(o0, o1, r0, r1);
            *(uint32_t*)(ch + base + ant * 8) = hp;
            *(uint32_t*)(cl + base + ant * 8) = pack_bf(r0, r1);
        }
    }
}

// ---------------- embedding + positional encoding ---------------------------
__global__ __launch_bounds__(512) void embed_pe_kernel(
    const int* __restrict__ tokens, const float* __restrict__ embed)
{
    int bt = blockIdx.x;
    int d  = threadIdx.x;
    int t  = bt % Tc;
    int tok = tokens[bt];
    float val = embed[(size_t)tok * Dc + d] * 22.62741699796952f;
    float expo  = (2.0f * (float)(d >> 1)) / (float)Dc;
    float denom = powf(10000.0f, expo);
    float angle = (float)t / denom;
    val += ((d & 1) == 0) ? sinf(angle) : cosf(angle);
    g_x[(size_t)bt * Dc + d] = val;
}

// ---------------- layernorm --------------------------------------------------
__global__ __launch_bounds__(256) void layernorm_kernel(
    const float* __restrict__ in, const float* __restrict__ gamma,
    const float* __restrict__ beta, float* __restrict__ outf,
    bf16* __restrict__ oh, bf16* __restrict__ ol)
{
    __shared__ float red[256];
    size_t base = (size_t)blockIdx.x * Dc;
    int tid = threadIdx.x;
    float v0 = in[base + tid];
    float v1 = in[base + tid + 256];
    red[tid] = v0 + v1;
    __syncthreads();
    #pragma unroll
    for (int s = 128; s > 0; s >>= 1) {
        if (tid < s) red[tid] += red[tid + s];
        __syncthreads();
    }
    float mu = red[0] * (1.0f / Dc);
    __syncthreads();
    float d0 = v0 - mu, d1 = v1 - mu;
    red[tid] = d0 * d0 + d1 * d1;
    __syncthreads();
    #pragma unroll
    for (int s = 128; s > 0; s >>= 1) {
        if (tid < s) red[tid] += red[tid + s];
        __syncthreads();
    }
    float rstd = rsqrtf(red[0] * (1.0f / Dc) + 1e-3f);
    float o0 = d0 * rstd * gamma[tid]       + beta[tid];
    float o1 = d1 * rstd * gamma[tid + 256] + beta[tid + 256];
    if (outf) {
        outf[base + tid]       = o0;
        outf[base + tid + 256] = o1;
    }
    if (oh) {
        bf16 h0 = __float2bfloat16_rn(o0);
        bf16 h1 = __float2bfloat16_rn(o1);
        oh[base + tid]       = h0;
        oh[base + tid + 256] = h1;
        ol[base + tid]       = __float2bfloat16_rn(o0 - __bfloat162float(h0));
        ol[base + tid + 256] = __float2bfloat16_rn(o1 - __bfloat162float(h1));
    }
}

// ---------------- ksum[b,h,t] from combined qkv (k at +Dc) ------------------
__global__ __launch_bounds__(256) void ksum_kernel(void)
{
    int i = blockIdx.x * blockDim.x + threadIdx.x;
    if (i >= Bc * Tc * Hc) return;
    int bt = i >> 3, h = i & 7;
    int b = bt / Tc, tt = bt % Tc;
    const bf16* ph = g_qkvh + (size_t)bt * QKVW + Dc + h * Ac;
    const bf16* pl = g_qkvl + (size_t)bt * QKVW + Dc + h * Ac;
    float s = 0.0f;
    #pragma unroll
    for (int a = 0; a < Ac; a++)
        s += __bfloat162float(ph[a]) + __bfloat162float(pl[a]);
    g_ksum[((size_t)b * Hc + h) * Tc + tt] = s;
}

// ---------------- zero -------------------------------------------------------
__global__ __launch_bounds__(256) void zero_kernel(float* __restrict__ p, int n4)
{
    int i = blockIdx.x * blockDim.x + threadIdx.x;
    if (i < n4) ((float4*)p)[i] = make_float4(0.f, 0.f, 0.f, 0.f);
}

// ---------------- sparse edge bias scatter ----------------------------------
__global__ __launch_bounds__(256) void bias_scatter_kernel(
    const int* __restrict__ ab, const float* __restrict__ be_l,
    const float* __restrict__ bs_l)
{
    __shared__ float evtab[BIASDIM];
    if (threadIdx.x < BIASDIM) {
        float s = 0.0f;
        #pragma unroll
        for (int a = 0; a < Ac; a++)
            s += be_l[threadIdx.x * Ac + a] * bs_l[a];
        evtab[threadIdx.x] = s;
    }
    __syncthreads();
    int e = blockIdx.x * blockDim.x + threadIdx.x;
    if (e >= Ec) return;
    int ty = ab[e * 4 + 0];
    int b  = ab[e * 4 + 1];
    int q  = ab[e * 4 + 2];
    int k  = ab[e * 4 + 3];
    atomicAdd(&g_dense[((size_t)b * Tc + q) * Tc + k], evtab[ty]);
}

// ---------------- host driver -----------------------------------------------
extern "C" void kernel_launch(void* const* d_in, const int* in_sizes, int n_in,
                              void* d_out, int out_size)
{
    const int*   tokens = (const int*)  d_in[0];
    const float* masks  = (const float*)d_in[1];
    const int*   ab     = (const int*)  d_in[2];
    const float* embed  = (const float*)d_in[3];
    const float* Wq     = (const float*)d_in[4];
    const float* Wk     = (const float*)d_in[5];
    const float* Wv     = (const float*)d_in[6];
    const float* Wo     = (const float*)d_in[7];
    const float* be     = (const float*)d_in[8];
    const float* bs     = (const float*)d_in[9];
    const float* ln_g   = (const float*)d_in[10];
    const float* ln_b   = (const float*)d_in[11];
    const float* ff1w   = (const float*)d_in[12];
    const float* ff1b   = (const float*)d_in[13];
    const float* ff2w   = (const float*)d_in[14];
    const float* ff2b   = (const float*)d_in[15];
    const float* lng    = (const float*)d_in[16];
    const float* lnb    = (const float*)d_in[17];
    float* out = (float*)d_out;

    float *x, *dense;
    bf16 *hh, *hl, *qkvh, *qkvl, *ch, *cl, *fh, *fl;
    bf16 *wqkvTh,*wqkvTl,*woTh,*woTl,*f1Th,*f1Tl,*f2Th,*f2Tl;
    cudaGetSymbolAddress((void**)&x,      g_x);
    cudaGetSymbolAddress((void**)&dense,  g_dense);
    cudaGetSymbolAddress((void**)&hh,     g_hh);
    cudaGetSymbolAddress((void**)&hl,     g_hl);
    cudaGetSymbolAddress((void**)&qkvh,   g_qkvh);
    cudaGetSymbolAddress((void**)&qkvl,   g_qkvl);
    cudaGetSymbolAddress((void**)&ch,     g_ch);
    cudaGetSymbolAddress((void**)&cl,     g_cl);
    cudaGetSymbolAddress((void**)&fh,     g_fh);
    cudaGetSymbolAddress((void**)&fl,     g_fl);
    cudaGetSymbolAddress((void**)&wqkvTh, g_wqkvTh);
    cudaGetSymbolAddress((void**)&wqkvTl, g_wqkvTl);
    cudaGetSymbolAddress((void**)&woTh,   g_woTh);
    cudaGetSymbolAddress((void**)&woTl,   g_woTl);
    cudaGetSymbolAddress((void**)&f1Th,   g_f1Th);
    cudaGetSymbolAddress((void**)&f1Tl,   g_f1Tl);
    cudaGetSymbolAddress((void**)&f2Th,   g_f2Th);
    cudaGetSymbolAddress((void**)&f2Tl,   g_f2Tl);

    cudaFuncSetAttribute(gemm_mma, cudaFuncAttributeMaxDynamicSharedMemorySize,
                         2 * STG);
    cudaFuncSetAttribute(flash_kernel, cudaFuncAttributeMaxDynamicSharedMemorySize,
                         FS_TOTAL);

    const int MT = Bc * Tc;                 // 8192 tokens
    dim3 wb(32, 8);

    wconv_kernel<<<dim3(16, 16, Lc), wb>>>(Wq, wqkvTh,           wqkvTl,           Dc, Dc, (size_t)QKVW*Dc);
    wconv_kernel<<<dim3(16, 16, Lc), wb>>>(Wk, wqkvTh + Dc*Dc,   wqkvTl + Dc*Dc,   Dc, Dc, (size_t)QKVW*Dc);
    wconv_kernel<<<dim3(16, 16, Lc), wb>>>(Wv, wqkvTh + 2*Dc*Dc, wqkvTl + 2*Dc*Dc, Dc, Dc, (size_t)QKVW*Dc);
    wconv_kernel<<<dim3(16, 16, Lc), wb>>>(Wo,   woTh, woTl, Dc, Dc, (size_t)Dc*Dc);
    wconv_kernel<<<dim3(64, 16, Lc), wb>>>(ff1w, f1Th, f1Tl, Dc, Fc, (size_t)Dc*Fc);
    wconv_kernel<<<dim3(16, 64, Lc), wb>>>(ff2w, f2Th, f2Tl, Fc, Dc, (size_t)Fc*Dc);

    embed_pe_kernel<<<MT, 512>>>(tokens, embed);

    for (int l = 0; l < Lc; l++) {
        size_t wqkv = (size_t)l * QKVW * Dc;
        size_t wo1  = (size_t)l * Dc * Dc;
        size_t wf1  = (size_t)l * Dc * Fc;
        size_t wf2  = (size_t)l * Fc * Dc;
        const float* be_l  = be + (size_t)l * BIASDIM * Ac;
        const float* bs_l  = bs + (size_t)l * Ac;
        const float* ln1g  = ln_g + (size_t)l * 2 * Dc;
        const float* ln1b  = ln_b + (size_t)l * 2 * Dc;
        const float* ln2g  = ln1g + Dc;
        const float* ln2b  = ln1b + Dc;
        const float* f1b   = ff1b + (size_t)l * Fc;
        const float* f2b   = ff2b + (size_t)l * Dc;

        layernorm_kernel<<<MT, 256>>>(x, ln1g, ln1b, nullptr, hh, hl);

        gemm_mma<<<dim3(QKVW/128, MT/128), 256, 2*STG>>>(hh, hl,
            wqkvTh + wqkv, wqkvTl + wqkv,
            nullptr, nullptr, nullptr, qkvh, qkvl, MT, QKVW, Dc, 0);

        ksum_kernel<<<(Bc*Tc*Hc + 255)/256, 256>>>();

        zero_kernel<<<(Bc*Tc*Tc/4 + 255)/256, 256>>>(dense, Bc*Tc*Tc/4);
        bias_scatter_kernel<<<(Ec + 255)/256, 256>>>(ab, be_l, bs_l);

        flash_kernel<<<dim3(Tc/128, Bc*Hc), 256, FS_TOTAL>>>(masks, ch, cl);

        gemm_mma<<<dim3(Dc/128, MT/128), 256, 2*STG>>>(ch, cl, woTh+wo1, woTl+wo1,
            nullptr, x, x, nullptr, nullptr, MT, Dc, Dc, 0);

        layernorm_kernel<<<MT, 256>>>(x, ln2g, ln2b, nullptr, hh, hl);
        gemm_mma<<<dim3(Fc/128, MT/128), 256, 2*STG>>>(hh, hl, f1Th+wf1, f1Tl+wf1,
            f1b, nullptr, nullptr, fh, fl, MT, Fc, Dc, 1);
        gemm_mma<<<dim3(Dc/128, MT/128), 256, 2*STG>>>(fh, fl, f2Th+wf2, f2Tl+wf2,
            f2b, x, x, nullptr, nullptr, MT, Dc, Fc, 0);
    }

    layernorm_kernel<<<MT, 256>>>(x, lng, lnb, out, nullptr, nullptr);
}

// round 9
// speedup vs baseline: 2.1025x; 1.1153x over previous
#include <cuda_runtime.h>
#include <cuda_bf16.h>
#include <math.h>
#include <stdint.h>

#define Lc 6
#define Bc 16
#define Tc 512
#define Dc 512
#define Hc 8
#define Ac 64
#define Fc 2048
#define Ec 200000
#define BIASDIM 4

typedef __nv_bfloat16 bf16;

// ======================= helpers =============================================
__device__ __forceinline__ uint32_t smem_u32(const void* p) {
    uint32_t a;
    asm("{ .reg .u64 t; cvta.to.shared.u64 t, %1; cvt.u32.u64 %0, t; }"
        : "=r"(a) : "l"(p));
    return a;
}
__device__ __forceinline__ void cp16(uint32_t s, const void* g) {
    asm volatile("cp.async.cg.shared.global [%0], [%1], 16;" :: "r"(s), "l"(g));
}
__device__ __forceinline__ void mma16816(float* c, const uint32_t* a,
                                         const uint32_t* b) {
    asm volatile("mma.sync.aligned.m16n8k16.row.col.f32.bf16.bf16.f32 "
        "{%0,%1,%2,%3}, {%4,%5,%6,%7}, {%8,%9}, {%0,%1,%2,%3};"
        : "+f"(c[0]), "+f"(c[1]), "+f"(c[2]), "+f"(c[3])
        : "r"(a[0]), "r"(a[1]), "r"(a[2]), "r"(a[3]), "r"(b[0]), "r"(b[1]));
}
__device__ __forceinline__ void ldmx4(uint32_t* r, uint32_t a) {
    asm volatile("ldmatrix.sync.aligned.m8n8.x4.shared.b16 {%0,%1,%2,%3}, [%4];"
        : "=r"(r[0]), "=r"(r[1]), "=r"(r[2]), "=r"(r[3]) : "r"(a));
}
__device__ __forceinline__ void ldmx4t(uint32_t* r, uint32_t a) {
    asm volatile("ldmatrix.sync.aligned.m8n8.x4.trans.shared.b16 {%0,%1,%2,%3}, [%4];"
        : "=r"(r[0]), "=r"(r[1]), "=r"(r[2]), "=r"(r[3]) : "r"(a));
}
__device__ __forceinline__ uint32_t pack_hi(float v0, float v1, float& r0, float& r1) {
    bf16 h0 = __float2bfloat16_rn(v0), h1 = __float2bfloat16_rn(v1);
    r0 = v0 - __bfloat162float(h0);
    r1 = v1 - __bfloat162float(h1);
    unsigned short u0 = *reinterpret_cast<unsigned short*>(&h0);
    unsigned short u1 = *reinterpret_cast<unsigned short*>(&h1);
    return (uint32_t)u0 | ((uint32_t)u1 << 16);
}
__device__ __forceinline__ uint32_t pack_bf(float v0, float v1) {
    bf16 h0 = __float2bfloat16_rn(v0), h1 = __float2bfloat16_rn(v1);
    unsigned short u0 = *reinterpret_cast<unsigned short*>(&h0);
    unsigned short u1 = *reinterpret_cast<unsigned short*>(&h1);
    return (uint32_t)u0 | ((uint32_t)u1 << 16);
}

// ---------------- scratch (device globals; no allocations) ------------------
#define QKVW (3*Dc)      // 1536
__device__ float g_x[Bc*Tc*Dc];
__device__ float g_ksum[Bc*Hc*Tc];
__device__ float g_dense[Bc*Tc*Tc];
__device__ bf16 g_hh[Bc*Tc*Dc],   g_hl[Bc*Tc*Dc];
__device__ bf16 g_qkvh[Bc*Tc*QKVW], g_qkvl[Bc*Tc*QKVW];
__device__ bf16 g_ch[Bc*Tc*Dc],   g_cl[Bc*Tc*Dc];
__device__ bf16 g_fh[Bc*Tc*Fc],   g_fl[Bc*Tc*Fc];
__device__ bf16 g_wqkvTh[Lc*QKVW*Dc], g_wqkvTl[Lc*QKVW*Dc];
__device__ bf16 g_woTh[Lc*Dc*Dc],  g_woTl[Lc*Dc*Dc];
__device__ bf16 g_f1Th[Lc*Dc*Fc],  g_f1Tl[Lc*Dc*Fc];
__device__ bf16 g_f2Th[Lc*Fc*Dc],  g_f2Tl[Lc*Fc*Dc];

// ======================= weight transpose+convert ============================
__global__ void wconv_kernel(const float* __restrict__ W,
                             bf16* __restrict__ Th, bf16* __restrict__ Tl,
                             int K, int N, size_t ozstride)
{
    __shared__ float tile[32][33];
    const float* Wz = W + (size_t)blockIdx.z * K * N;
    bf16* Thz = Th + (size_t)blockIdx.z * ozstride;
    bf16* Tlz = Tl + (size_t)blockIdx.z * ozstride;
    int n0 = blockIdx.x * 32, k0 = blockIdx.y * 32;
    int tx = threadIdx.x, ty = threadIdx.y;
    #pragma unroll
    for (int i = 0; i < 4; i++)
        tile[ty + 8*i][tx] = Wz[(size_t)(k0 + ty + 8*i) * N + n0 + tx];
    __syncthreads();
    #pragma unroll
    for (int i = 0; i < 4; i++) {
        int n = n0 + ty + 8*i, k = k0 + tx;
        float v = tile[tx][ty + 8*i];
        bf16 h = __float2bfloat16_rn(v);
        Thz[(size_t)n * K + k] = h;
        Tlz[(size_t)n * K + k] = __float2bfloat16_rn(v - __bfloat162float(h));
    }
}

// ======================= bf16-split MMA GEMM =================================
#define STG 40960u
__global__ __launch_bounds__(256, 2) void gemm_mma(
    const bf16* __restrict__ Ahi, const bf16* __restrict__ Alo,
    const bf16* __restrict__ Bhi, const bf16* __restrict__ Blo,
    const float* __restrict__ bias, const float* __restrict__ resid,
    float* __restrict__ Cf, bf16* __restrict__ Ch, bf16* __restrict__ Cl,
    int M, int N, int K, int do_relu)
{
    extern __shared__ char smem[];
    uint32_t sb = smem_u32(smem);
    int t = threadIdx.x;
    int lane = t & 31, w = t >> 5;
    int row0 = blockIdx.y * 128, col0 = blockIdx.x * 128;
    int warpM = (w & 3) * 32, warpN = (w >> 2) * 64;
    int g = lane >> 2, tg = lane & 3;

    int arow = t >> 1, koff = (t & 1) * 16;
    const bf16* pAh = Ahi + (size_t)(row0 + arow) * K + koff;
    const bf16* pAl = Alo + (size_t)(row0 + arow) * K + koff;
    const bf16* pBh = Bhi + (size_t)(col0 + arow) * K + koff;
    const bf16* pBl = Blo + (size_t)(col0 + arow) * K + koff;
    uint32_t soff = (uint32_t)(arow * 80 + koff * 2);

    float c[2][8][4];
    #pragma unroll
    for (int i = 0; i < 2; i++)
        #pragma unroll
        for (int j = 0; j < 8; j++)
            #pragma unroll
            for (int r = 0; r < 4; r++) c[i][j][r] = 0.0f;

    int ns = K / 32;

    auto issue = [&](int kt) {
        uint32_t base = sb + (uint32_t)(kt & 1) * STG;
        const bf16* a;
        a = pAh + kt * 32;
        cp16(base + soff, a);                 cp16(base + soff + 16, a + 8);
        a = pAl + kt * 32;
        cp16(base + 10240 + soff, a);         cp16(base + 10240 + soff + 16, a + 8);
        a = pBh + kt * 32;
        cp16(base + 20480 + soff, a);         cp16(base + 20480 + soff + 16, a + 8);
        a = pBl + kt * 32;
        cp16(base + 30720 + soff, a);         cp16(base + 30720 + soff + 16, a + 8);
        asm volatile("cp.async.commit_group;" ::: "memory");
    };

    issue(0);
    for (int kt = 0; kt < ns; kt++) {
        if (kt + 1 < ns) {
            issue(kt + 1);
            asm volatile("cp.async.wait_group 1;" ::: "memory");
        } else {
            asm volatile("cp.async.wait_group 0;" ::: "memory");
        }
        __syncthreads();
        uint32_t base = sb + (uint32_t)(kt & 1) * STG;
        #pragma unroll
        for (int ks = 0; ks < 2; ks++) {
            int k0 = ks * 16;
            #pragma unroll
            for (int am = 0; am < 2; am++) {
                uint32_t aoff = (uint32_t)(
                    (warpM + am*16 + (lane & 15)) * 80
                    + (k0 + ((lane >> 4) << 3)) * 2);
                uint32_t ah[4], al[4];
                ldmx4(ah, base + aoff);
                ldmx4(al, base + 10240 + aoff);
                #pragma unroll
                for (int n2 = 0; n2 < 4; n2++) {
                    uint32_t roff = (uint32_t)(
                        (warpN + n2*16 + (lane & 7) + (((lane >> 4) & 1) << 3)) * 80
                        + (k0 + (((lane >> 3) & 1) << 3)) * 2);
                    uint32_t kb[4], klb[4];
                    ldmx4(kb,  base + 20480 + roff);
                    ldmx4(klb, base + 30720 + roff);
                    uint32_t bh0[2] = {kb[0],  kb[1]},  bh1[2] = {kb[2],  kb[3]};
                    uint32_t bl0[2] = {klb[0], klb[1]}, bl1[2] = {klb[2], klb[3]};
                    mma16816(c[am][2*n2],   ah, bh0);
                    mma16816(c[am][2*n2],   ah, bl0);
                    mma16816(c[am][2*n2],   al, bh0);
                    mma16816(c[am][2*n2+1], ah, bh1);
                    mma16816(c[am][2*n2+1], ah, bl1);
                    mma16816(c[am][2*n2+1], al, bh1);
                }
            }
        }
        __syncthreads();
    }

    #pragma unroll
    for (int am = 0; am < 2; am++) {
        #pragma unroll
        for (int bn = 0; bn < 8; bn++) {
            int n = col0 + warpN + (bn >> 1) * 16 + (bn & 1) * 8 + tg * 2;
            #pragma unroll
            for (int hf = 0; hf < 2; hf++) {
                int m = row0 + warpM + am*16 + g + hf*8;
                float v0 = c[am][bn][hf*2+0], v1 = c[am][bn][hf*2+1];
                if (bias) { v0 += bias[n]; v1 += bias[n+1]; }
                if (do_relu) { v0 = fmaxf(v0, 0.f); v1 = fmaxf(v1, 0.f); }
                if (resid) {
                    float2 r = *(const float2*)(resid + (size_t)m * N + n);
                    v0 += r.x; v1 += r.y;
                }
                if (Cf) *(float2*)(Cf + (size_t)m * N + n) = make_float2(v0, v1);
                if (Ch) {
                    float l0, l1;
                    uint32_t hp = pack_hi(v0, v1, l0, l1);
                    *(uint32_t*)(Ch + (size_t)m * N + n) = hp;
                    *(uint32_t*)(Cl + (size_t)m * N + n) = pack_bf(l0, l1);
                }
            }
        }
    }
}

// ======================= fused flash attention (K-tile 64, 2 CTAs/SM) ========
#define FS_QH    0u
#define FS_QL    18432u
#define FS_KS    36864u
#define FS_ST    38912u
#define FS_K     0u
#define FS_KLO   9216u
#define FS_V     18432u
#define FS_VLO   27648u
#define FS_STAGE 36864u
#define FS_TOTAL (38912u + 2u * 36864u)   // 112640

__global__ __launch_bounds__(256, 2) void flash_kernel(
    const float* __restrict__ masks,
    bf16* __restrict__ ch, bf16* __restrict__ cl)
{
    extern __shared__ char smem[];
    uint32_t sb = smem_u32(smem);
    int t = threadIdx.x, lane = t & 31, w = t >> 5;
    int z = blockIdx.y, b = z >> 3, h = z & 7;
    int q0 = blockIdx.x * 128;
    size_t bT = (size_t)b * Tc;

    // Q hi/lo (128 rows) + ksum row
    {
        int row = t >> 1, half = t & 1;
        size_t gq = (bT + q0 + row) * QKVW + h * Ac + half * 32;
        uint32_t so = (uint32_t)(row * 144 + half * 64);
        #pragma unroll
        for (int c4 = 0; c4 < 4; c4++) {
            cp16(sb + FS_QH + so + c4 * 16, g_qkvh + gq + c4 * 8);
            cp16(sb + FS_QL + so + c4 * 16, g_qkvl + gq + c4 * 8);
        }
        if (t < 128)
            cp16(sb + FS_KS + t * 16, g_ksum + ((size_t)b * Hc + h) * Tc + t * 4);
    }
    // K/V stage loader: 64 rows per tile; idx over 512 16B-chunks, 2 per thread
    auto issue = [&](int it) {
        uint32_t base = sb + FS_ST + (uint32_t)(it & 1) * FS_STAGE;
        #pragma unroll
        for (int j = 0; j < 2; j++) {
            int idx = t * 2 + j;
            int row = idx >> 3, c8 = idx & 7;
            size_t gk = (bT + it * 64 + row) * QKVW + Dc + h * Ac + c8 * 8;
            size_t gv = gk + Dc;
            uint32_t so = (uint32_t)(row * 144 + c8 * 16);
            cp16(base + FS_K   + so, g_qkvh + gk);
            cp16(base + FS_KLO + so, g_qkvl + gk);
            cp16(base + FS_V   + so, g_qkvh + gv);
            cp16(base + FS_VLO + so, g_qkvl + gv);
        }
        asm volatile("cp.async.commit_group;" ::: "memory");
    };
    issue(0);

    int wm = w * 16;
    int g = lane >> 2, tg = lane & 3;
    float m_[2] = {-1e30f, -1e30f};
    float l_[2] = {0.f, 0.f};
    float o[8][4] = {};

    for (int it = 0; it < 8; it++) {
        asm volatile("cp.async.wait_group 0;" ::: "memory");
        __syncthreads();
        if (it + 1 < 8) issue(it + 1);
        uint32_t stb = sb + FS_ST + (uint32_t)(it & 1) * FS_STAGE;

        // S = Q @ K^T over 64 k-cols
        float c[8][4] = {};
        #pragma unroll
        for (int s = 0; s < 4; s++) {
            uint32_t qoff = (uint32_t)((wm + (lane & 15)) * 144
                           + (s * 16 + ((lane >> 4) << 3)) * 2);
            uint32_t aqh[4], aql[4];
            ldmx4(aqh, sb + FS_QH + qoff);
            ldmx4(aql, sb + FS_QL + qoff);
            #pragma unroll
            for (int n2 = 0; n2 < 4; n2++) {
                uint32_t koff = (uint32_t)(
                    (n2 * 16 + (lane & 7) + ((lane >> 4) << 3)) * 144
                    + (s * 16 + (((lane >> 3) & 1) << 3)) * 2);
                uint32_t kb[4], klb[4];
                ldmx4(kb, stb + FS_K + koff);
                ldmx4(klb, stb + FS_KLO + koff);
                uint32_t bh0[2] = {kb[0], kb[1]},  bh1[2] = {kb[2], kb[3]};
                uint32_t bl0[2] = {klb[0], klb[1]}, bl1[2] = {klb[2], klb[3]};
                mma16816(c[2*n2],   aqh, bh0);
                mma16816(c[2*n2],   aqh, bl0);
                mma16816(c[2*n2],   aql, bh0);
                mma16816(c[2*n2+1], aqh, bh1);
                mma16816(c[2*n2+1], aqh, bl1);
                mma16816(c[2*n2+1], aql, bh1);
            }
        }
        // bias + scale + mask
        #pragma unroll
        for (int nt = 0; nt < 8; nt++) {
            int kc = it * 64 + nt * 8 + tg * 2;
            float2 ks = *(float2*)(smem + FS_KS + kc * 4);
            #pragma unroll
            for (int hf = 0; hf < 2; hf++) {
                int row = q0 + wm + g + hf * 8;
                size_t off = (bT + row) * Tc + kc;
                float2 dv = *(const float2*)(g_dense + off);
                float2 mk = *(const float2*)(masks + off);
                float v0 = (c[nt][hf*2+0] + dv.x * ks.x) * 0.125f;
                float v1 = (c[nt][hf*2+1] + dv.y * ks.y) * 0.125f;
                c[nt][hf*2+0] = v0 * mk.x + (1.f - ceilf(mk.x)) * (-3.402823466e38f);
                c[nt][hf*2+1] = v1 * mk.y + (1.f - ceilf(mk.y)) * (-3.402823466e38f);
            }
        }
        // online softmax
        float scale[2];
        #pragma unroll
        for (int hf = 0; hf < 2; hf++) {
            float mx = -3.402823466e38f;
            #pragma unroll
            for (int nt = 0; nt < 8; nt++)
                mx = fmaxf(mx, fmaxf(c[nt][hf*2], c[nt][hf*2+1]));
            mx = fmaxf(mx, __shfl_xor_sync(0xffffffffu, mx, 1));
            mx = fmaxf(mx, __shfl_xor_sync(0xffffffffu, mx, 2));
            float mn = fmaxf(m_[hf], mx);
            scale[hf] = __expf(m_[hf] - mn);
            m_[hf] = mn;
            float sum = 0.f;
            #pragma unroll
            for (int nt = 0; nt < 8; nt++) {
                float p0 = __expf(c[nt][hf*2]   - mn);
                float p1 = __expf(c[nt][hf*2+1] - mn);
                c[nt][hf*2] = p0; c[nt][hf*2+1] = p1;
                sum += p0 + p1;
            }
            sum += __shfl_xor_sync(0xffffffffu, sum, 1);
            sum += __shfl_xor_sync(0xffffffffu, sum, 2);
            l_[hf] = l_[hf] * scale[hf] + sum;
        }
        #pragma unroll
        for (int ant = 0; ant < 8; ant++) {
            o[ant][0] *= scale[0]; o[ant][1] *= scale[0];
            o[ant][2] *= scale[1]; o[ant][3] *= scale[1];
        }
        // O += P @ V  (P: 128x64 -> 4 k16 tiles)
        #pragma unroll
        for (int j = 0; j < 4; j++) {
            uint32_t ah[4], al[4];
            float r0, r1;
            ah[0] = pack_hi(c[2*j][0],   c[2*j][1],   r0, r1); al[0] = pack_bf(r0, r1);
            ah[1] = pack_hi(c[2*j][2],   c[2*j][3],   r0, r1); al[1] = pack_bf(r0, r1);
            ah[2] = pack_hi(c[2*j+1][0], c[2*j+1][1], r0, r1); al[2] = pack_bf(r0, r1);
            ah[3] = pack_hi(c[2*j+1][2], c[2*j+1][3], r0, r1); al[3] = pack_bf(r0, r1);
            #pragma unroll
            for (int ap = 0; ap < 4; ap++) {
                uint32_t voff = (uint32_t)(
                    (j * 16 + (lane & 7) + (((lane >> 3) & 1) << 3)) * 144
                    + (ap * 16 + ((lane >> 4) << 3)) * 2);
                uint32_t vb[4], vlb[4];
                ldmx4t(vb, stb + FS_V + voff);
                ldmx4t(vlb, stb + FS_VLO + voff);
                uint32_t vh0[2] = {vb[0], vb[1]},  vh1[2] = {vb[2], vb[3]};
                uint32_t vl0[2] = {vlb[0], vlb[1]}, vl1[2] = {vlb[2], vlb[3]};
                mma16816(o[2*ap],   ah, vh0);
                mma16816(o[2*ap],   ah, vl0);
                mma16816(o[2*ap],   al, vh0);
                mma16816(o[2*ap+1], ah, vh1);
                mma16816(o[2*ap+1], ah, vl1);
                mma16816(o[2*ap+1], al, vh1);
            }
        }
    }
    #pragma unroll
    for (int hf = 0; hf < 2; hf++) {
        float inv = (l_[hf] > 0.f) ? 1.f / l_[hf] : 0.f;
        int row = q0 + wm + g + hf * 8;
        size_t base = (bT + row) * Dc + h * Ac + tg * 2;
        #pragma unroll
        for (int ant = 0; ant < 8; ant++) {
            float o0 = o[ant][hf*2+0] * inv, o1 = o[ant][hf*2+1] * inv;
            float r0, r1;
            uint32_t hp = pack_hi(o0, o1, r0, r1);
            *(uint32_t*)(ch + base + ant * 8) = hp;
            *(uint32_t*)(cl + base + ant * 8) = pack_bf(r0, r1);
        }
    }
}

// ---------------- embedding + positional encoding ---------------------------
__global__ __launch_bounds__(512) void embed_pe_kernel(
    const int* __restrict__ tokens, const float* __restrict__ embed)
{
    int bt = blockIdx.x;
    int d  = threadIdx.x;
    int t  = bt % Tc;
    int tok = tokens[bt];
    float val = embed[(size_t)tok * Dc + d] * 22.62741699796952f;
    float expo  = (2.0f * (float)(d >> 1)) / (float)Dc;
    float denom = powf(10000.0f, expo);
    float angle = (float)t / denom;
    val += ((d & 1) == 0) ? sinf(angle) : cosf(angle);
    g_x[(size_t)bt * Dc + d] = val;
}

// ---------------- layernorm: warp-per-token, shuffle reductions --------------
__global__ __launch_bounds__(256) void layernorm_kernel(
    const float* __restrict__ in, const float* __restrict__ gamma,
    const float* __restrict__ beta, float* __restrict__ outf,
    bf16* __restrict__ oh, bf16* __restrict__ ol)
{
    int w = threadIdx.x >> 5, lane = threadIdx.x & 31;
    int token = blockIdx.x * 8 + w;
    size_t base = (size_t)token * Dc;

    float4 v[4];
    #pragma unroll
    for (int i = 0; i < 4; i++)
        v[i] = *(const float4*)(in + base + lane * 4 + i * 128);

    float s = 0.f;
    #pragma unroll
    for (int i = 0; i < 4; i++) s += v[i].x + v[i].y + v[i].z + v[i].w;
    #pragma unroll
    for (int off = 16; off > 0; off >>= 1)
        s += __shfl_xor_sync(0xffffffffu, s, off);
    float mu = s * (1.0f / Dc);

    float q = 0.f;
    #pragma unroll
    for (int i = 0; i < 4; i++) {
        float d0 = v[i].x - mu, d1 = v[i].y - mu;
        float d2 = v[i].z - mu, d3 = v[i].w - mu;
        q += d0*d0 + d1*d1 + d2*d2 + d3*d3;
    }
    #pragma unroll
    for (int off = 16; off > 0; off >>= 1)
        q += __shfl_xor_sync(0xffffffffu, q, off);
    float rstd = rsqrtf(q * (1.0f / Dc) + 1e-3f);

    #pragma unroll
    for (int i = 0; i < 4; i++) {
        int col = lane * 4 + i * 128;
        float4 gm = *(const float4*)(gamma + col);
        float4 bt = *(const float4*)(beta + col);
        float o0 = (v[i].x - mu) * rstd * gm.x + bt.x;
        float o1 = (v[i].y - mu) * rstd * gm.y + bt.y;
        float o2 = (v[i].z - mu) * rstd * gm.z + bt.z;
        float o3 = (v[i].w - mu) * rstd * gm.w + bt.w;
        if (outf)
            *(float4*)(outf + base + col) = make_float4(o0, o1, o2, o3);
        if (oh) {
            float l0, l1, l2, l3;
            uint32_t h0 = pack_hi(o0, o1, l0, l1);
            uint32_t h1 = pack_hi(o2, o3, l2, l3);
            uint2 hv = make_uint2(h0, h1);
            uint2 lv = make_uint2(pack_bf(l0, l1), pack_bf(l2, l3));
            *(uint2*)(oh + base + col) = hv;
            *(uint2*)(ol + base + col) = lv;
        }
    }
}

// ---------------- ksum[b,h,t] from combined qkv (vectorized) -----------------
__global__ __launch_bounds__(256) void ksum_kernel(void)
{
    int i = blockIdx.x * blockDim.x + threadIdx.x;
    if (i >= Bc * Tc * Hc) return;
    int bt = i >> 3, h = i & 7;
    int b = bt / Tc, tt = bt % Tc;
    const uint4* ph = (const uint4*)(g_qkvh + (size_t)bt * QKVW + Dc + h * Ac);
    const uint4* pl = (const uint4*)(g_qkvl + (size_t)bt * QKVW + Dc + h * Ac);
    float s = 0.0f;
    #pragma unroll
    for (int j = 0; j < 8; j++) {
        uint4 uh = ph[j], ul = pl[j];
        uint32_t ws[8] = {uh.x, uh.y, uh.z, uh.w, ul.x, ul.y, ul.z, ul.w};
        #pragma unroll
        for (int k2 = 0; k2 < 8; k2++) {
            s += __uint_as_float(ws[k2] << 16);
            s += __uint_as_float(ws[k2] & 0xFFFF0000u);
        }
    }
    g_ksum[((size_t)b * Hc + h) * Tc + tt] = s;
}

// ---------------- zero -------------------------------------------------------
__global__ __launch_bounds__(256) void zero_kernel(float* __restrict__ p, int n4)
{
    int i = blockIdx.x * blockDim.x + threadIdx.x;
    if (i < n4) ((float4*)p)[i] = make_float4(0.f, 0.f, 0.f, 0.f);
}

// ---------------- sparse edge bias scatter ----------------------------------
__global__ __launch_bounds__(256) void bias_scatter_kernel(
    const int* __restrict__ ab, const float* __restrict__ be_l,
    const float* __restrict__ bs_l)
{
    __shared__ float evtab[BIASDIM];
    if (threadIdx.x < BIASDIM) {
        float s = 0.0f;
        #pragma unroll
        for (int a = 0; a < Ac; a++)
            s += be_l[threadIdx.x * Ac + a] * bs_l[a];
        evtab[threadIdx.x] = s;
    }
    __syncthreads();
    int e = blockIdx.x * blockDim.x + threadIdx.x;
    if (e >= Ec) return;
    int ty = ab[e * 4 + 0];
    int b  = ab[e * 4 + 1];
    int q  = ab[e * 4 + 2];
    int k  = ab[e * 4 + 3];
    atomicAdd(&g_dense[((size_t)b * Tc + q) * Tc + k], evtab[ty]);
}

// ---------------- host driver -----------------------------------------------
extern "C" void kernel_launch(void* const* d_in, const int* in_sizes, int n_in,
                              void* d_out, int out_size)
{
    const int*   tokens = (const int*)  d_in[0];
    const float* masks  = (const float*)d_in[1];
    const int*   ab     = (const int*)  d_in[2];
    const float* embed  = (const float*)d_in[3];
    const float* Wq     = (const float*)d_in[4];
    const float* Wk     = (const float*)d_in[5];
    const float* Wv     = (const float*)d_in[6];
    const float* Wo     = (const float*)d_in[7];
    const float* be     = (const float*)d_in[8];
    const float* bs     = (const float*)d_in[9];
    const float* ln_g   = (const float*)d_in[10];
    const float* ln_b   = (const float*)d_in[11];
    const float* ff1w   = (const float*)d_in[12];
    const float* ff1b   = (const float*)d_in[13];
    const float* ff2w   = (const float*)d_in[14];
    const float* ff2b   = (const float*)d_in[15];
    const float* lng    = (const float*)d_in[16];
    const float* lnb    = (const float*)d_in[17];
    float* out = (float*)d_out;

    float *x, *dense;
    bf16 *hh, *hl, *qkvh, *qkvl, *ch, *cl, *fh, *fl;
    bf16 *wqkvTh,*wqkvTl,*woTh,*woTl,*f1Th,*f1Tl,*f2Th,*f2Tl;
    cudaGetSymbolAddress((void**)&x,      g_x);
    cudaGetSymbolAddress((void**)&dense,  g_dense);
    cudaGetSymbolAddress((void**)&hh,     g_hh);
    cudaGetSymbolAddress((void**)&hl,     g_hl);
    cudaGetSymbolAddress((void**)&qkvh,   g_qkvh);
    cudaGetSymbolAddress((void**)&qkvl,   g_qkvl);
    cudaGetSymbolAddress((void**)&ch,     g_ch);
    cudaGetSymbolAddress((void**)&cl,     g_cl);
    cudaGetSymbolAddress((void**)&fh,     g_fh);
    cudaGetSymbolAddress((void**)&fl,     g_fl);
    cudaGetSymbolAddress((void**)&wqkvTh, g_wqkvTh);
    cudaGetSymbolAddress((void**)&wqkvTl, g_wqkvTl);
    cudaGetSymbolAddress((void**)&woTh,   g_woTh);
    cudaGetSymbolAddress((void**)&woTl,   g_woTl);
    cudaGetSymbolAddress((void**)&f1Th,   g_f1Th);
    cudaGetSymbolAddress((void**)&f1Tl,   g_f1Tl);
    cudaGetSymbolAddress((void**)&f2Th,   g_f2Th);
    cudaGetSymbolAddress((void**)&f2Tl,   g_f2Tl);

    cudaFuncSetAttribute(gemm_mma, cudaFuncAttributeMaxDynamicSharedMemorySize,
                         2 * STG);
    cudaFuncSetAttribute(flash_kernel, cudaFuncAttributeMaxDynamicSharedMemorySize,
                         FS_TOTAL);

    const int MT = Bc * Tc;                 // 8192 tokens
    dim3 wb(32, 8);

    wconv_kernel<<<dim3(16, 16, Lc), wb>>>(Wq, wqkvTh,           wqkvTl,           Dc, Dc, (size_t)QKVW*Dc);
    wconv_kernel<<<dim3(16, 16, Lc), wb>>>(Wk, wqkvTh + Dc*Dc,   wqkvTl + Dc*Dc,   Dc, Dc, (size_t)QKVW*Dc);
    wconv_kernel<<<dim3(16, 16, Lc), wb>>>(Wv, wqkvTh + 2*Dc*Dc, wqkvTl + 2*Dc*Dc, Dc, Dc, (size_t)QKVW*Dc);
    wconv_kernel<<<dim3(16, 16, Lc), wb>>>(Wo,   woTh, woTl, Dc, Dc, (size_t)Dc*Dc);
    wconv_kernel<<<dim3(64, 16, Lc), wb>>>(ff1w, f1Th, f1Tl, Dc, Fc, (size_t)Dc*Fc);
    wconv_kernel<<<dim3(16, 64, Lc), wb>>>(ff2w, f2Th, f2Tl, Fc, Dc, (size_t)Fc*Dc);

    embed_pe_kernel<<<MT, 512>>>(tokens, embed);

    for (int l = 0; l < Lc; l++) {
        size_t wqkv = (size_t)l * QKVW * Dc;
        size_t wo1  = (size_t)l * Dc * Dc;
        size_t wf1  = (size_t)l * Dc * Fc;
        size_t wf2  = (size_t)l * Fc * Dc;
        const float* be_l  = be + (size_t)l * BIASDIM * Ac;
        const float* bs_l  = bs + (size_t)l * Ac;
        const float* ln1g  = ln_g + (size_t)l * 2 * Dc;
        const float* ln1b  = ln_b + (size_t)l * 2 * Dc;
        const float* ln2g  = ln1g + Dc;
        const float* ln2b  = ln1b + Dc;
        const float* f1b   = ff1b + (size_t)l * Fc;
        const float* f2b   = ff2b + (size_t)l * Dc;

        layernorm_kernel<<<MT/8, 256>>>(x, ln1g, ln1b, nullptr, hh, hl);

        gemm_mma<<<dim3(QKVW/128, MT/128), 256, 2*STG>>>(hh, hl,
            wqkvTh + wqkv, wqkvTl + wqkv,
            nullptr, nullptr, nullptr, qkvh, qkvl, MT, QKVW, Dc, 0);

        ksum_kernel<<<(Bc*Tc*Hc + 255)/256, 256>>>();

        zero_kernel<<<(Bc*Tc*Tc/4 + 255)/256, 256>>>(dense, Bc*Tc*Tc/4);
        bias_scatter_kernel<<<(Ec + 255)/256, 256>>>(ab, be_l, bs_l);

        flash_kernel<<<dim3(Tc/128, Bc*Hc), 256, FS_TOTAL>>>(masks, ch, cl);

        gemm_mma<<<dim3(Dc/128, MT/128), 256, 2*STG>>>(ch, cl, woTh+wo1, woTl+wo1,
            nullptr, x, x, nullptr, nullptr, MT, Dc, Dc, 0);

        layernorm_kernel<<<MT/8, 256>>>(x, ln2g, ln2b, nullptr, hh, hl);
        gemm_mma<<<dim3(Fc/128, MT/128), 256, 2*STG>>>(hh, hl, f1Th+wf1, f1Tl+wf1,
            f1b, nullptr, nullptr, fh, fl, MT, Fc, Dc, 1);
        gemm_mma<<<dim3(Dc/128, MT/128), 256, 2*STG>>>(fh, fl, f2Th+wf2, f2Tl+wf2,
            f2b, x, x, nullptr, nullptr, MT, Dc, Fc, 0);
    }

    layernorm_kernel<<<MT/8, 256>>>(x, lng, lnb, out, nullptr, nullptr);
}

// round 10
// speedup vs baseline: 2.1208x; 1.0087x over previous
#include <cuda_runtime.h>
#include <cuda_bf16.h>
#include <math.h>
#include <stdint.h>

#define Lc 6
#define Bc 16
#define Tc 512
#define Dc 512
#define Hc 8
#define Ac 64
#define Fc 2048
#define Ec 200000
#define BIASDIM 4

typedef __nv_bfloat16 bf16;

// ======================= helpers =============================================
__device__ __forceinline__ uint32_t smem_u32(const void* p) {
    uint32_t a;
    asm("{ .reg .u64 t; cvta.to.shared.u64 t, %1; cvt.u32.u64 %0, t; }"
        : "=r"(a) : "l"(p));
    return a;
}
__device__ __forceinline__ void cp16(uint32_t s, const void* g) {
    asm volatile("cp.async.cg.shared.global [%0], [%1], 16;" :: "r"(s), "l"(g));
}
__device__ __forceinline__ void mma16816(float* c, const uint32_t* a,
                                         const uint32_t* b) {
    asm volatile("mma.sync.aligned.m16n8k16.row.col.f32.bf16.bf16.f32 "
        "{%0,%1,%2,%3}, {%4,%5,%6,%7}, {%8,%9}, {%0,%1,%2,%3};"
        : "+f"(c[0]), "+f"(c[1]), "+f"(c[2]), "+f"(c[3])
        : "r"(a[0]), "r"(a[1]), "r"(a[2]), "r"(a[3]), "r"(b[0]), "r"(b[1]));
}
__device__ __forceinline__ void ldmx4(uint32_t* r, uint32_t a) {
    asm volatile("ldmatrix.sync.aligned.m8n8.x4.shared.b16 {%0,%1,%2,%3}, [%4];"
        : "=r"(r[0]), "=r"(r[1]), "=r"(r[2]), "=r"(r[3]) : "r"(a));
}
__device__ __forceinline__ void ldmx4t(uint32_t* r, uint32_t a) {
    asm volatile("ldmatrix.sync.aligned.m8n8.x4.trans.shared.b16 {%0,%1,%2,%3}, [%4];"
        : "=r"(r[0]), "=r"(r[1]), "=r"(r[2]), "=r"(r[3]) : "r"(a));
}
__device__ __forceinline__ uint32_t pack_hi(float v0, float v1, float& r0, float& r1) {
    bf16 h0 = __float2bfloat16_rn(v0), h1 = __float2bfloat16_rn(v1);
    r0 = v0 - __bfloat162float(h0);
    r1 = v1 - __bfloat162float(h1);
    unsigned short u0 = *reinterpret_cast<unsigned short*>(&h0);
    unsigned short u1 = *reinterpret_cast<unsigned short*>(&h1);
    return (uint32_t)u0 | ((uint32_t)u1 << 16);
}
__device__ __forceinline__ uint32_t pack_bf(float v0, float v1) {
    bf16 h0 = __float2bfloat16_rn(v0), h1 = __float2bfloat16_rn(v1);
    unsigned short u0 = *reinterpret_cast<unsigned short*>(&h0);
    unsigned short u1 = *reinterpret_cast<unsigned short*>(&h1);
    return (uint32_t)u0 | ((uint32_t)u1 << 16);
}
// pack {bf16(dense) | bf16(mask)<<16}
__device__ __forceinline__ uint32_t pack_dm(float d, float m) {
    bf16 hd = __float2bfloat16_rn(d), hm = __float2bfloat16_rn(m);
    unsigned short ud = *reinterpret_cast<unsigned short*>(&hd);
    unsigned short um = *reinterpret_cast<unsigned short*>(&hm);
    return (uint32_t)ud | ((uint32_t)um << 16);
}

// ---------------- scratch (device globals; no allocations) ------------------
#define QKVW (3*Dc)      // 1536
__device__ float g_x[Bc*Tc*Dc];
__device__ float g_ksum[Bc*Hc*Tc];
__device__ float g_dense[Bc*Tc*Tc];
__device__ uint32_t g_cmb[Bc*Tc*Tc];          // {bf16 dense, bf16 mask}
__device__ bf16 g_hh[Bc*Tc*Dc],   g_hl[Bc*Tc*Dc];
__device__ bf16 g_qkvh[Bc*Tc*QKVW], g_qkvl[Bc*Tc*QKVW];
__device__ bf16 g_ch[Bc*Tc*Dc],   g_cl[Bc*Tc*Dc];
__device__ bf16 g_fh[Bc*Tc*Fc],   g_fl[Bc*Tc*Fc];
__device__ bf16 g_wqkvTh[Lc*QKVW*Dc], g_wqkvTl[Lc*QKVW*Dc];
__device__ bf16 g_woTh[Lc*Dc*Dc],  g_woTl[Lc*Dc*Dc];
__device__ bf16 g_f1Th[Lc*Dc*Fc],  g_f1Tl[Lc*Dc*Fc];
__device__ bf16 g_f2Th[Lc*Fc*Dc],  g_f2Tl[Lc*Fc*Dc];

// ======================= weight transpose+convert ============================
__global__ void wconv_kernel(const float* __restrict__ W,
                             bf16* __restrict__ Th, bf16* __restrict__ Tl,
                             int K, int N, size_t ozstride)
{
    __shared__ float tile[32][33];
    const float* Wz = W + (size_t)blockIdx.z * K * N;
    bf16* Thz = Th + (size_t)blockIdx.z * ozstride;
    bf16* Tlz = Tl + (size_t)blockIdx.z * ozstride;
    int n0 = blockIdx.x * 32, k0 = blockIdx.y * 32;
    int tx = threadIdx.x, ty = threadIdx.y;
    #pragma unroll
    for (int i = 0; i < 4; i++)
        tile[ty + 8*i][tx] = Wz[(size_t)(k0 + ty + 8*i) * N + n0 + tx];
    __syncthreads();
    #pragma unroll
    for (int i = 0; i < 4; i++) {
        int n = n0 + ty + 8*i, k = k0 + tx;
        float v = tile[tx][ty + 8*i];
        bf16 h = __float2bfloat16_rn(v);
        Thz[(size_t)n * K + k] = h;
        Tlz[(size_t)n * K + k] = __float2bfloat16_rn(v - __bfloat162float(h));
    }
}

// ======================= bf16-split MMA GEMM =================================
#define STG 40960u
__global__ __launch_bounds__(256, 2) void gemm_mma(
    const bf16* __restrict__ Ahi, const bf16* __restrict__ Alo,
    const bf16* __restrict__ Bhi, const bf16* __restrict__ Blo,
    const float* __restrict__ bias, const float* __restrict__ resid,
    float* __restrict__ Cf, bf16* __restrict__ Ch, bf16* __restrict__ Cl,
    int M, int N, int K, int do_relu)
{
    extern __shared__ char smem[];
    uint32_t sb = smem_u32(smem);
    int t = threadIdx.x;
    int lane = t & 31, w = t >> 5;
    int row0 = blockIdx.y * 128, col0 = blockIdx.x * 128;
    int warpM = (w & 3) * 32, warpN = (w >> 2) * 64;
    int g = lane >> 2, tg = lane & 3;

    int arow = t >> 1, koff = (t & 1) * 16;
    const bf16* pAh = Ahi + (size_t)(row0 + arow) * K + koff;
    const bf16* pAl = Alo + (size_t)(row0 + arow) * K + koff;
    const bf16* pBh = Bhi + (size_t)(col0 + arow) * K + koff;
    const bf16* pBl = Blo + (size_t)(col0 + arow) * K + koff;
    uint32_t soff = (uint32_t)(arow * 80 + koff * 2);

    float c[2][8][4];
    #pragma unroll
    for (int i = 0; i < 2; i++)
        #pragma unroll
        for (int j = 0; j < 8; j++)
            #pragma unroll
            for (int r = 0; r < 4; r++) c[i][j][r] = 0.0f;

    int ns = K / 32;

    auto issue = [&](int kt) {
        uint32_t base = sb + (uint32_t)(kt & 1) * STG;
        const bf16* a;
        a = pAh + kt * 32;
        cp16(base + soff, a);                 cp16(base + soff + 16, a + 8);
        a = pAl + kt * 32;
        cp16(base + 10240 + soff, a);         cp16(base + 10240 + soff + 16, a + 8);
        a = pBh + kt * 32;
        cp16(base + 20480 + soff, a);         cp16(base + 20480 + soff + 16, a + 8);
        a = pBl + kt * 32;
        cp16(base + 30720 + soff, a);         cp16(base + 30720 + soff + 16, a + 8);
        asm volatile("cp.async.commit_group;" ::: "memory");
    };

    issue(0);
    for (int kt = 0; kt < ns; kt++) {
        if (kt + 1 < ns) {
            issue(kt + 1);
            asm volatile("cp.async.wait_group 1;" ::: "memory");
        } else {
            asm volatile("cp.async.wait_group 0;" ::: "memory");
        }
        __syncthreads();
        uint32_t base = sb + (uint32_t)(kt & 1) * STG;
        #pragma unroll
        for (int ks = 0; ks < 2; ks++) {
            int k0 = ks * 16;
            #pragma unroll
            for (int am = 0; am < 2; am++) {
                uint32_t aoff = (uint32_t)(
                    (warpM + am*16 + (lane & 15)) * 80
                    + (k0 + ((lane >> 4) << 3)) * 2);
                uint32_t ah[4], al[4];
                ldmx4(ah, base + aoff);
                ldmx4(al, base + 10240 + aoff);
                #pragma unroll
                for (int n2 = 0; n2 < 4; n2++) {
                    uint32_t roff = (uint32_t)(
                        (warpN + n2*16 + (lane & 7) + (((lane >> 4) & 1) << 3)) * 80
                        + (k0 + (((lane >> 3) & 1) << 3)) * 2);
                    uint32_t kb[4], klb[4];
                    ldmx4(kb,  base + 20480 + roff);
                    ldmx4(klb, base + 30720 + roff);
                    uint32_t bh0[2] = {kb[0],  kb[1]},  bh1[2] = {kb[2],  kb[3]};
                    uint32_t bl0[2] = {klb[0], klb[1]}, bl1[2] = {klb[2], klb[3]};
                    mma16816(c[am][2*n2],   ah, bh0);
                    mma16816(c[am][2*n2],   ah, bl0);
                    mma16816(c[am][2*n2],   al, bh0);
                    mma16816(c[am][2*n2+1], ah, bh1);
                    mma16816(c[am][2*n2+1], ah, bl1);
                    mma16816(c[am][2*n2+1], al, bh1);
                }
            }
        }
        __syncthreads();
    }

    #pragma unroll
    for (int am = 0; am < 2; am++) {
        #pragma unroll
        for (int bn = 0; bn < 8; bn++) {
            int n = col0 + warpN + (bn >> 1) * 16 + (bn & 1) * 8 + tg * 2;
            #pragma unroll
            for (int hf = 0; hf < 2; hf++) {
                int m = row0 + warpM + am*16 + g + hf*8;
                float v0 = c[am][bn][hf*2+0], v1 = c[am][bn][hf*2+1];
                if (bias) { v0 += bias[n]; v1 += bias[n+1]; }
                if (do_relu) { v0 = fmaxf(v0, 0.f); v1 = fmaxf(v1, 0.f); }
                if (resid) {
                    float2 r = *(const float2*)(resid + (size_t)m * N + n);
                    v0 += r.x; v1 += r.y;
                }
                if (Cf) *(float2*)(Cf + (size_t)m * N + n) = make_float2(v0, v1);
                if (Ch) {
                    float l0, l1;
                    uint32_t hp = pack_hi(v0, v1, l0, l1);
                    *(uint32_t*)(Ch + (size_t)m * N + n) = hp;
                    *(uint32_t*)(Cl + (size_t)m * N + n) = pack_bf(l0, l1);
                }
            }
        }
    }
}

// ======================= fused flash attention (K-tile 64, 2 CTAs/SM) ========
#define FS_QH    0u
#define FS_QL    18432u
#define FS_KS    36864u
#define FS_ST    38912u
#define FS_K     0u
#define FS_KLO   9216u
#define FS_V     18432u
#define FS_VLO   27648u
#define FS_STAGE 36864u
#define FS_TOTAL (38912u + 2u * 36864u)   // 112640

__global__ __launch_bounds__(256, 2) void flash_kernel(
    bf16* __restrict__ ch, bf16* __restrict__ cl)
{
    extern __shared__ char smem[];
    uint32_t sb = smem_u32(smem);
    int t = threadIdx.x, lane = t & 31, w = t >> 5;
    int z = blockIdx.y, b = z >> 3, h = z & 7;
    int q0 = blockIdx.x * 128;
    size_t bT = (size_t)b * Tc;

    // Q hi/lo (128 rows) + ksum row
    {
        int row = t >> 1, half = t & 1;
        size_t gq = (bT + q0 + row) * QKVW + h * Ac + half * 32;
        uint32_t so = (uint32_t)(row * 144 + half * 64);
        #pragma unroll
        for (int c4 = 0; c4 < 4; c4++) {
            cp16(sb + FS_QH + so + c4 * 16, g_qkvh + gq + c4 * 8);
            cp16(sb + FS_QL + so + c4 * 16, g_qkvl + gq + c4 * 8);
        }
        if (t < 128)
            cp16(sb + FS_KS + t * 16, g_ksum + ((size_t)b * Hc + h) * Tc + t * 4);
    }
    auto issue = [&](int it) {
        uint32_t base = sb + FS_ST + (uint32_t)(it & 1) * FS_STAGE;
        #pragma unroll
        for (int j = 0; j < 2; j++) {
            int idx = t * 2 + j;
            int row = idx >> 3, c8 = idx & 7;
            size_t gk = (bT + it * 64 + row) * QKVW + Dc + h * Ac + c8 * 8;
            size_t gv = gk + Dc;
            uint32_t so = (uint32_t)(row * 144 + c8 * 16);
            cp16(base + FS_K   + so, g_qkvh + gk);
            cp16(base + FS_KLO + so, g_qkvl + gk);
            cp16(base + FS_V   + so, g_qkvh + gv);
            cp16(base + FS_VLO + so, g_qkvl + gv);
        }
        asm volatile("cp.async.commit_group;" ::: "memory");
    };
    issue(0);

    int wm = w * 16;
    int g = lane >> 2, tg = lane & 3;
    float m_[2] = {-1e30f, -1e30f};
    float l_[2] = {0.f, 0.f};
    float o[8][4] = {};

    for (int it = 0; it < 8; it++) {
        asm volatile("cp.async.wait_group 0;" ::: "memory");
        __syncthreads();
        if (it + 1 < 8) issue(it + 1);
        uint32_t stb = sb + FS_ST + (uint32_t)(it & 1) * FS_STAGE;

        // S = Q @ K^T over 64 k-cols
        float c[8][4] = {};
        #pragma unroll
        for (int s = 0; s < 4; s++) {
            uint32_t qoff = (uint32_t)((wm + (lane & 15)) * 144
                           + (s * 16 + ((lane >> 4) << 3)) * 2);
            uint32_t aqh[4], aql[4];
            ldmx4(aqh, sb + FS_QH + qoff);
            ldmx4(aql, sb + FS_QL + qoff);
            #pragma unroll
            for (int n2 = 0; n2 < 4; n2++) {
                uint32_t koff = (uint32_t)(
                    (n2 * 16 + (lane & 7) + ((lane >> 4) << 3)) * 144
                    + (s * 16 + (((lane >> 3) & 1) << 3)) * 2);
                uint32_t kb[4], klb[4];
                ldmx4(kb, stb + FS_K + koff);
                ldmx4(klb, stb + FS_KLO + koff);
                uint32_t bh0[2] = {kb[0], kb[1]},  bh1[2] = {kb[2], kb[3]};
                uint32_t bl0[2] = {klb[0], klb[1]}, bl1[2] = {klb[2], klb[3]};
                mma16816(c[2*n2],   aqh, bh0);
                mma16816(c[2*n2],   aqh, bl0);
                mma16816(c[2*n2],   aql, bh0);
                mma16816(c[2*n2+1], aqh, bh1);
                mma16816(c[2*n2+1], aqh, bl1);
                mma16816(c[2*n2+1], aql, bh1);
            }
        }
        // bias + scale + mask from combined bf16 buffer
        #pragma unroll
        for (int nt = 0; nt < 8; nt++) {
            int kc = it * 64 + nt * 8 + tg * 2;
            float2 ks = *(float2*)(smem + FS_KS + kc * 4);
            #pragma unroll
            for (int hf = 0; hf < 2; hf++) {
                int row = q0 + wm + g + hf * 8;
                size_t off = (bT + row) * Tc + kc;
                uint2 dm = *(const uint2*)(g_cmb + off);
                float d0 = __uint_as_float(dm.x << 16);
                float m0 = __uint_as_float(dm.x & 0xFFFF0000u);
                float d1 = __uint_as_float(dm.y << 16);
                float m1 = __uint_as_float(dm.y & 0xFFFF0000u);
                float v0 = (c[nt][hf*2+0] + d0 * ks.x) * 0.125f;
                float v1 = (c[nt][hf*2+1] + d1 * ks.y) * 0.125f;
                c[nt][hf*2+0] = v0 * m0 + (1.f - ceilf(m0)) * (-3.402823466e38f);
                c[nt][hf*2+1] = v1 * m1 + (1.f - ceilf(m1)) * (-3.402823466e38f);
            }
        }
        // online softmax
        float scale[2];
        #pragma unroll
        for (int hf = 0; hf < 2; hf++) {
            float mx = -3.402823466e38f;
            #pragma unroll
            for (int nt = 0; nt < 8; nt++)
                mx = fmaxf(mx, fmaxf(c[nt][hf*2], c[nt][hf*2+1]));
            mx = fmaxf(mx, __shfl_xor_sync(0xffffffffu, mx, 1));
            mx = fmaxf(mx, __shfl_xor_sync(0xffffffffu, mx, 2));
            float mn = fmaxf(m_[hf], mx);
            scale[hf] = __expf(m_[hf] - mn);
            m_[hf] = mn;
            float sum = 0.f;
            #pragma unroll
            for (int nt = 0; nt < 8; nt++) {
                float p0 = __expf(c[nt][hf*2]   - mn);
                float p1 = __expf(c[nt][hf*2+1] - mn);
                c[nt][hf*2] = p0; c[nt][hf*2+1] = p1;
                sum += p0 + p1;
            }
            sum += __shfl_xor_sync(0xffffffffu, sum, 1);
            sum += __shfl_xor_sync(0xffffffffu, sum, 2);
            l_[hf] = l_[hf] * scale[hf] + sum;
        }
        #pragma unroll
        for (int ant = 0; ant < 8; ant++) {
            o[ant][0] *= scale[0]; o[ant][1] *= scale[0];
            o[ant][2] *= scale[1]; o[ant][3] *= scale[1];
        }
        // O += P @ V
        #pragma unroll
        for (int j = 0; j < 4; j++) {
            uint32_t ah[4], al[4];
            float r0, r1;
            ah[0] = pack_hi(c[2*j][0],   c[2*j][1],   r0, r1); al[0] = pack_bf(r0, r1);
            ah[1] = pack_hi(c[2*j][2],   c[2*j][3],   r0, r1); al[1] = pack_bf(r0, r1);
            ah[2] = pack_hi(c[2*j+1][0], c[2*j+1][1], r0, r1); al[2] = pack_bf(r0, r1);
            ah[3] = pack_hi(c[2*j+1][2], c[2*j+1][3], r0, r1); al[3] = pack_bf(r0, r1);
            #pragma unroll
            for (int ap = 0; ap < 4; ap++) {
                uint32_t voff = (uint32_t)(
                    (j * 16 + (lane & 7) + (((lane >> 3) & 1) << 3)) * 144
                    + (ap * 16 + ((lane >> 4) << 3)) * 2);
                uint32_t vb[4], vlb[4];
                ldmx4t(vb, stb + FS_V + voff);
                ldmx4t(vlb, stb + FS_VLO + voff);
                uint32_t vh0[2] = {vb[0], vb[1]},  vh1[2] = {vb[2], vb[3]};
                uint32_t vl0[2] = {vlb[0], vlb[1]}, vl1[2] = {vlb[2], vlb[3]};
                mma16816(o[2*ap],   ah, vh0);
                mma16816(o[2*ap],   ah, vl0);
                mma16816(o[2*ap],   al, vh0);
                mma16816(o[2*ap+1], ah, vh1);
                mma16816(o[2*ap+1], ah, vl1);
                mma16816(o[2*ap+1], al, vh1);
            }
        }
    }
    #pragma unroll
    for (int hf = 0; hf < 2; hf++) {
        float inv = (l_[hf] > 0.f) ? 1.f / l_[hf] : 0.f;
        int row = q0 + wm + g + hf * 8;
        size_t base = (bT + row) * Dc + h * Ac + tg * 2;
        #pragma unroll
        for (int ant = 0; ant < 8; ant++) {
            float o0 = o[ant][hf*2+0] * inv, o1 = o[ant][hf*2+1] * inv;
            float r0, r1;
            uint32_t hp = pack_hi(o0, o1, r0, r1);
            *(uint32_t*)(ch + base + ant * 8) = hp;
            *(uint32_t*)(cl + base + ant * 8) = pack_bf(r0, r1);
        }
    }
}

// ---------------- embedding + positional encoding ---------------------------
__global__ __launch_bounds__(512) void embed_pe_kernel(
    const int* __restrict__ tokens, const float* __restrict__ embed)
{
    int bt = blockIdx.x;
    int d  = threadIdx.x;
    int t  = bt % Tc;
    int tok = tokens[bt];
    float val = embed[(size_t)tok * Dc + d] * 22.62741699796952f;
    float expo  = (2.0f * (float)(d >> 1)) / (float)Dc;
    float denom = __powf(10000.0f, expo);
    float angle = (float)t / denom;
    val += ((d & 1) == 0) ? sinf(angle) : cosf(angle);
    g_x[(size_t)bt * Dc + d] = val;
}

// ---------------- layernorm: warp-per-token, shuffle reductions --------------
__global__ __launch_bounds__(256) void layernorm_kernel(
    const float* __restrict__ in, const float* __restrict__ gamma,
    const float* __restrict__ beta, float* __restrict__ outf,
    bf16* __restrict__ oh, bf16* __restrict__ ol)
{
    int w = threadIdx.x >> 5, lane = threadIdx.x & 31;
    int token = blockIdx.x * 8 + w;
    size_t base = (size_t)token * Dc;

    float4 v[4];
    #pragma unroll
    for (int i = 0; i < 4; i++)
        v[i] = *(const float4*)(in + base + lane * 4 + i * 128);

    float s = 0.f;
    #pragma unroll
    for (int i = 0; i < 4; i++) s += v[i].x + v[i].y + v[i].z + v[i].w;
    #pragma unroll
    for (int off = 16; off > 0; off >>= 1)
        s += __shfl_xor_sync(0xffffffffu, s, off);
    float mu = s * (1.0f / Dc);

    float q = 0.f;
    #pragma unroll
    for (int i = 0; i < 4; i++) {
        float d0 = v[i].x - mu, d1 = v[i].y - mu;
        float d2 = v[i].z - mu, d3 = v[i].w - mu;
        q += d0*d0 + d1*d1 + d2*d2 + d3*d3;
    }
    #pragma unroll
    for (int off = 16; off > 0; off >>= 1)
        q += __shfl_xor_sync(0xffffffffu, q, off);
    float rstd = rsqrtf(q * (1.0f / Dc) + 1e-3f);

    #pragma unroll
    for (int i = 0; i < 4; i++) {
        int col = lane * 4 + i * 128;
        float4 gm = *(const float4*)(gamma + col);
        float4 bt = *(const float4*)(beta + col);
        float o0 = (v[i].x - mu) * rstd * gm.x + bt.x;
        float o1 = (v[i].y - mu) * rstd * gm.y + bt.y;
        float o2 = (v[i].z - mu) * rstd * gm.z + bt.z;
        float o3 = (v[i].w - mu) * rstd * gm.w + bt.w;
        if (outf)
            *(float4*)(outf + base + col) = make_float4(o0, o1, o2, o3);
        if (oh) {
            float l0, l1, l2, l3;
            uint32_t h0 = pack_hi(o0, o1, l0, l1);
            uint32_t h1 = pack_hi(o2, o3, l2, l3);
            uint2 hv = make_uint2(h0, h1);
            uint2 lv = make_uint2(pack_bf(l0, l1), pack_bf(l2, l3));
            *(uint2*)(oh + base + col) = hv;
            *(uint2*)(ol + base + col) = lv;
        }
    }
}

// ---------------- ksum[b,h,t] from combined qkv (vectorized) -----------------
__global__ __launch_bounds__(256) void ksum_kernel(void)
{
    int i = blockIdx.x * blockDim.x + threadIdx.x;
    if (i >= Bc * Tc * Hc) return;
    int bt = i >> 3, h = i & 7;
    int b = bt / Tc, tt = bt % Tc;
    const uint4* ph = (const uint4*)(g_qkvh + (size_t)bt * QKVW + Dc + h * Ac);
    const uint4* pl = (const uint4*)(g_qkvl + (size_t)bt * QKVW + Dc + h * Ac);
    float s = 0.0f;
    #pragma unroll
    for (int j = 0; j < 8; j++) {
        uint4 uh = ph[j], ul = pl[j];
        uint32_t ws[8] = {uh.x, uh.y, uh.z, uh.w, ul.x, ul.y, ul.z, ul.w};
        #pragma unroll
        for (int k2 = 0; k2 < 8; k2++) {
            s += __uint_as_float(ws[k2] << 16);
            s += __uint_as_float(ws[k2] & 0xFFFF0000u);
        }
    }
    g_ksum[((size_t)b * Hc + h) * Tc + tt] = s;
}

// ---------------- zero -------------------------------------------------------
__global__ __launch_bounds__(256) void zero_kernel(float* __restrict__ p, int n4)
{
    int i = blockIdx.x * blockDim.x + threadIdx.x;
    if (i < n4) ((float4*)p)[i] = make_float4(0.f, 0.f, 0.f, 0.f);
}

// ---------------- sparse edge bias scatter ----------------------------------
__global__ __launch_bounds__(256) void bias_scatter_kernel(
    const int* __restrict__ ab, const float* __restrict__ be_l,
    const float* __restrict__ bs_l)
{
    __shared__ float evtab[BIASDIM];
    if (threadIdx.x < BIASDIM) {
        float s = 0.0f;
        #pragma unroll
        for (int a = 0; a < Ac; a++)
            s += be_l[threadIdx.x * Ac + a] * bs_l[a];
        evtab[threadIdx.x] = s;
    }
    __syncthreads();
    int e = blockIdx.x * blockDim.x + threadIdx.x;
    if (e >= Ec) return;
    int ty = ab[e * 4 + 0];
    int b  = ab[e * 4 + 1];
    int q  = ab[e * 4 + 2];
    int k  = ab[e * 4 + 3];
    atomicAdd(&g_dense[((size_t)b * Tc + q) * Tc + k], evtab[ty]);
}

// ---------------- combine dense+mask into bf16x2 -----------------------------
__global__ __launch_bounds__(256) void cmb_kernel(const float* __restrict__ masks)
{
    int i = blockIdx.x * blockDim.x + threadIdx.x;
    if (i >= Bc * Tc * Tc / 4) return;
    float4 d = ((const float4*)g_dense)[i];
    float4 m = ((const float4*)masks)[i];
    uint4 o;
    o.x = pack_dm(d.x, m.x);
    o.y = pack_dm(d.y, m.y);
    o.z = pack_dm(d.z, m.z);
    o.w = pack_dm(d.w, m.w);
    ((uint4*)g_cmb)[i] = o;
}

// ---------------- host driver -----------------------------------------------
extern "C" void kernel_launch(void* const* d_in, const int* in_sizes, int n_in,
                              void* d_out, int out_size)
{
    const int*   tokens = (const int*)  d_in[0];
    const float* masks  = (const float*)d_in[1];
    const int*   ab     = (const int*)  d_in[2];
    const float* embed  = (const float*)d_in[3];
    const float* Wq     = (const float*)d_in[4];
    const float* Wk     = (const float*)d_in[5];
    const float* Wv     = (const float*)d_in[6];
    const float* Wo     = (const float*)d_in[7];
    const float* be     = (const float*)d_in[8];
    const float* bs     = (const float*)d_in[9];
    const float* ln_g   = (const float*)d_in[10];
    const float* ln_b   = (const float*)d_in[11];
    const float* ff1w   = (const float*)d_in[12];
    const float* ff1b   = (const float*)d_in[13];
    const float* ff2w   = (const float*)d_in[14];
    const float* ff2b   = (const float*)d_in[15];
    const float* lng    = (const float*)d_in[16];
    const float* lnb    = (const float*)d_in[17];
    float* out = (float*)d_out;

    float *x, *dense;
    bf16 *hh, *hl, *qkvh, *qkvl, *ch, *cl, *fh, *fl;
    bf16 *wqkvTh,*wqkvTl,*woTh,*woTl,*f1Th,*f1Tl,*f2Th,*f2Tl;
    cudaGetSymbolAddress((void**)&x,      g_x);
    cudaGetSymbolAddress((void**)&dense,  g_dense);
    cudaGetSymbolAddress((void**)&hh,     g_hh);
    cudaGetSymbolAddress((void**)&hl,     g_hl);
    cudaGetSymbolAddress((void**)&qkvh,   g_qkvh);
    cudaGetSymbolAddress((void**)&qkvl,   g_qkvl);
    cudaGetSymbolAddress((void**)&ch,     g_ch);
    cudaGetSymbolAddress((void**)&cl,     g_cl);
    cudaGetSymbolAddress((void**)&fh,     g_fh);
    cudaGetSymbolAddress((void**)&fl,     g_fl);
    cudaGetSymbolAddress((void**)&wqkvTh, g_wqkvTh);
    cudaGetSymbolAddress((void**)&wqkvTl, g_wqkvTl);
    cudaGetSymbolAddress((void**)&woTh,   g_woTh);
    cudaGetSymbolAddress((void**)&woTl,   g_woTl);
    cudaGetSymbolAddress((void**)&f1Th,   g_f1Th);
    cudaGetSymbolAddress((void**)&f1Tl,   g_f1Tl);
    cudaGetSymbolAddress((void**)&f2Th,   g_f2Th);
    cudaGetSymbolAddress((void**)&f2Tl,   g_f2Tl);

    cudaFuncSetAttribute(gemm_mma, cudaFuncAttributeMaxDynamicSharedMemorySize,
                         2 * STG);
    cudaFuncSetAttribute(flash_kernel, cudaFuncAttributeMaxDynamicSharedMemorySize,
                         FS_TOTAL);

    const int MT = Bc * Tc;                 // 8192 tokens
    dim3 wb(32, 8);

    wconv_kernel<<<dim3(16, 16, Lc), wb>>>(Wq, wqkvTh,           wqkvTl,           Dc, Dc, (size_t)QKVW*Dc);
    wconv_kernel<<<dim3(16, 16, Lc), wb>>>(Wk, wqkvTh + Dc*Dc,   wqkvTl + Dc*Dc,   Dc, Dc, (size_t)QKVW*Dc);
    wconv_kernel<<<dim3(16, 16, Lc), wb>>>(Wv, wqkvTh + 2*Dc*Dc, wqkvTl + 2*Dc*Dc, Dc, Dc, (size_t)QKVW*Dc);
    wconv_kernel<<<dim3(16, 16, Lc), wb>>>(Wo,   woTh, woTl, Dc, Dc, (size_t)Dc*Dc);
    wconv_kernel<<<dim3(64, 16, Lc), wb>>>(ff1w, f1Th, f1Tl, Dc, Fc, (size_t)Dc*Fc);
    wconv_kernel<<<dim3(16, 64, Lc), wb>>>(ff2w, f2Th, f2Tl, Fc, Dc, (size_t)Fc*Dc);

    embed_pe_kernel<<<MT, 512>>>(tokens, embed);

    for (int l = 0; l < Lc; l++) {
        size_t wqkv = (size_t)l * QKVW * Dc;
        size_t wo1  = (size_t)l * Dc * Dc;
        size_t wf1  = (size_t)l * Dc * Fc;
        size_t wf2  = (size_t)l * Fc * Dc;
        const float* be_l  = be + (size_t)l * BIASDIM * Ac;
        const float* bs_l  = bs + (size_t)l * Ac;
        const float* ln1g  = ln_g + (size_t)l * 2 * Dc;
        const float* ln1b  = ln_b + (size_t)l * 2 * Dc;
        const float* ln2g  = ln1g + Dc;
        const float* ln2b  = ln1b + Dc;
        const float* f1b   = ff1b + (size_t)l * Fc;
        const float* f2b   = ff2b + (size_t)l * Dc;

        layernorm_kernel<<<MT/8, 256>>>(x, ln1g, ln1b, nullptr, hh, hl);

        gemm_mma<<<dim3(QKVW/128, MT/128), 256, 2*STG>>>(hh, hl,
            wqkvTh + wqkv, wqkvTl + wqkv,
            nullptr, nullptr, nullptr, qkvh, qkvl, MT, QKVW, Dc, 0);

        ksum_kernel<<<(Bc*Tc*Hc + 255)/256, 256>>>();

        zero_kernel<<<(Bc*Tc*Tc/4 + 255)/256, 256>>>(dense, Bc*Tc*Tc/4);
        bias_scatter_kernel<<<(Ec + 255)/256, 256>>>(ab, be_l, bs_l);
        cmb_kernel<<<(Bc*Tc*Tc/4 + 255)/256, 256>>>(masks);

        flash_kernel<<<dim3(Tc/128, Bc*Hc), 256, FS_TOTAL>>>(ch, cl);

        gemm_mma<<<dim3(Dc/128, MT/128), 256, 2*STG>>>(ch, cl, woTh+wo1, woTl+wo1,
            nullptr, x, x, nullptr, nullptr, MT, Dc, Dc, 0);

        layernorm_kernel<<<MT/8, 256>>>(x, ln2g, ln2b, nullptr, hh, hl);
        gemm_mma<<<dim3(Fc/128, MT/128), 256, 2*STG>>>(hh, hl, f1Th+wf1, f1Tl+wf1,
            f1b, nullptr, nullptr, fh, fl, MT, Fc, Dc, 1);
        gemm_mma<<<dim3(Dc/128, MT/128), 256, 2*STG>>>(fh, fl, f2Th+wf2, f2Tl+wf2,
            f2b, x, x, nullptr, nullptr, MT, Dc, Fc, 0);
    }

    layernorm_kernel<<<MT/8, 256>>>(x, lng, lnb, out, nullptr, nullptr);
}